// round 8
// baseline (speedup 1.0000x reference)
#include <cuda_runtime.h>
#include <math.h>
#include <stdint.h>

// ---------------- problem constants ----------------
#define DEPTH 2
#define DIM   1024
#define HEADS 16
#define DH    64
#define BATCH 8
#define NQ    256
#define JTOT  1088
#define MS    1024
#define MROWS (BATCH*NQ)    // 2048
#define CROWS (BATCH*JTOT)  // 8704
#define FFH   4096
#define SCALE 0.125f
#define NJT   17            // JTOT / 64

// ---------------- scratch ----------------
__device__ float g_Q[MROWS * DIM];
__device__ float g_K[CROWS * DIM];
__device__ float g_V[CROWS * DIM];
__device__ float g_VT[(long)BATCH * DIM * JTOT];
__device__ float g_O[MROWS * DIM];
__device__ float g_Y[(long)MROWS * FFH];
__device__ float g_WqT[(long)DEPTH * DIM * DIM];
__device__ float g_WkT[(long)DEPTH * DIM * DIM];
__device__ float g_WvT[(long)DEPTH * DIM * DIM];
__device__ float g_WoT[(long)DEPTH * DIM * DIM];
__device__ float g_W1T[(long)DEPTH * 2 * FFH * DIM];
__device__ float g_W2T[(long)DEPTH * DIM * FFH];
__device__ float g_cosS[NQ * DH];
__device__ float g_sinS[NQ * DH];
__device__ float g_cosT[MS * DH];
__device__ float g_sinT[MS * DH];

// ---------------- ptx helpers ----------------
__device__ __forceinline__ float tf32r(float f) {
    uint32_t u;
    asm("cvt.rna.tf32.f32 %0, %1;" : "=r"(u) : "f"(f));
    return __uint_as_float(u);
}
__device__ __forceinline__ void ldsm4(uint32_t* r, uint32_t a) {
    asm volatile("ldmatrix.sync.aligned.m8n8.x4.shared.b16 {%0,%1,%2,%3}, [%4];"
                 : "=r"(r[0]), "=r"(r[1]), "=r"(r[2]), "=r"(r[3]) : "r"(a));
}
__device__ __forceinline__ void mma_tf32b(float* c, const uint32_t* a, uint32_t b0, uint32_t b1) {
    asm volatile(
        "mma.sync.aligned.m16n8k8.row.col.f32.tf32.tf32.f32 "
        "{%0,%1,%2,%3}, {%4,%5,%6,%7}, {%8,%9}, {%0,%1,%2,%3};"
        : "+f"(c[0]), "+f"(c[1]), "+f"(c[2]), "+f"(c[3])
        : "r"(a[0]), "r"(a[1]), "r"(a[2]), "r"(a[3]), "r"(b0), "r"(b1));
}
__device__ __forceinline__ void cpa16(uint32_t d, const float* s) {
    asm volatile("cp.async.cg.shared.global [%0], [%1], 16;" :: "r"(d), "l"(s));
}

// ---------------- tf32 GEMM; EPI: 0=plain, 1=rope_q+scale, 2=rpe_bias+rope_k --
// B fragments loaded with paired ldsm4 (2 per kk instead of 4 ldsm2).
template <int EPI>
__global__ void __launch_bounds__(256, 2)
gemm_tc(const float* __restrict__ A, const float* __restrict__ B,
        float* __restrict__ C, const float* __restrict__ Cadd,
        const float* __restrict__ bias,
        int K, int lda, int ldb, int ldc, float alpha,
        const float* __restrict__ ctab, const float* __restrict__ stab,
        const float* __restrict__ rpe_l, const int* __restrict__ rel_idx)
{
    constexpr int BM = 128, BN = 128;
    constexpr int ASZ = BM * 32, STF = ASZ + BN * 32;
    constexpr int WTM = 64, WTN = 32;     // WM=2, WN=4
    constexpr int MI = 4, NI = 4;

    extern __shared__ float smdyn[];
    const uint32_t sb = (uint32_t)__cvta_generic_to_shared(smdyn);

    const int tid = threadIdx.x, warp = tid >> 5, lane = tid & 31;
    const int wm = warp >> 2, wn = warp & 3;
    const int g = lane >> 2, t = lane & 3;
    const int bm0 = blockIdx.y * BM, bn0 = blockIdx.x * BN;

    const int arow = tid >> 3;
    const int cc   = tid & 7;

    const float* Ag = A + (long long)(bm0 + arow) * lda + cc * 4;
    const float* Bg = B + (long long)(bn0 + arow) * ldb + cc * 4;

    const int KT = K >> 5;

    auto load_stage = [&](int s, int kt) {
        if (kt < KT) {
            const int k0 = kt << 5;
            uint32_t ab = sb + (uint32_t)(s * STF) * 4u;
            uint32_t bb = ab + (uint32_t)ASZ * 4u;
            #pragma unroll
            for (int i = 0; i < 4; i++) {
                int r = arow + i * 32;
                uint32_t sw = (uint32_t)((cc ^ (r & 7)) << 4);
                cpa16(ab + r * 128 + sw, Ag + (long long)i * 32 * lda + k0);
                cpa16(bb + r * 128 + sw, Bg + (long long)i * 32 * ldb + k0);
            }
        }
        asm volatile("cp.async.commit_group;");
    };

    float acc[MI][NI][4];
    #pragma unroll
    for (int mi = 0; mi < MI; mi++)
        #pragma unroll
        for (int ni = 0; ni < NI; ni++)
            #pragma unroll
            for (int q = 0; q < 4; q++) acc[mi][ni][q] = 0.f;

    const int fr = lane & 15;     // ldsm4 row within 16
    const int fc = lane >> 4;     // ldsm4 k-chunk select

    load_stage(0, 0);
    load_stage(1, 1);

    for (int kt = 0; kt < KT; kt++) {
        asm volatile("cp.async.wait_group 1;");
        __syncthreads();
        load_stage((kt + 2) % 3, kt + 2);

        const int s = kt % 3;
        const uint32_t ab = sb + (uint32_t)(s * STF) * 4u;
        const uint32_t bb = ab + (uint32_t)ASZ * 4u;

        #pragma unroll
        for (int kk = 0; kk < 4; kk++) {
            const int kc = kk * 2 + fc;
            uint32_t af[MI][4], bf[2][4];
            #pragma unroll
            for (int mi = 0; mi < MI; mi++) {
                int r = wm * WTM + mi * 16 + fr;
                ldsm4(af[mi], ab + r * 128 + ((kc ^ (r & 7)) << 4));
            }
            #pragma unroll
            for (int n2 = 0; n2 < 2; n2++) {
                int r = wn * WTN + n2 * 16 + fr;
                ldsm4(bf[n2], bb + r * 128 + ((kc ^ (r & 7)) << 4));
            }
            #pragma unroll
            for (int mi = 0; mi < MI; mi++)
                #pragma unroll
                for (int n2 = 0; n2 < 2; n2++) {
                    mma_tf32b(acc[mi][2 * n2],     af[mi], bf[n2][0], bf[n2][2]);
                    mma_tf32b(acc[mi][2 * n2 + 1], af[mi], bf[n2][1], bf[n2][3]);
                }
        }
    }

    #pragma unroll
    for (int mi = 0; mi < MI; mi++) {
        int row0 = bm0 + wm * WTM + mi * 16 + g;
        int jA = 0, jB = 0;
        if (EPI == 2) { jA = row0 % JTOT; jB = (row0 + 8) % JTOT; }
        #pragma unroll
        for (int ni = 0; ni < NI; ni++) {
            int col = bn0 + wn * WTN + ni * 8 + 2 * t;
            float v0 = alpha * acc[mi][ni][0];
            float v1 = alpha * acc[mi][ni][1];
            float v2 = alpha * acc[mi][ni][2];
            float v3 = alpha * acc[mi][ni][3];
            if (bias) { float b0 = bias[col], b1 = bias[col + 1]; v0 += b0; v1 += b1; v2 += b0; v3 += b1; }
            if (Cadd) {
                const float2 c0 = *(const float2*)(Cadd + (long long)row0 * ldc + col);
                const float2 c1 = *(const float2*)(Cadd + (long long)(row0 + 8) * ldc + col);
                v0 += c0.x; v1 += c0.y; v2 += c1.x; v3 += c1.y;
            }
            if (EPI == 1) {
                int d = col & (DH - 1);
                int nA = row0 & (NQ - 1), nB = (row0 + 8) & (NQ - 1);
                float cA0 = ctab[nA * DH + d],     sA0 = stab[nA * DH + d];
                float cA1 = ctab[nA * DH + d + 1], sA1 = stab[nA * DH + d + 1];
                float cB0 = ctab[nB * DH + d],     sB0 = stab[nB * DH + d];
                float cB1 = ctab[nB * DH + d + 1], sB1 = stab[nB * DH + d + 1];
                float o0 = (v0 * cA0 - v1 * sA0) * SCALE;
                float o1 = (v1 * cA1 + v0 * sA1) * SCALE;
                float o2 = (v2 * cB0 - v3 * sB0) * SCALE;
                float o3 = (v3 * cB1 + v2 * sB1) * SCALE;
                v0 = o0; v1 = o1; v2 = o2; v3 = o3;
            }
            if (EPI == 2) {
                int d = col & (DH - 1);
                int h = col >> 6;
                if (jA < MS) {
                    float bb2 = rpe_l[rel_idx[jA >> 8] * HEADS + h];
                    float k0 = v0 + bb2, k1 = v1 + bb2;
                    float c0 = ctab[jA * DH + d],     s0 = stab[jA * DH + d];
                    float c1 = ctab[jA * DH + d + 1], s1 = stab[jA * DH + d + 1];
                    v0 = k0 * c0 - k1 * s0;
                    v1 = k1 * c1 + k0 * s1;
                }
                if (jB < MS) {
                    float bb2 = rpe_l[rel_idx[jB >> 8] * HEADS + h];
                    float k0 = v2 + bb2, k1 = v3 + bb2;
                    float c0 = ctab[jB * DH + d],     s0 = stab[jB * DH + d];
                    float c1 = ctab[jB * DH + d + 1], s1 = stab[jB * DH + d + 1];
                    v2 = k0 * c0 - k1 * s0;
                    v3 = k1 * c1 + k0 * s1;
                }
            }
            *(float2*)(C + (long long)row0 * ldc + col) = make_float2(v0, v1);
            *(float2*)(C + (long long)(row0 + 8) * ldc + col) = make_float2(v2, v3);
        }
    }
}

// ---------------- FFN1 + GEGLU fused ----------------
__global__ void __launch_bounds__(256, 2)
gemm_ffn1(const float* __restrict__ A, const float* __restrict__ B,
          float* __restrict__ Y, const float* __restrict__ b1l)
{
    constexpr int BM = 128, BN = 64;
    constexpr int ASZ = BM * 32, BSZ = BN * 32, STF = ASZ + 2 * BSZ;
    constexpr int WTM = 32, WTN = 32, MI = 2, NI = 4;
    const int KT = 32;

    extern __shared__ float smdyn[];
    const uint32_t sb = (uint32_t)__cvta_generic_to_shared(smdyn);

    const int tid = threadIdx.x, warp = tid >> 5, lane = tid & 31;
    const int wm = warp >> 1, wn = warp & 1;
    const int g = lane >> 2, t = lane & 3;
    const int bm0 = blockIdx.y * BM, bn0 = blockIdx.x * BN;

    const int arow = tid >> 3;
    const int cc   = tid & 7;

    const float* Ag  = A + (long long)(bm0 + arow) * DIM + cc * 4;
    const float* Bga = B + (long long)(bn0 + arow) * DIM + cc * 4;
    const float* Bgg = B + (long long)(FFH + bn0 + arow) * DIM + cc * 4;

    auto load_stage = [&](int s, int kt) {
        if (kt < KT) {
            const int k0 = kt << 5;
            uint32_t ab = sb + (uint32_t)(s * STF) * 4u;
            #pragma unroll
            for (int i = 0; i < 4; i++) {
                int r = arow + i * 32;
                cpa16(ab + r * 128 + ((cc ^ (r & 7)) << 4),
                      Ag + (long long)i * 32 * DIM + k0);
            }
            uint32_t bba = sb + (uint32_t)(s * STF + ASZ) * 4u;
            uint32_t bbg = bba + (uint32_t)BSZ * 4u;
            #pragma unroll
            for (int i = 0; i < 2; i++) {
                int r = arow + i * 32;
                uint32_t sw = (uint32_t)((cc ^ (r & 7)) << 4);
                cpa16(bba + r * 128 + sw, Bga + (long long)i * 32 * DIM + k0);
                cpa16(bbg + r * 128 + sw, Bgg + (long long)i * 32 * DIM + k0);
            }
        }
        asm volatile("cp.async.commit_group;");
    };

    float acca[MI][NI][4], accg[MI][NI][4];
    #pragma unroll
    for (int mi = 0; mi < MI; mi++)
        #pragma unroll
        for (int ni = 0; ni < NI; ni++)
            #pragma unroll
            for (int q = 0; q < 4; q++) { acca[mi][ni][q] = 0.f; accg[mi][ni][q] = 0.f; }

    const int fr = lane & 15;
    const int fc = lane >> 4;

    load_stage(0, 0);
    load_stage(1, 1);

    for (int kt = 0; kt < KT; kt++) {
        asm volatile("cp.async.wait_group 1;");
        __syncthreads();
        load_stage((kt + 2) % 3, kt + 2);

        const int s = kt % 3;
        const uint32_t ab  = sb + (uint32_t)(s * STF) * 4u;
        const uint32_t bba = ab + (uint32_t)ASZ * 4u;
        const uint32_t bbg = bba + (uint32_t)BSZ * 4u;

        #pragma unroll
        for (int kk = 0; kk < 4; kk++) {
            const int kc = kk * 2 + fc;
            uint32_t af[MI][4], bfa[2][4], bfg[2][4];
            #pragma unroll
            for (int mi = 0; mi < MI; mi++) {
                int r = wm * WTM + mi * 16 + fr;
                ldsm4(af[mi], ab + r * 128 + ((kc ^ (r & 7)) << 4));
            }
            #pragma unroll
            for (int n2 = 0; n2 < 2; n2++) {
                int r = wn * WTN + n2 * 16 + fr;
                uint32_t sw = (uint32_t)((kc ^ (r & 7)) << 4);
                ldsm4(bfa[n2], bba + r * 128 + sw);
                ldsm4(bfg[n2], bbg + r * 128 + sw);
            }
            #pragma unroll
            for (int mi = 0; mi < MI; mi++)
                #pragma unroll
                for (int n2 = 0; n2 < 2; n2++) {
                    mma_tf32b(acca[mi][2 * n2],     af[mi], bfa[n2][0], bfa[n2][2]);
                    mma_tf32b(acca[mi][2 * n2 + 1], af[mi], bfa[n2][1], bfa[n2][3]);
                    mma_tf32b(accg[mi][2 * n2],     af[mi], bfg[n2][0], bfg[n2][2]);
                    mma_tf32b(accg[mi][2 * n2 + 1], af[mi], bfg[n2][1], bfg[n2][3]);
                }
        }
    }

    #pragma unroll
    for (int mi = 0; mi < MI; mi++) {
        int row0 = bm0 + wm * WTM + mi * 16 + g;
        #pragma unroll
        for (int ni = 0; ni < NI; ni++) {
            int col = bn0 + wn * WTN + ni * 8 + 2 * t;
            float ba0 = b1l[col], ba1 = b1l[col + 1];
            float bg0 = b1l[FFH + col], bg1 = b1l[FFH + col + 1];
            #pragma unroll
            for (int half = 0; half < 2; half++) {
                float a0 = acca[mi][ni][half * 2 + 0] + ba0;
                float a1 = acca[mi][ni][half * 2 + 1] + ba1;
                float g0 = accg[mi][ni][half * 2 + 0] + bg0;
                float g1 = accg[mi][ni][half * 2 + 1] + bg1;
                float y0 = a0 * (0.5f * g0 * (1.0f + erff(g0 * 0.70710678118654752f)));
                float y1 = a1 * (0.5f * g1 * (1.0f + erff(g1 * 0.70710678118654752f)));
                *(float2*)(Y + (long long)(row0 + half * 8) * FFH + col) = make_float2(y0, y1);
            }
        }
    }
}

// ---------------- flash attention ----------------
__global__ void __launch_bounds__(256)
flash_attn(const float* __restrict__ Q, const float* __restrict__ K,
           const float* __restrict__ VT, float* __restrict__ O)
{
    extern __shared__ float sm[];
    const uint32_t sb = (uint32_t)__cvta_generic_to_shared(sm);
    const uint32_t qb = sb;
    const uint32_t kb = sb + 8192u * 4u;
    const uint32_t vb = sb + 16384u * 4u;
    const uint32_t pb = sb + 24576u * 4u;

    const int tid = threadIdx.x, warp = tid >> 5, lane = tid & 31;
    const int g = lane >> 2, t = lane & 3;
    const int m0 = blockIdx.x * 128;
    const int z = blockIdx.y;
    const int b = z >> 4, h = z & 15;

    const float* Qg = Q + ((long long)(b * NQ + m0)) * DIM + h * DH;
    const float* Kg = K + (long long)b * JTOT * DIM + h * DH;
    const float* Vg = VT + (long long)b * DIM * JTOT + (long long)h * DH * JTOT;
    float* Og = O + ((long long)(b * NQ + m0)) * DIM + h * DH;

    auto load_kv_body = [&](int s, int jt) {
        #pragma unroll
        for (int i = 0; i < 4; i++) {
            int idx = tid + i * 256;
            int cc = idx & 7, r = (idx >> 3) & 63, hf = idx >> 9;
            uint32_t off = (uint32_t)(s * 4096 + (hf * 64 + r) * 32) * 4u + ((cc ^ (r & 7)) << 4);
            cpa16(kb + off, Kg + (long long)(jt * 64 + r) * DIM + hf * 32 + cc * 4);
            cpa16(vb + off, Vg + (long long)r * JTOT + jt * 64 + hf * 32 + cc * 4);
        }
    };

    #pragma unroll
    for (int i = 0; i < 8; i++) {
        int idx = tid + i * 256;
        int cc = idx & 7, r = (idx >> 3) & 127, hf = idx >> 10;
        cpa16(qb + (uint32_t)(hf * 128 + r) * 128u + ((cc ^ (r & 7)) << 4),
              Qg + (long long)r * DIM + hf * 32 + cc * 4);
    }
    load_kv_body(0, 0);
    asm volatile("cp.async.commit_group;");
    load_kv_body(1, 1);
    asm volatile("cp.async.commit_group;");

    float acco[8][4];
    #pragma unroll
    for (int ni = 0; ni < 8; ni++)
        #pragma unroll
        for (int q = 0; q < 4; q++) acco[ni][q] = 0.f;
    float mr0 = -INFINITY, mr1 = -INFINITY, l0 = 0.f, l1 = 0.f;

    const int fr = lane & 15;
    const int fc = lane >> 4;

    for (int jt = 0; jt < NJT; jt++) {
        const int s = jt & 1;
        asm volatile("cp.async.wait_group 1;");
        __syncthreads();

        float accs[8][4];
        #pragma unroll
        for (int ni = 0; ni < 8; ni++)
            #pragma unroll
            for (int q = 0; q < 4; q++) accs[ni][q] = 0.f;

        #pragma unroll
        for (int kk = 0; kk < 8; kk++) {
            const int hf = kk >> 2;
            const int kc = (kk & 3) * 2 + fc;
            uint32_t a[4];
            {
                int r = warp * 16 + fr;
                ldsm4(a, qb + (uint32_t)(hf * 128 + r) * 128u + ((kc ^ (r & 7)) << 4));
            }
            #pragma unroll
            for (int p = 0; p < 4; p++) {
                int r = p * 16 + fr;
                uint32_t bf[4];
                ldsm4(bf, kb + (uint32_t)(s * 4096 + (hf * 64 + r) * 32) * 4u + ((kc ^ (r & 7)) << 4));
                mma_tf32b(accs[2 * p],     a, bf[0], bf[2]);
                mma_tf32b(accs[2 * p + 1], a, bf[1], bf[3]);
            }
        }

        float vm0 = -INFINITY, vm1 = -INFINITY;
        #pragma unroll
        for (int ni = 0; ni < 8; ni++) {
            vm0 = fmaxf(vm0, fmaxf(accs[ni][0], accs[ni][1]));
            vm1 = fmaxf(vm1, fmaxf(accs[ni][2], accs[ni][3]));
        }
        vm0 = fmaxf(vm0, __shfl_xor_sync(0xffffffffu, vm0, 1));
        vm0 = fmaxf(vm0, __shfl_xor_sync(0xffffffffu, vm0, 2));
        vm1 = fmaxf(vm1, __shfl_xor_sync(0xffffffffu, vm1, 1));
        vm1 = fmaxf(vm1, __shfl_xor_sync(0xffffffffu, vm1, 2));
        float mn0 = fmaxf(mr0, vm0), mn1 = fmaxf(mr1, vm1);
        float sc0 = __expf(mr0 - mn0), sc1 = __expf(mr1 - mn1);

        float ps0 = 0.f, ps1 = 0.f;
        float pv[8][4];
        #pragma unroll
        for (int ni = 0; ni < 8; ni++) {
            pv[ni][0] = tf32r(__expf(accs[ni][0] - mn0));
            pv[ni][1] = tf32r(__expf(accs[ni][1] - mn0));
            pv[ni][2] = tf32r(__expf(accs[ni][2] - mn1));
            pv[ni][3] = tf32r(__expf(accs[ni][3] - mn1));
            ps0 += pv[ni][0] + pv[ni][1];
            ps1 += pv[ni][2] + pv[ni][3];
        }
        ps0 += __shfl_xor_sync(0xffffffffu, ps0, 1);
        ps0 += __shfl_xor_sync(0xffffffffu, ps0, 2);
        ps1 += __shfl_xor_sync(0xffffffffu, ps1, 1);
        ps1 += __shfl_xor_sync(0xffffffffu, ps1, 2);
        l0 = l0 * sc0 + ps0;
        l1 = l1 * sc1 + ps1;
        mr0 = mn0; mr1 = mn1;
        #pragma unroll
        for (int ni = 0; ni < 8; ni++) {
            acco[ni][0] *= sc0; acco[ni][1] *= sc0;
            acco[ni][2] *= sc1; acco[ni][3] *= sc1;
        }

        const int r0 = warp * 16 + g, r1 = r0 + 8;
        #pragma unroll
        for (int ni = 0; ni < 8; ni++) {
            int hf = ni >> 2;
            int cc = (ni & 3) * 2 + (t >> 1);
            uint32_t ofs = (uint32_t)((t & 1) * 8);
            uint32_t a0 = pb + (uint32_t)(hf * 128 + r0) * 128u + ((cc ^ (r0 & 7)) << 4) + ofs;
            uint32_t a1 = pb + (uint32_t)(hf * 128 + r1) * 128u + ((cc ^ (r1 & 7)) << 4) + ofs;
            asm volatile("st.shared.v2.f32 [%0], {%1,%2};" :: "r"(a0), "f"(pv[ni][0]), "f"(pv[ni][1]));
            asm volatile("st.shared.v2.f32 [%0], {%1,%2};" :: "r"(a1), "f"(pv[ni][2]), "f"(pv[ni][3]));
        }
        __syncwarp();

        #pragma unroll
        for (int kk = 0; kk < 8; kk++) {
            const int hf = kk >> 2;
            const int kc = (kk & 3) * 2 + fc;
            uint32_t a[4];
            {
                int r = warp * 16 + fr;
                ldsm4(a, pb + (uint32_t)(hf * 128 + r) * 128u + ((kc ^ (r & 7)) << 4));
            }
            #pragma unroll
            for (int p = 0; p < 4; p++) {
                int r = p * 16 + fr;
                uint32_t bf[4];
                ldsm4(bf, vb + (uint32_t)(s * 4096 + (hf * 64 + r) * 32) * 4u + ((kc ^ (r & 7)) << 4));
                mma_tf32b(acco[2 * p],     a, bf[0], bf[2]);
                mma_tf32b(acco[2 * p + 1], a, bf[1], bf[3]);
            }
        }
        __syncthreads();

        if (jt + 2 < NJT) load_kv_body(s, jt + 2);
        asm volatile("cp.async.commit_group;");
    }

    float inv0 = 1.f / l0, inv1 = 1.f / l1;
    const int r0 = warp * 16 + g, r1 = r0 + 8;
    #pragma unroll
    for (int ni = 0; ni < 8; ni++) {
        int col = ni * 8 + 2 * t;
        *(float2*)(Og + (long long)r0 * DIM + col) =
            make_float2(acco[ni][0] * inv0, acco[ni][1] * inv0);
        *(float2*)(Og + (long long)r1 * DIM + col) =
            make_float2(acco[ni][2] * inv1, acco[ni][3] * inv1);
    }
}

// ---------------- batched weight transpose (single launch) ----------------
__global__ void __launch_bounds__(256)
wtrans_all(const float* __restrict__ Wq, const float* __restrict__ Wk,
           const float* __restrict__ Wv, const float* __restrict__ Wo,
           const float* __restrict__ W1, const float* __restrict__ W2,
           float* __restrict__ WqT, float* __restrict__ WkT,
           float* __restrict__ WvT, float* __restrict__ WoT,
           float* __restrict__ W1T, float* __restrict__ W2T)
{
    __shared__ float tbuf[32][33];
    const float* ins[6] = {Wq, Wk, Wv, Wo, W1, W2};
    float* outs[6] = {WqT, WkT, WvT, WoT, W1T, W2T};
    const int Rs[6] = {DIM, DIM, DIM, DIM, DIM, FFH};
    const int Cs[6] = {DIM, DIM, DIM, DIM, 2 * FFH, DIM};

    int tile = blockIdx.x, job = 0;
    #pragma unroll
    for (int j2 = 0; j2 < 6; j2++) {
        int nt = DEPTH * (Rs[j2] / 32) * (Cs[j2] / 32);
        if (tile >= nt) { tile -= nt; job++; }
        else break;
    }
    const int R = Rs[job], C = Cs[job];
    const int tpz = (R / 32) * (C / 32);
    const int zdx = tile / tpz;
    const int rem = tile - zdx * tpz;
    const int ty = rem / (C / 32), tx = rem - ty * (C / 32);
    const float* in = ins[job] + (long long)zdx * R * C;
    float* out = outs[job] + (long long)zdx * R * C;

    int c0 = tx * 32, r0 = ty * 32;
    int x = threadIdx.x & 31, y = threadIdx.x >> 5;
    #pragma unroll
    for (int i = 0; i < 32; i += 8)
        tbuf[y + i][x] = in[(long long)(r0 + y + i) * C + c0 + x];
    __syncthreads();
    #pragma unroll
    for (int i = 0; i < 32; i += 8)
        out[(long long)(c0 + y + i) * R + r0 + x] = tf32r(tbuf[x][y + i]);
}

// ---------------- cos/sin tables ----------------
__global__ void prep_trig(const float* __restrict__ srcf, const float* __restrict__ tgtf,
                          float* __restrict__ cS, float* __restrict__ sS,
                          float* __restrict__ cT, float* __restrict__ sT)
{
    int idx = blockIdx.x * blockDim.x + threadIdx.x;
    if (idx < NQ * DH) {
        float f = srcf[idx];
        cS[idx] = cosf(f); sS[idx] = sinf(f);
    } else if (idx < NQ * DH + MS * DH) {
        int i = idx - NQ * DH;
        float f = tgtf[i];
        cT[i] = cosf(f); sT[i] = sinf(f);
    }
}

// ---------------- V transpose per batch ----------------
__global__ void transpose_cvt(const float* __restrict__ in, float* __restrict__ out,
                              int R, int C, long long sIn, long long sOut)
{
    __shared__ float tbuf[32][33];
    in  += (long long)blockIdx.z * sIn;
    out += (long long)blockIdx.z * sOut;
    int c0 = blockIdx.x * 32, r0 = blockIdx.y * 32;
    int x = threadIdx.x, y = threadIdx.y;
    #pragma unroll
    for (int i = 0; i < 32; i += 8)
        tbuf[y + i][x] = in[(long long)(r0 + y + i) * C + c0 + x];
    __syncthreads();
    #pragma unroll
    for (int i = 0; i < 32; i += 8)
        out[(long long)(c0 + y + i) * R + r0 + x] = tf32r(tbuf[x][y + i]);
}

// ---------------- launcher ----------------
extern "C" void kernel_launch(void* const* d_in, const int* in_sizes, int n_in,
                              void* d_out, int out_size)
{
    const float* x    = (const float*)d_in[0];
    const float* cond = (const float*)d_in[1];
    const float* Wq   = (const float*)d_in[2];
    const float* Wk   = (const float*)d_in[3];
    const float* Wv   = (const float*)d_in[4];
    const float* Wo   = (const float*)d_in[5];
    const float* bo   = (const float*)d_in[6];
    const float* rpe  = (const float*)d_in[7];
    const float* W1   = (const float*)d_in[8];
    const float* b1   = (const float*)d_in[9];
    const float* W2   = (const float*)d_in[10];
    const float* b2   = (const float*)d_in[11];
    const float* srcf = (const float*)d_in[12];
    const float* tgtf = (const float*)d_in[13];
    const int*   reli = (const int*)d_in[14];
    float* xo = (float*)d_out;

    float *Q, *K, *V, *VT, *O, *Y;
    float *WqT, *WkT, *WvT, *WoT, *W1T, *W2T;
    float *cS, *sS, *cT, *sT;
    cudaGetSymbolAddress((void**)&Q, g_Q);
    cudaGetSymbolAddress((void**)&K, g_K);
    cudaGetSymbolAddress((void**)&V, g_V);
    cudaGetSymbolAddress((void**)&VT, g_VT);
    cudaGetSymbolAddress((void**)&O, g_O);
    cudaGetSymbolAddress((void**)&Y, g_Y);
    cudaGetSymbolAddress((void**)&WqT, g_WqT);
    cudaGetSymbolAddress((void**)&WkT, g_WkT);
    cudaGetSymbolAddress((void**)&WvT, g_WvT);
    cudaGetSymbolAddress((void**)&WoT, g_WoT);
    cudaGetSymbolAddress((void**)&W1T, g_W1T);
    cudaGetSymbolAddress((void**)&W2T, g_W2T);
    cudaGetSymbolAddress((void**)&cS, g_cosS);
    cudaGetSymbolAddress((void**)&sS, g_sinS);
    cudaGetSymbolAddress((void**)&cT, g_cosT);
    cudaGetSymbolAddress((void**)&sT, g_sinT);

    const int SM128 = (128 * 32 + 128 * 32) * 3 * 4;     // 96 KB
    const int SMF1  = (128 * 32 + 2 * 64 * 32) * 3 * 4;  // 96 KB
    const int SMFL  = 32768 * 4;                         // 128 KB
    cudaFuncSetAttribute(gemm_tc<0>, cudaFuncAttributeMaxDynamicSharedMemorySize, SM128);
    cudaFuncSetAttribute(gemm_tc<1>, cudaFuncAttributeMaxDynamicSharedMemorySize, SM128);
    cudaFuncSetAttribute(gemm_tc<2>, cudaFuncAttributeMaxDynamicSharedMemorySize, SM128);
    cudaFuncSetAttribute(gemm_ffn1, cudaFuncAttributeMaxDynamicSharedMemorySize, SMF1);
    cudaFuncSetAttribute(flash_attn, cudaFuncAttributeMaxDynamicSharedMemorySize, SMFL);

    cudaMemcpyAsync(xo, x, (size_t)MROWS * DIM * sizeof(float),
                    cudaMemcpyDeviceToDevice, 0);

    wtrans_all<<<32768, 256>>>(Wq, Wk, Wv, Wo, W1, W2, WqT, WkT, WvT, WoT, W1T, W2T);
    prep_trig<<<((NQ + MS) * DH + 255) / 256, 256>>>(srcf, tgtf, cS, sS, cT, sT);

    dim3 tb(32, 8);
    for (int l = 0; l < DEPTH; l++) {
        const float* wqt = WqT + (long long)l * DIM * DIM;
        const float* wkt = WkT + (long long)l * DIM * DIM;
        const float* wvt = WvT + (long long)l * DIM * DIM;
        const float* wot = WoT + (long long)l * DIM * DIM;
        const float* bol = bo + l * DIM;
        const float* rpel = rpe + (long long)l * 405 * HEADS;
        const float* w1t = W1T + (long long)l * DIM * 2 * FFH;
        const float* b1l = b1 + (long long)l * (2 * FFH);
        const float* w2t = W2T + (long long)l * DIM * FFH;
        const float* b2l = b2 + l * DIM;

        // Q = rope(x @ Wq) * SCALE
        gemm_tc<1><<<dim3(DIM / 128, MROWS / 128), 256, SM128>>>(
            xo, wqt, Q, nullptr, nullptr,
            DIM, DIM, DIM, DIM, 1.0f, cS, sS, nullptr, nullptr);
        // V = cond @ Wv
        gemm_tc<0><<<dim3(DIM / 128, CROWS / 128), 256, SM128>>>(
            cond, wvt, V, nullptr, nullptr,
            DIM, DIM, DIM, DIM, 1.0f, nullptr, nullptr, nullptr, nullptr);
        // V^T per batch
        transpose_cvt<<<dim3(DIM / 32, JTOT / 32, BATCH), tb>>>(
            V, VT, JTOT, DIM, (long long)JTOT * DIM, (long long)DIM * JTOT);
        // K = rope_bias(cond @ Wk)
        gemm_tc<2><<<dim3(DIM / 128, CROWS / 128), 256, SM128>>>(
            cond, wkt, K, nullptr, nullptr,
            DIM, DIM, DIM, DIM, 1.0f, cT, sT, rpel, reli);

        // fused attention -> O
        flash_attn<<<dim3(NQ / 128, BATCH * HEADS), 256, SMFL>>>(Q, K, VT, O);

        // x = x + O @ Wo + bo
        gemm_tc<0><<<dim3(DIM / 128, MROWS / 128), 256, SM128>>>(
            O, wot, xo, xo, bol,
            DIM, DIM, DIM, DIM, 1.0f, nullptr, nullptr, nullptr, nullptr);

        // Y = GEGLU(x @ W1 + b1)
        gemm_ffn1<<<dim3(FFH / 64, MROWS / 128), 256, SMF1>>>(xo, w1t, Y, b1l);

        // x = x + Y @ W2 + b2
        gemm_tc<0><<<dim3(DIM / 128, MROWS / 128), 256, SM128>>>(
            Y, w2t, xo, xo, b2l,
            FFH, FFH, FFH, DIM, 1.0f, nullptr, nullptr, nullptr, nullptr);
    }
}

// round 9
// speedup vs baseline: 1.0704x; 1.0704x over previous
#include <cuda_runtime.h>
#include <math.h>
#include <stdint.h>

// ---------------- problem constants ----------------
#define DEPTH 2
#define DIM   1024
#define HEADS 16
#define DH    64
#define BATCH 8
#define NQ    256
#define JTOT  1088
#define MS    1024
#define MROWS (BATCH*NQ)    // 2048
#define CROWS (BATCH*JTOT)  // 8704
#define FFH   4096
#define SCALE 0.125f
#define NJT   17            // JTOT / 64

// ---------------- scratch ----------------
__device__ float g_Q[MROWS * DIM];
__device__ float g_K[CROWS * DIM];
__device__ float g_VT[(long)BATCH * DIM * JTOT];
__device__ float g_O[MROWS * DIM];
__device__ float g_Y[(long)MROWS * FFH];
__device__ float g_WqT[(long)DEPTH * DIM * DIM];
__device__ float g_WkT[(long)DEPTH * DIM * DIM];
__device__ float g_WvT[(long)DEPTH * DIM * DIM];
__device__ float g_WoT[(long)DEPTH * DIM * DIM];
__device__ float g_W1T[(long)DEPTH * 2 * FFH * DIM];
__device__ float g_W2T[(long)DEPTH * DIM * FFH];
__device__ float g_cosS[NQ * DH];
__device__ float g_sinS[NQ * DH];
__device__ float g_cosT[MS * DH];
__device__ float g_sinT[MS * DH];

// ---------------- ptx helpers ----------------
__device__ __forceinline__ float tf32r(float f) {
    uint32_t u;
    asm("cvt.rna.tf32.f32 %0, %1;" : "=r"(u) : "f"(f));
    return __uint_as_float(u);
}
__device__ __forceinline__ void ldsm4(uint32_t* r, uint32_t a) {
    asm volatile("ldmatrix.sync.aligned.m8n8.x4.shared.b16 {%0,%1,%2,%3}, [%4];"
                 : "=r"(r[0]), "=r"(r[1]), "=r"(r[2]), "=r"(r[3]) : "r"(a));
}
__device__ __forceinline__ void ldsm2(uint32_t* r, uint32_t a) {
    asm volatile("ldmatrix.sync.aligned.m8n8.x2.shared.b16 {%0,%1}, [%2];"
                 : "=r"(r[0]), "=r"(r[1]) : "r"(a));
}
__device__ __forceinline__ void mma_tf32(float* c, const uint32_t* a, const uint32_t* b) {
    asm volatile(
        "mma.sync.aligned.m16n8k8.row.col.f32.tf32.tf32.f32 "
        "{%0,%1,%2,%3}, {%4,%5,%6,%7}, {%8,%9}, {%0,%1,%2,%3};"
        : "+f"(c[0]), "+f"(c[1]), "+f"(c[2]), "+f"(c[3])
        : "r"(a[0]), "r"(a[1]), "r"(a[2]), "r"(a[3]), "r"(b[0]), "r"(b[1]));
}
__device__ __forceinline__ void mma_tf32b(float* c, const uint32_t* a, uint32_t b0, uint32_t b1) {
    asm volatile(
        "mma.sync.aligned.m16n8k8.row.col.f32.tf32.tf32.f32 "
        "{%0,%1,%2,%3}, {%4,%5,%6,%7}, {%8,%9}, {%0,%1,%2,%3};"
        : "+f"(c[0]), "+f"(c[1]), "+f"(c[2]), "+f"(c[3])
        : "r"(a[0]), "r"(a[1]), "r"(a[2]), "r"(a[3]), "r"(b0), "r"(b1));
}
__device__ __forceinline__ void cpa16(uint32_t d, const float* s) {
    asm volatile("cp.async.cg.shared.global [%0], [%1], 16;" :: "r"(d), "l"(s));
}

// ---- tf32 GEMM; EPI: 0=plain, 1=rope_q+scale, 2=rpe_bias+rope_k, 3=V^T out --
// BM=128, BN=128, BK=32. R6 fragment scheme (ldsm4 A, ldsm2 B).
template <int EPI>
__global__ void __launch_bounds__(256, 2)
gemm_tc(const float* __restrict__ A, const float* __restrict__ B,
        float* __restrict__ C, const float* __restrict__ Cadd,
        const float* __restrict__ bias,
        int K, int lda, int ldb, int ldc, float alpha,
        const float* __restrict__ ctab, const float* __restrict__ stab,
        const float* __restrict__ rpe_l, const int* __restrict__ rel_idx)
{
    constexpr int BM = 128, BN = 128;
    constexpr int ASZ = BM * 32, STF = ASZ + BN * 32;
    constexpr int WTM = 64, WTN = 32;   // WM=2, WN=4
    constexpr int MI = 4, NI = 4;

    extern __shared__ float smdyn[];
    const uint32_t sb = (uint32_t)__cvta_generic_to_shared(smdyn);

    const int tid = threadIdx.x, warp = tid >> 5, lane = tid & 31;
    const int wm = warp >> 2, wn = warp & 3;
    const int g = lane >> 2, t = lane & 3;
    const int bm0 = blockIdx.y * BM, bn0 = blockIdx.x * BN;

    const int arow = tid >> 3;
    const int cc   = tid & 7;

    const float* Ag = A + (long long)(bm0 + arow) * lda + cc * 4;
    const float* Bg = B + (long long)(bn0 + arow) * ldb + cc * 4;

    const int KT = K >> 5;

    auto load_stage = [&](int s, int kt) {
        if (kt < KT) {
            const int k0 = kt << 5;
            uint32_t ab = sb + (uint32_t)(s * STF) * 4u;
            uint32_t bb = ab + (uint32_t)ASZ * 4u;
            #pragma unroll
            for (int i = 0; i < 4; i++) {
                int r = arow + i * 32;
                uint32_t sw = (uint32_t)((cc ^ (r & 7)) << 4);
                cpa16(ab + r * 128 + sw, Ag + (long long)i * 32 * lda + k0);
                cpa16(bb + r * 128 + sw, Bg + (long long)i * 32 * ldb + k0);
            }
        }
        asm volatile("cp.async.commit_group;");
    };

    float acc[MI][NI][4];
    #pragma unroll
    for (int mi = 0; mi < MI; mi++)
        #pragma unroll
        for (int ni = 0; ni < NI; ni++)
            #pragma unroll
            for (int q = 0; q < 4; q++) acc[mi][ni][q] = 0.f;

    const int a_r  = lane & 15;
    const int a_kc = lane >> 4;
    const int b_r  = lane & 7;
    const int b_kc = (lane >> 3) & 1;

    load_stage(0, 0);
    load_stage(1, 1);

    for (int kt = 0; kt < KT; kt++) {
        asm volatile("cp.async.wait_group 1;");
        __syncthreads();
        load_stage((kt + 2) % 3, kt + 2);

        const int s = kt % 3;
        const uint32_t ab = sb + (uint32_t)(s * STF) * 4u;
        const uint32_t bb = ab + (uint32_t)ASZ * 4u;

        #pragma unroll
        for (int kk = 0; kk < 4; kk++) {
            uint32_t af[MI][4], bf[NI][2];
            #pragma unroll
            for (int mi = 0; mi < MI; mi++) {
                int r = wm * WTM + mi * 16 + a_r;
                int kc = kk * 2 + a_kc;
                ldsm4(af[mi], ab + r * 128 + ((kc ^ (r & 7)) << 4));
            }
            #pragma unroll
            for (int ni = 0; ni < NI; ni++) {
                int r = wn * WTN + ni * 8 + b_r;
                int kc = kk * 2 + b_kc;
                ldsm2(bf[ni], bb + r * 128 + ((kc ^ (r & 7)) << 4));
            }
            #pragma unroll
            for (int mi = 0; mi < MI; mi++)
                #pragma unroll
                for (int ni = 0; ni < NI; ni++)
                    mma_tf32(acc[mi][ni], af[mi], bf[ni]);
        }
    }

    #pragma unroll
    for (int mi = 0; mi < MI; mi++) {
        int row0 = bm0 + wm * WTM + mi * 16 + g;
        int jA = 0, jB = 0, bA = 0, bB = 0;
        if (EPI == 2 || EPI == 3) {
            bA = row0 / JTOT;       jA = row0 - bA * JTOT;
            bB = (row0 + 8) / JTOT; jB = (row0 + 8) - bB * JTOT;
        }
        #pragma unroll
        for (int ni = 0; ni < NI; ni++) {
            int col = bn0 + wn * WTN + ni * 8 + 2 * t;
            float v0 = alpha * acc[mi][ni][0];
            float v1 = alpha * acc[mi][ni][1];
            float v2 = alpha * acc[mi][ni][2];
            float v3 = alpha * acc[mi][ni][3];
            if (bias) { float b0 = bias[col], b1 = bias[col + 1]; v0 += b0; v1 += b1; v2 += b0; v3 += b1; }
            if (Cadd) {
                const float2 c0 = *(const float2*)(Cadd + (long long)row0 * ldc + col);
                const float2 c1 = *(const float2*)(Cadd + (long long)(row0 + 8) * ldc + col);
                v0 += c0.x; v1 += c0.y; v2 += c1.x; v3 += c1.y;
            }
            if (EPI == 1) {
                int d = col & (DH - 1);
                int nA = row0 & (NQ - 1), nB = (row0 + 8) & (NQ - 1);
                float cA0 = ctab[nA * DH + d],     sA0 = stab[nA * DH + d];
                float cA1 = ctab[nA * DH + d + 1], sA1 = stab[nA * DH + d + 1];
                float cB0 = ctab[nB * DH + d],     sB0 = stab[nB * DH + d];
                float cB1 = ctab[nB * DH + d + 1], sB1 = stab[nB * DH + d + 1];
                float o0 = (v0 * cA0 - v1 * sA0) * SCALE;
                float o1 = (v1 * cA1 + v0 * sA1) * SCALE;
                float o2 = (v2 * cB0 - v3 * sB0) * SCALE;
                float o3 = (v3 * cB1 + v2 * sB1) * SCALE;
                v0 = o0; v1 = o1; v2 = o2; v3 = o3;
            }
            if (EPI == 2) {
                int d = col & (DH - 1);
                int h = col >> 6;
                if (jA < MS) {
                    float bb2 = rpe_l[rel_idx[jA >> 8] * HEADS + h];
                    float k0 = v0 + bb2, k1 = v1 + bb2;
                    float c0 = ctab[jA * DH + d],     s0 = stab[jA * DH + d];
                    float c1 = ctab[jA * DH + d + 1], s1 = stab[jA * DH + d + 1];
                    v0 = k0 * c0 - k1 * s0;
                    v1 = k1 * c1 + k0 * s1;
                }
                if (jB < MS) {
                    float bb2 = rpe_l[rel_idx[jB >> 8] * HEADS + h];
                    float k0 = v2 + bb2, k1 = v3 + bb2;
                    float c0 = ctab[jB * DH + d],     s0 = stab[jB * DH + d];
                    float c1 = ctab[jB * DH + d + 1], s1 = stab[jB * DH + d + 1];
                    v2 = k0 * c0 - k1 * s0;
                    v3 = k1 * c1 + k0 * s1;
                }
            }
            if (EPI == 3) {
                // C = VT base: element (b, d, j) at b*DIM*JTOT + d*JTOT + j
                float* vtA = C + (long long)bA * DIM * JTOT + (long long)col * JTOT + jA;
                float* vtB = C + (long long)bB * DIM * JTOT + (long long)col * JTOT + jB;
                vtA[0]    = tf32r(v0);
                vtA[JTOT] = tf32r(v1);
                vtB[0]    = tf32r(v2);
                vtB[JTOT] = tf32r(v3);
            } else {
                *(float2*)(C + (long long)row0 * ldc + col) = make_float2(v0, v1);
                *(float2*)(C + (long long)(row0 + 8) * ldc + col) = make_float2(v2, v3);
            }
        }
    }
}

// ---------------- FFN1 + GEGLU fused (R6 exact) ----------------
__global__ void __launch_bounds__(256, 2)
gemm_ffn1(const float* __restrict__ A, const float* __restrict__ B,
          float* __restrict__ Y, const float* __restrict__ b1l)
{
    constexpr int BM = 128, BN = 64;
    constexpr int ASZ = BM * 32, BSZ = BN * 32, STF = ASZ + 2 * BSZ;
    constexpr int WTM = 32, WTN = 32, MI = 2, NI = 4;
    const int KT = 32;

    extern __shared__ float smdyn[];
    const uint32_t sb = (uint32_t)__cvta_generic_to_shared(smdyn);

    const int tid = threadIdx.x, warp = tid >> 5, lane = tid & 31;
    const int wm = warp >> 1, wn = warp & 1;
    const int g = lane >> 2, t = lane & 3;
    const int bm0 = blockIdx.y * BM, bn0 = blockIdx.x * BN;

    const int arow = tid >> 3;
    const int cc   = tid & 7;

    const float* Ag  = A + (long long)(bm0 + arow) * DIM + cc * 4;
    const float* Bga = B + (long long)(bn0 + arow) * DIM + cc * 4;
    const float* Bgg = B + (long long)(FFH + bn0 + arow) * DIM + cc * 4;

    auto load_stage = [&](int s, int kt) {
        if (kt < KT) {
            const int k0 = kt << 5;
            uint32_t ab = sb + (uint32_t)(s * STF) * 4u;
            #pragma unroll
            for (int i = 0; i < 4; i++) {
                int r = arow + i * 32;
                cpa16(ab + r * 128 + ((cc ^ (r & 7)) << 4),
                      Ag + (long long)i * 32 * DIM + k0);
            }
            uint32_t bba = sb + (uint32_t)(s * STF + ASZ) * 4u;
            uint32_t bbg = bba + (uint32_t)BSZ * 4u;
            #pragma unroll
            for (int i = 0; i < 2; i++) {
                int r = arow + i * 32;
                uint32_t sw = (uint32_t)((cc ^ (r & 7)) << 4);
                cpa16(bba + r * 128 + sw, Bga + (long long)i * 32 * DIM + k0);
                cpa16(bbg + r * 128 + sw, Bgg + (long long)i * 32 * DIM + k0);
            }
        }
        asm volatile("cp.async.commit_group;");
    };

    float acca[MI][NI][4], accg[MI][NI][4];
    #pragma unroll
    for (int mi = 0; mi < MI; mi++)
        #pragma unroll
        for (int ni = 0; ni < NI; ni++)
            #pragma unroll
            for (int q = 0; q < 4; q++) { acca[mi][ni][q] = 0.f; accg[mi][ni][q] = 0.f; }

    const int a_r  = lane & 15;
    const int a_kc = lane >> 4;
    const int b_r  = lane & 7;
    const int b_kc = (lane >> 3) & 1;

    load_stage(0, 0);
    load_stage(1, 1);

    for (int kt = 0; kt < KT; kt++) {
        asm volatile("cp.async.wait_group 1;");
        __syncthreads();
        load_stage((kt + 2) % 3, kt + 2);

        const int s = kt % 3;
        const uint32_t ab  = sb + (uint32_t)(s * STF) * 4u;
        const uint32_t bba = ab + (uint32_t)ASZ * 4u;
        const uint32_t bbg = bba + (uint32_t)BSZ * 4u;

        #pragma unroll
        for (int kk = 0; kk < 4; kk++) {
            uint32_t af[MI][4], bfa[NI][2], bfg[NI][2];
            #pragma unroll
            for (int mi = 0; mi < MI; mi++) {
                int r = wm * WTM + mi * 16 + a_r;
                int kc = kk * 2 + a_kc;
                ldsm4(af[mi], ab + r * 128 + ((kc ^ (r & 7)) << 4));
            }
            #pragma unroll
            for (int ni = 0; ni < NI; ni++) {
                int r = wn * WTN + ni * 8 + b_r;
                int kc = kk * 2 + b_kc;
                ldsm2(bfa[ni], bba + r * 128 + ((kc ^ (r & 7)) << 4));
                ldsm2(bfg[ni], bbg + r * 128 + ((kc ^ (r & 7)) << 4));
            }
            #pragma unroll
            for (int mi = 0; mi < MI; mi++)
                #pragma unroll
                for (int ni = 0; ni < NI; ni++) {
                    mma_tf32(acca[mi][ni], af[mi], bfa[ni]);
                    mma_tf32(accg[mi][ni], af[mi], bfg[ni]);
                }
        }
    }

    #pragma unroll
    for (int mi = 0; mi < MI; mi++) {
        int row0 = bm0 + wm * WTM + mi * 16 + g;
        #pragma unroll
        for (int ni = 0; ni < NI; ni++) {
            int col = bn0 + wn * WTN + ni * 8 + 2 * t;
            float ba0 = b1l[col], ba1 = b1l[col + 1];
            float bg0 = b1l[FFH + col], bg1 = b1l[FFH + col + 1];
            #pragma unroll
            for (int half = 0; half < 2; half++) {
                float a0 = acca[mi][ni][half * 2 + 0] + ba0;
                float a1 = acca[mi][ni][half * 2 + 1] + ba1;
                float g0 = accg[mi][ni][half * 2 + 0] + bg0;
                float g1 = accg[mi][ni][half * 2 + 1] + bg1;
                float y0 = a0 * (0.5f * g0 * (1.0f + erff(g0 * 0.70710678118654752f)));
                float y1 = a1 * (0.5f * g1 * (1.0f + erff(g1 * 0.70710678118654752f)));
                *(float2*)(Y + (long long)(row0 + half * 8) * FFH + col) = make_float2(y0, y1);
            }
        }
    }
}

// ---------------- flash attention ----------------
__global__ void __launch_bounds__(256)
flash_attn(const float* __restrict__ Q, const float* __restrict__ K,
           const float* __restrict__ VT, float* __restrict__ O)
{
    extern __shared__ float sm[];
    const uint32_t sb = (uint32_t)__cvta_generic_to_shared(sm);
    const uint32_t qb = sb;
    const uint32_t kb = sb + 8192u * 4u;
    const uint32_t vb = sb + 16384u * 4u;
    const uint32_t pb = sb + 24576u * 4u;

    const int tid = threadIdx.x, warp = tid >> 5, lane = tid & 31;
    const int g = lane >> 2, t = lane & 3;
    const int m0 = blockIdx.x * 128;
    const int z = blockIdx.y;
    const int b = z >> 4, h = z & 15;

    const float* Qg = Q + ((long long)(b * NQ + m0)) * DIM + h * DH;
    const float* Kg = K + (long long)b * JTOT * DIM + h * DH;
    const float* Vg = VT + (long long)b * DIM * JTOT + (long long)h * DH * JTOT;
    float* Og = O + ((long long)(b * NQ + m0)) * DIM + h * DH;

    auto load_kv_body = [&](int s, int jt) {
        #pragma unroll
        for (int i = 0; i < 4; i++) {
            int idx = tid + i * 256;
            int cc = idx & 7, r = (idx >> 3) & 63, hf = idx >> 9;
            uint32_t off = (uint32_t)(s * 4096 + (hf * 64 + r) * 32) * 4u + ((cc ^ (r & 7)) << 4);
            cpa16(kb + off, Kg + (long long)(jt * 64 + r) * DIM + hf * 32 + cc * 4);
            cpa16(vb + off, Vg + (long long)r * JTOT + jt * 64 + hf * 32 + cc * 4);
        }
    };

    #pragma unroll
    for (int i = 0; i < 8; i++) {
        int idx = tid + i * 256;
        int cc = idx & 7, r = (idx >> 3) & 127, hf = idx >> 10;
        cpa16(qb + (uint32_t)(hf * 128 + r) * 128u + ((cc ^ (r & 7)) << 4),
              Qg + (long long)r * DIM + hf * 32 + cc * 4);
    }
    load_kv_body(0, 0);
    asm volatile("cp.async.commit_group;");
    load_kv_body(1, 1);
    asm volatile("cp.async.commit_group;");

    float acco[8][4];
    #pragma unroll
    for (int ni = 0; ni < 8; ni++)
        #pragma unroll
        for (int q = 0; q < 4; q++) acco[ni][q] = 0.f;
    float mr0 = -INFINITY, mr1 = -INFINITY, l0 = 0.f, l1 = 0.f;

    const int fr = lane & 15;
    const int fc = lane >> 4;

    for (int jt = 0; jt < NJT; jt++) {
        const int s = jt & 1;
        asm volatile("cp.async.wait_group 1;");
        __syncthreads();

        float accs[8][4];
        #pragma unroll
        for (int ni = 0; ni < 8; ni++)
            #pragma unroll
            for (int q = 0; q < 4; q++) accs[ni][q] = 0.f;

        #pragma unroll
        for (int kk = 0; kk < 8; kk++) {
            const int hf = kk >> 2;
            const int kc = (kk & 3) * 2 + fc;
            uint32_t a[4];
            {
                int r = warp * 16 + fr;
                ldsm4(a, qb + (uint32_t)(hf * 128 + r) * 128u + ((kc ^ (r & 7)) << 4));
            }
            #pragma unroll
            for (int p = 0; p < 4; p++) {
                int r = p * 16 + fr;
                uint32_t bf[4];
                ldsm4(bf, kb + (uint32_t)(s * 4096 + (hf * 64 + r) * 32) * 4u + ((kc ^ (r & 7)) << 4));
                mma_tf32b(accs[2 * p],     a, bf[0], bf[2]);
                mma_tf32b(accs[2 * p + 1], a, bf[1], bf[3]);
            }
        }

        float vm0 = -INFINITY, vm1 = -INFINITY;
        #pragma unroll
        for (int ni = 0; ni < 8; ni++) {
            vm0 = fmaxf(vm0, fmaxf(accs[ni][0], accs[ni][1]));
            vm1 = fmaxf(vm1, fmaxf(accs[ni][2], accs[ni][3]));
        }
        vm0 = fmaxf(vm0, __shfl_xor_sync(0xffffffffu, vm0, 1));
        vm0 = fmaxf(vm0, __shfl_xor_sync(0xffffffffu, vm0, 2));
        vm1 = fmaxf(vm1, __shfl_xor_sync(0xffffffffu, vm1, 1));
        vm1 = fmaxf(vm1, __shfl_xor_sync(0xffffffffu, vm1, 2));
        float mn0 = fmaxf(mr0, vm0), mn1 = fmaxf(mr1, vm1);
        float sc0 = __expf(mr0 - mn0), sc1 = __expf(mr1 - mn1);

        float ps0 = 0.f, ps1 = 0.f;
        float pv[8][4];
        #pragma unroll
        for (int ni = 0; ni < 8; ni++) {
            pv[ni][0] = tf32r(__expf(accs[ni][0] - mn0));
            pv[ni][1] = tf32r(__expf(accs[ni][1] - mn0));
            pv[ni][2] = tf32r(__expf(accs[ni][2] - mn1));
            pv[ni][3] = tf32r(__expf(accs[ni][3] - mn1));
            ps0 += pv[ni][0] + pv[ni][1];
            ps1 += pv[ni][2] + pv[ni][3];
        }
        ps0 += __shfl_xor_sync(0xffffffffu, ps0, 1);
        ps0 += __shfl_xor_sync(0xffffffffu, ps0, 2);
        ps1 += __shfl_xor_sync(0xffffffffu, ps1, 1);
        ps1 += __shfl_xor_sync(0xffffffffu, ps1, 2);
        l0 = l0 * sc0 + ps0;
        l1 = l1 * sc1 + ps1;
        mr0 = mn0; mr1 = mn1;
        #pragma unroll
        for (int ni = 0; ni < 8; ni++) {
            acco[ni][0] *= sc0; acco[ni][1] *= sc0;
            acco[ni][2] *= sc1; acco[ni][3] *= sc1;
        }

        const int r0 = warp * 16 + g, r1 = r0 + 8;
        #pragma unroll
        for (int ni = 0; ni < 8; ni++) {
            int hf = ni >> 2;
            int cc = (ni & 3) * 2 + (t >> 1);
            uint32_t ofs = (uint32_t)((t & 1) * 8);
            uint32_t a0 = pb + (uint32_t)(hf * 128 + r0) * 128u + ((cc ^ (r0 & 7)) << 4) + ofs;
            uint32_t a1 = pb + (uint32_t)(hf * 128 + r1) * 128u + ((cc ^ (r1 & 7)) << 4) + ofs;
            asm volatile("st.shared.v2.f32 [%0], {%1,%2};" :: "r"(a0), "f"(pv[ni][0]), "f"(pv[ni][1]));
            asm volatile("st.shared.v2.f32 [%0], {%1,%2};" :: "r"(a1), "f"(pv[ni][2]), "f"(pv[ni][3]));
        }
        __syncwarp();

        #pragma unroll
        for (int kk = 0; kk < 8; kk++) {
            const int hf = kk >> 2;
            const int kc = (kk & 3) * 2 + fc;
            uint32_t a[4];
            {
                int r = warp * 16 + fr;
                ldsm4(a, pb + (uint32_t)(hf * 128 + r) * 128u + ((kc ^ (r & 7)) << 4));
            }
            #pragma unroll
            for (int p = 0; p < 4; p++) {
                int r = p * 16 + fr;
                uint32_t bf[4];
                ldsm4(bf, vb + (uint32_t)(s * 4096 + (hf * 64 + r) * 32) * 4u + ((kc ^ (r & 7)) << 4));
                mma_tf32b(acco[2 * p],     a, bf[0], bf[2]);
                mma_tf32b(acco[2 * p + 1], a, bf[1], bf[3]);
            }
        }
        __syncthreads();

        if (jt + 2 < NJT) load_kv_body(s, jt + 2);
        asm volatile("cp.async.commit_group;");
    }

    float inv0 = 1.f / l0, inv1 = 1.f / l1;
    const int r0 = warp * 16 + g, r1 = r0 + 8;
    #pragma unroll
    for (int ni = 0; ni < 8; ni++) {
        int col = ni * 8 + 2 * t;
        *(float2*)(Og + (long long)r0 * DIM + col) =
            make_float2(acco[ni][0] * inv0, acco[ni][1] * inv0);
        *(float2*)(Og + (long long)r1 * DIM + col) =
            make_float2(acco[ni][2] * inv1, acco[ni][3] * inv1);
    }
}

// ---------------- batched weight transpose (single launch) ----------------
__global__ void __launch_bounds__(256)
wtrans_all(const float* __restrict__ Wq, const float* __restrict__ Wk,
           const float* __restrict__ Wv, const float* __restrict__ Wo,
           const float* __restrict__ W1, const float* __restrict__ W2,
           float* __restrict__ WqT, float* __restrict__ WkT,
           float* __restrict__ WvT, float* __restrict__ WoT,
           float* __restrict__ W1T, float* __restrict__ W2T)
{
    __shared__ float tbuf[32][33];
    const float* ins[6] = {Wq, Wk, Wv, Wo, W1, W2};
    float* outs[6] = {WqT, WkT, WvT, WoT, W1T, W2T};
    const int Rs[6] = {DIM, DIM, DIM, DIM, DIM, FFH};
    const int Cs[6] = {DIM, DIM, DIM, DIM, 2 * FFH, DIM};

    int tile = blockIdx.x, job = 0;
    #pragma unroll
    for (int j2 = 0; j2 < 6; j2++) {
        int nt = DEPTH * (Rs[j2] / 32) * (Cs[j2] / 32);
        if (tile >= nt) { tile -= nt; job++; }
        else break;
    }
    const int R = Rs[job], C = Cs[job];
    const int tpz = (R / 32) * (C / 32);
    const int zdx = tile / tpz;
    const int rem = tile - zdx * tpz;
    const int ty = rem / (C / 32), tx = rem - ty * (C / 32);
    const float* in = ins[job] + (long long)zdx * R * C;
    float* out = outs[job] + (long long)zdx * R * C;

    int c0 = tx * 32, r0 = ty * 32;
    int x = threadIdx.x & 31, y = threadIdx.x >> 5;
    #pragma unroll
    for (int i = 0; i < 32; i += 8)
        tbuf[y + i][x] = in[(long long)(r0 + y + i) * C + c0 + x];
    __syncthreads();
    #pragma unroll
    for (int i = 0; i < 32; i += 8)
        out[(long long)(c0 + y + i) * R + r0 + x] = tf32r(tbuf[x][y + i]);
}

// ---------------- cos/sin tables ----------------
__global__ void prep_trig(const float* __restrict__ srcf, const float* __restrict__ tgtf,
                          float* __restrict__ cS, float* __restrict__ sS,
                          float* __restrict__ cT, float* __restrict__ sT)
{
    int idx = blockIdx.x * blockDim.x + threadIdx.x;
    if (idx < NQ * DH) {
        float f = srcf[idx];
        cS[idx] = cosf(f); sS[idx] = sinf(f);
    } else if (idx < NQ * DH + MS * DH) {
        int i = idx - NQ * DH;
        float f = tgtf[i];
        cT[i] = cosf(f); sT[i] = sinf(f);
    }
}

// ---------------- launcher ----------------
extern "C" void kernel_launch(void* const* d_in, const int* in_sizes, int n_in,
                              void* d_out, int out_size)
{
    const float* x    = (const float*)d_in[0];
    const float* cond = (const float*)d_in[1];
    const float* Wq   = (const float*)d_in[2];
    const float* Wk   = (const float*)d_in[3];
    const float* Wv   = (const float*)d_in[4];
    const float* Wo   = (const float*)d_in[5];
    const float* bo   = (const float*)d_in[6];
    const float* rpe  = (const float*)d_in[7];
    const float* W1   = (const float*)d_in[8];
    const float* b1   = (const float*)d_in[9];
    const float* W2   = (const float*)d_in[10];
    const float* b2   = (const float*)d_in[11];
    const float* srcf = (const float*)d_in[12];
    const float* tgtf = (const float*)d_in[13];
    const int*   reli = (const int*)d_in[14];
    float* xo = (float*)d_out;

    float *Q, *K, *VT, *O, *Y;
    float *WqT, *WkT, *WvT, *WoT, *W1T, *W2T;
    float *cS, *sS, *cT, *sT;
    cudaGetSymbolAddress((void**)&Q, g_Q);
    cudaGetSymbolAddress((void**)&K, g_K);
    cudaGetSymbolAddress((void**)&VT, g_VT);
    cudaGetSymbolAddress((void**)&O, g_O);
    cudaGetSymbolAddress((void**)&Y, g_Y);
    cudaGetSymbolAddress((void**)&WqT, g_WqT);
    cudaGetSymbolAddress((void**)&WkT, g_WkT);
    cudaGetSymbolAddress((void**)&WvT, g_WvT);
    cudaGetSymbolAddress((void**)&WoT, g_WoT);
    cudaGetSymbolAddress((void**)&W1T, g_W1T);
    cudaGetSymbolAddress((void**)&W2T, g_W2T);
    cudaGetSymbolAddress((void**)&cS, g_cosS);
    cudaGetSymbolAddress((void**)&sS, g_sinS);
    cudaGetSymbolAddress((void**)&cT, g_cosT);
    cudaGetSymbolAddress((void**)&sT, g_sinT);

    const int SM128 = (128 * 32 + 128 * 32) * 3 * 4;     // 96 KB
    const int SMF1  = (128 * 32 + 2 * 64 * 32) * 3 * 4;  // 96 KB
    const int SMFL  = 32768 * 4;                         // 128 KB
    cudaFuncSetAttribute(gemm_tc<0>, cudaFuncAttributeMaxDynamicSharedMemorySize, SM128);
    cudaFuncSetAttribute(gemm_tc<1>, cudaFuncAttributeMaxDynamicSharedMemorySize, SM128);
    cudaFuncSetAttribute(gemm_tc<2>, cudaFuncAttributeMaxDynamicSharedMemorySize, SM128);
    cudaFuncSetAttribute(gemm_tc<3>, cudaFuncAttributeMaxDynamicSharedMemorySize, SM128);
    cudaFuncSetAttribute(gemm_ffn1, cudaFuncAttributeMaxDynamicSharedMemorySize, SMF1);
    cudaFuncSetAttribute(flash_attn, cudaFuncAttributeMaxDynamicSharedMemorySize, SMFL);

    cudaMemcpyAsync(xo, x, (size_t)MROWS * DIM * sizeof(float),
                    cudaMemcpyDeviceToDevice, 0);

    wtrans_all<<<32768, 256>>>(Wq, Wk, Wv, Wo, W1, W2, WqT, WkT, WvT, WoT, W1T, W2T);
    prep_trig<<<((NQ + MS) * DH + 255) / 256, 256>>>(srcf, tgtf, cS, sS, cT, sT);

    for (int l = 0; l < DEPTH; l++) {
        const float* wqt = WqT + (long long)l * DIM * DIM;
        const float* wkt = WkT + (long long)l * DIM * DIM;
        const float* wvt = WvT + (long long)l * DIM * DIM;
        const float* wot = WoT + (long long)l * DIM * DIM;
        const float* bol = bo + l * DIM;
        const float* rpel = rpe + (long long)l * 405 * HEADS;
        const float* w1t = W1T + (long long)l * DIM * 2 * FFH;
        const float* b1l = b1 + (long long)l * (2 * FFH);
        const float* w2t = W2T + (long long)l * DIM * FFH;
        const float* b2l = b2 + l * DIM;

        // Q = rope(x @ Wq) * SCALE
        gemm_tc<1><<<dim3(DIM / 128, MROWS / 128), 256, SM128>>>(
            xo, wqt, Q, nullptr, nullptr,
            DIM, DIM, DIM, DIM, 1.0f, cS, sS, nullptr, nullptr);
        // VT = (cond @ Wv)^T per batch (fused transpose epilogue)
        gemm_tc<3><<<dim3(DIM / 128, CROWS / 128), 256, SM128>>>(
            cond, wvt, VT, nullptr, nullptr,
            DIM, DIM, DIM, DIM, 1.0f, nullptr, nullptr, nullptr, nullptr);
        // K = rope_bias(cond @ Wk)
        gemm_tc<2><<<dim3(DIM / 128, CROWS / 128), 256, SM128>>>(
            cond, wkt, K, nullptr, nullptr,
            DIM, DIM, DIM, DIM, 1.0f, cT, sT, rpel, reli);

        // fused attention -> O
        flash_attn<<<dim3(NQ / 128, BATCH * HEADS), 256, SMFL>>>(Q, K, VT, O);

        // x = x + O @ Wo + bo
        gemm_tc<0><<<dim3(DIM / 128, MROWS / 128), 256, SM128>>>(
            O, wot, xo, xo, bol,
            DIM, DIM, DIM, DIM, 1.0f, nullptr, nullptr, nullptr, nullptr);

        // Y = GEGLU(x @ W1 + b1)
        gemm_ffn1<<<dim3(FFH / 64, MROWS / 128), 256, SMF1>>>(xo, w1t, Y, b1l);

        // x = x + Y @ W2 + b2
        gemm_tc<0><<<dim3(DIM / 128, MROWS / 128), 256, SM128>>>(
            Y, w2t, xo, xo, b2l,
            FFH, FFH, FFH, DIM, 1.0f, nullptr, nullptr, nullptr, nullptr);
    }
}

// round 10
// speedup vs baseline: 1.0765x; 1.0057x over previous
#include <cuda_runtime.h>
#include <math.h>
#include <stdint.h>

// ---------------- problem constants ----------------
#define DEPTH 2
#define DIM   1024
#define HEADS 16
#define DH    64
#define BATCH 8
#define NQ    256
#define JTOT  1088
#define MS    1024
#define MROWS (BATCH*NQ)    // 2048
#define CROWS (BATCH*JTOT)  // 8704
#define FFH   4096
#define SCALE 0.125f
#define NJT   17            // JTOT / 64

// ---------------- scratch ----------------
__device__ float g_Q[MROWS * DIM];
__device__ float g_K[CROWS * DIM];
__device__ float g_VT[(long)BATCH * DIM * JTOT];
__device__ float g_O[MROWS * DIM];
__device__ float g_Y[(long)MROWS * FFH];
__device__ float g_WqT[(long)DEPTH * DIM * DIM];
__device__ float g_WkT[(long)DEPTH * DIM * DIM];
__device__ float g_WvT[(long)DEPTH * DIM * DIM];
__device__ float g_WoT[(long)DEPTH * DIM * DIM];
__device__ float g_W1T[(long)DEPTH * 2 * FFH * DIM];
__device__ float g_W2T[(long)DEPTH * DIM * FFH];
__device__ float g_cosS[NQ * DH];
__device__ float g_sinS[NQ * DH];
__device__ float g_cosT[MS * DH];
__device__ float g_sinT[MS * DH];

// ---------------- ptx helpers ----------------
__device__ __forceinline__ float tf32r(float f) {
    uint32_t u;
    asm("cvt.rna.tf32.f32 %0, %1;" : "=r"(u) : "f"(f));
    return __uint_as_float(u);
}
__device__ __forceinline__ void ldsm4(uint32_t* r, uint32_t a) {
    asm volatile("ldmatrix.sync.aligned.m8n8.x4.shared.b16 {%0,%1,%2,%3}, [%4];"
                 : "=r"(r[0]), "=r"(r[1]), "=r"(r[2]), "=r"(r[3]) : "r"(a));
}
__device__ __forceinline__ void ldsm2(uint32_t* r, uint32_t a) {
    asm volatile("ldmatrix.sync.aligned.m8n8.x2.shared.b16 {%0,%1}, [%2];"
                 : "=r"(r[0]), "=r"(r[1]) : "r"(a));
}
__device__ __forceinline__ void mma_tf32(float* c, const uint32_t* a, const uint32_t* b) {
    asm volatile(
        "mma.sync.aligned.m16n8k8.row.col.f32.tf32.tf32.f32 "
        "{%0,%1,%2,%3}, {%4,%5,%6,%7}, {%8,%9}, {%0,%1,%2,%3};"
        : "+f"(c[0]), "+f"(c[1]), "+f"(c[2]), "+f"(c[3])
        : "r"(a[0]), "r"(a[1]), "r"(a[2]), "r"(a[3]), "r"(b[0]), "r"(b[1]));
}
__device__ __forceinline__ void mma_tf32b(float* c, const uint32_t* a, uint32_t b0, uint32_t b1) {
    asm volatile(
        "mma.sync.aligned.m16n8k8.row.col.f32.tf32.tf32.f32 "
        "{%0,%1,%2,%3}, {%4,%5,%6,%7}, {%8,%9}, {%0,%1,%2,%3};"
        : "+f"(c[0]), "+f"(c[1]), "+f"(c[2]), "+f"(c[3])
        : "r"(a[0]), "r"(a[1]), "r"(a[2]), "r"(a[3]), "r"(b0), "r"(b1));
}
__device__ __forceinline__ void cpa16(uint32_t d, const float* s) {
    asm volatile("cp.async.cg.shared.global [%0], [%1], 16;" :: "r"(d), "l"(s));
}

// ---- tf32 GEMM; EPI: 0=plain, 1=rope_q+scale, 2=rpe_bias+rope_k, 3=V^T out --
template <int EPI>
__global__ void __launch_bounds__(256, 2)
gemm_tc(const float* __restrict__ A, const float* __restrict__ B,
        float* __restrict__ C, const float* __restrict__ Cadd,
        const float* __restrict__ bias,
        int K, int lda, int ldb, int ldc, float alpha,
        const float* __restrict__ ctab, const float* __restrict__ stab,
        const float* __restrict__ rpe_l, const int* __restrict__ rel_idx)
{
    constexpr int BM = 128, BN = 128;
    constexpr int ASZ = BM * 32, STF = ASZ + BN * 32;
    constexpr int WTM = 64, WTN = 32;   // WM=2, WN=4
    constexpr int MI = 4, NI = 4;

    extern __shared__ float smdyn[];
    const uint32_t sb = (uint32_t)__cvta_generic_to_shared(smdyn);

    const int tid = threadIdx.x, warp = tid >> 5, lane = tid & 31;
    const int wm = warp >> 2, wn = warp & 3;
    const int g = lane >> 2, t = lane & 3;
    const int bm0 = blockIdx.y * BM, bn0 = blockIdx.x * BN;

    const int arow = tid >> 3;
    const int cc   = tid & 7;

    const float* Ag = A + (long long)(bm0 + arow) * lda + cc * 4;
    const float* Bg = B + (long long)(bn0 + arow) * ldb + cc * 4;

    const int KT = K >> 5;

    auto load_stage = [&](int s, int kt) {
        if (kt < KT) {
            const int k0 = kt << 5;
            uint32_t ab = sb + (uint32_t)(s * STF) * 4u;
            uint32_t bb = ab + (uint32_t)ASZ * 4u;
            #pragma unroll
            for (int i = 0; i < 4; i++) {
                int r = arow + i * 32;
                uint32_t sw = (uint32_t)((cc ^ (r & 7)) << 4);
                cpa16(ab + r * 128 + sw, Ag + (long long)i * 32 * lda + k0);
                cpa16(bb + r * 128 + sw, Bg + (long long)i * 32 * ldb + k0);
            }
        }
        asm volatile("cp.async.commit_group;");
    };

    float acc[MI][NI][4];
    #pragma unroll
    for (int mi = 0; mi < MI; mi++)
        #pragma unroll
        for (int ni = 0; ni < NI; ni++)
            #pragma unroll
            for (int q = 0; q < 4; q++) acc[mi][ni][q] = 0.f;

    const int a_r  = lane & 15;
    const int a_kc = lane >> 4;
    const int b_r  = lane & 7;
    const int b_kc = (lane >> 3) & 1;

    load_stage(0, 0);
    load_stage(1, 1);

    for (int kt = 0; kt < KT; kt++) {
        asm volatile("cp.async.wait_group 1;");
        __syncthreads();
        load_stage((kt + 2) % 3, kt + 2);

        const int s = kt % 3;
        const uint32_t ab = sb + (uint32_t)(s * STF) * 4u;
        const uint32_t bb = ab + (uint32_t)ASZ * 4u;

        #pragma unroll
        for (int kk = 0; kk < 4; kk++) {
            uint32_t af[MI][4], bf[NI][2];
            #pragma unroll
            for (int mi = 0; mi < MI; mi++) {
                int r = wm * WTM + mi * 16 + a_r;
                int kc = kk * 2 + a_kc;
                ldsm4(af[mi], ab + r * 128 + ((kc ^ (r & 7)) << 4));
            }
            #pragma unroll
            for (int ni = 0; ni < NI; ni++) {
                int r = wn * WTN + ni * 8 + b_r;
                int kc = kk * 2 + b_kc;
                ldsm2(bf[ni], bb + r * 128 + ((kc ^ (r & 7)) << 4));
            }
            #pragma unroll
            for (int mi = 0; mi < MI; mi++)
                #pragma unroll
                for (int ni = 0; ni < NI; ni++)
                    mma_tf32(acc[mi][ni], af[mi], bf[ni]);
        }
    }

    #pragma unroll
    for (int mi = 0; mi < MI; mi++) {
        int row0 = bm0 + wm * WTM + mi * 16 + g;
        int jA = 0, jB = 0, bA = 0, bB = 0;
        if (EPI == 2 || EPI == 3) {
            bA = row0 / JTOT;       jA = row0 - bA * JTOT;
            bB = (row0 + 8) / JTOT; jB = (row0 + 8) - bB * JTOT;
        }
        #pragma unroll
        for (int ni = 0; ni < NI; ni++) {
            int col = bn0 + wn * WTN + ni * 8 + 2 * t;
            float v0 = alpha * acc[mi][ni][0];
            float v1 = alpha * acc[mi][ni][1];
            float v2 = alpha * acc[mi][ni][2];
            float v3 = alpha * acc[mi][ni][3];
            if (bias) { float b0 = bias[col], b1 = bias[col + 1]; v0 += b0; v1 += b1; v2 += b0; v3 += b1; }
            if (Cadd) {
                const float2 c0 = *(const float2*)(Cadd + (long long)row0 * ldc + col);
                const float2 c1 = *(const float2*)(Cadd + (long long)(row0 + 8) * ldc + col);
                v0 += c0.x; v1 += c0.y; v2 += c1.x; v3 += c1.y;
            }
            if (EPI == 1) {
                int d = col & (DH - 1);
                int nA = row0 & (NQ - 1), nB = (row0 + 8) & (NQ - 1);
                float cA0 = ctab[nA * DH + d],     sA0 = stab[nA * DH + d];
                float cA1 = ctab[nA * DH + d + 1], sA1 = stab[nA * DH + d + 1];
                float cB0 = ctab[nB * DH + d],     sB0 = stab[nB * DH + d];
                float cB1 = ctab[nB * DH + d + 1], sB1 = stab[nB * DH + d + 1];
                float o0 = (v0 * cA0 - v1 * sA0) * SCALE;
                float o1 = (v1 * cA1 + v0 * sA1) * SCALE;
                float o2 = (v2 * cB0 - v3 * sB0) * SCALE;
                float o3 = (v3 * cB1 + v2 * sB1) * SCALE;
                v0 = o0; v1 = o1; v2 = o2; v3 = o3;
            }
            if (EPI == 2) {
                int d = col & (DH - 1);
                int h = col >> 6;
                if (jA < MS) {
                    float bb2 = rpe_l[rel_idx[jA >> 8] * HEADS + h];
                    float k0 = v0 + bb2, k1 = v1 + bb2;
                    float c0 = ctab[jA * DH + d],     s0 = stab[jA * DH + d];
                    float c1 = ctab[jA * DH + d + 1], s1 = stab[jA * DH + d + 1];
                    v0 = k0 * c0 - k1 * s0;
                    v1 = k1 * c1 + k0 * s1;
                }
                if (jB < MS) {
                    float bb2 = rpe_l[rel_idx[jB >> 8] * HEADS + h];
                    float k0 = v2 + bb2, k1 = v3 + bb2;
                    float c0 = ctab[jB * DH + d],     s0 = stab[jB * DH + d];
                    float c1 = ctab[jB * DH + d + 1], s1 = stab[jB * DH + d + 1];
                    v2 = k0 * c0 - k1 * s0;
                    v3 = k1 * c1 + k0 * s1;
                }
            }
            if (EPI == 3) {
                float* vtA = C + (long long)bA * DIM * JTOT + (long long)col * JTOT + jA;
                float* vtB = C + (long long)bB * DIM * JTOT + (long long)col * JTOT + jB;
                vtA[0]    = tf32r(v0);
                vtA[JTOT] = tf32r(v1);
                vtB[0]    = tf32r(v2);
                vtB[JTOT] = tf32r(v3);
            } else {
                *(float2*)(C + (long long)row0 * ldc + col) = make_float2(v0, v1);
                *(float2*)(C + (long long)(row0 + 8) * ldc + col) = make_float2(v2, v3);
            }
        }
    }
}

// ---------------- FFN1 + GEGLU fused ----------------
__global__ void __launch_bounds__(256, 2)
gemm_ffn1(const float* __restrict__ A, const float* __restrict__ B,
          float* __restrict__ Y, const float* __restrict__ b1l)
{
    constexpr int BM = 128, BN = 64;
    constexpr int ASZ = BM * 32, BSZ = BN * 32, STF = ASZ + 2 * BSZ;
    constexpr int WTM = 32, WTN = 32, MI = 2, NI = 4;
    const int KT = 32;

    extern __shared__ float smdyn[];
    const uint32_t sb = (uint32_t)__cvta_generic_to_shared(smdyn);

    const int tid = threadIdx.x, warp = tid >> 5, lane = tid & 31;
    const int wm = warp >> 1, wn = warp & 1;
    const int g = lane >> 2, t = lane & 3;
    const int bm0 = blockIdx.y * BM, bn0 = blockIdx.x * BN;

    const int arow = tid >> 3;
    const int cc   = tid & 7;

    const float* Ag  = A + (long long)(bm0 + arow) * DIM + cc * 4;
    const float* Bga = B + (long long)(bn0 + arow) * DIM + cc * 4;
    const float* Bgg = B + (long long)(FFH + bn0 + arow) * DIM + cc * 4;

    auto load_stage = [&](int s, int kt) {
        if (kt < KT) {
            const int k0 = kt << 5;
            uint32_t ab = sb + (uint32_t)(s * STF) * 4u;
            #pragma unroll
            for (int i = 0; i < 4; i++) {
                int r = arow + i * 32;
                cpa16(ab + r * 128 + ((cc ^ (r & 7)) << 4),
                      Ag + (long long)i * 32 * DIM + k0);
            }
            uint32_t bba = sb + (uint32_t)(s * STF + ASZ) * 4u;
            uint32_t bbg = bba + (uint32_t)BSZ * 4u;
            #pragma unroll
            for (int i = 0; i < 2; i++) {
                int r = arow + i * 32;
                uint32_t sw = (uint32_t)((cc ^ (r & 7)) << 4);
                cpa16(bba + r * 128 + sw, Bga + (long long)i * 32 * DIM + k0);
                cpa16(bbg + r * 128 + sw, Bgg + (long long)i * 32 * DIM + k0);
            }
        }
        asm volatile("cp.async.commit_group;");
    };

    float acca[MI][NI][4], accg[MI][NI][4];
    #pragma unroll
    for (int mi = 0; mi < MI; mi++)
        #pragma unroll
        for (int ni = 0; ni < NI; ni++)
            #pragma unroll
            for (int q = 0; q < 4; q++) { acca[mi][ni][q] = 0.f; accg[mi][ni][q] = 0.f; }

    const int a_r  = lane & 15;
    const int a_kc = lane >> 4;
    const int b_r  = lane & 7;
    const int b_kc = (lane >> 3) & 1;

    load_stage(0, 0);
    load_stage(1, 1);

    for (int kt = 0; kt < KT; kt++) {
        asm volatile("cp.async.wait_group 1;");
        __syncthreads();
        load_stage((kt + 2) % 3, kt + 2);

        const int s = kt % 3;
        const uint32_t ab  = sb + (uint32_t)(s * STF) * 4u;
        const uint32_t bba = ab + (uint32_t)ASZ * 4u;
        const uint32_t bbg = bba + (uint32_t)BSZ * 4u;

        #pragma unroll
        for (int kk = 0; kk < 4; kk++) {
            uint32_t af[MI][4], bfa[NI][2], bfg[NI][2];
            #pragma unroll
            for (int mi = 0; mi < MI; mi++) {
                int r = wm * WTM + mi * 16 + a_r;
                int kc = kk * 2 + a_kc;
                ldsm4(af[mi], ab + r * 128 + ((kc ^ (r & 7)) << 4));
            }
            #pragma unroll
            for (int ni = 0; ni < NI; ni++) {
                int r = wn * WTN + ni * 8 + b_r;
                int kc = kk * 2 + b_kc;
                ldsm2(bfa[ni], bba + r * 128 + ((kc ^ (r & 7)) << 4));
                ldsm2(bfg[ni], bbg + r * 128 + ((kc ^ (r & 7)) << 4));
            }
            #pragma unroll
            for (int mi = 0; mi < MI; mi++)
                #pragma unroll
                for (int ni = 0; ni < NI; ni++) {
                    mma_tf32(acca[mi][ni], af[mi], bfa[ni]);
                    mma_tf32(accg[mi][ni], af[mi], bfg[ni]);
                }
        }
    }

    #pragma unroll
    for (int mi = 0; mi < MI; mi++) {
        int row0 = bm0 + wm * WTM + mi * 16 + g;
        #pragma unroll
        for (int ni = 0; ni < NI; ni++) {
            int col = bn0 + wn * WTN + ni * 8 + 2 * t;
            float ba0 = b1l[col], ba1 = b1l[col + 1];
            float bg0 = b1l[FFH + col], bg1 = b1l[FFH + col + 1];
            #pragma unroll
            for (int half = 0; half < 2; half++) {
                float a0 = acca[mi][ni][half * 2 + 0] + ba0;
                float a1 = acca[mi][ni][half * 2 + 1] + ba1;
                float g0 = accg[mi][ni][half * 2 + 0] + bg0;
                float g1 = accg[mi][ni][half * 2 + 1] + bg1;
                float y0 = a0 * (0.5f * g0 * (1.0f + erff(g0 * 0.70710678118654752f)));
                float y1 = a1 * (0.5f * g1 * (1.0f + erff(g1 * 0.70710678118654752f)));
                *(float2*)(Y + (long long)(row0 + half * 8) * FFH + col) = make_float2(y0, y1);
            }
        }
    }
}

// ---------------- flash attention: Q in registers, 96KB smem, 2 CTA/SM -------
__global__ void __launch_bounds__(256, 2)
flash_attn(const float* __restrict__ Q, const float* __restrict__ K,
           const float* __restrict__ VT, float* __restrict__ O)
{
    extern __shared__ float sm[];
    const uint32_t sb = (uint32_t)__cvta_generic_to_shared(sm);
    const uint32_t pq = sb;                    // 8192 floats: Q staging, then P
    const uint32_t kb = sb + 8192u * 4u;       // 2 stages x 4096
    const uint32_t vb = sb + 16384u * 4u;      // 2 stages x 4096

    const int tid = threadIdx.x, warp = tid >> 5, lane = tid & 31;
    const int g = lane >> 2, t = lane & 3;
    const int m0 = blockIdx.x * 128;
    const int z = blockIdx.y;
    const int b = z >> 4, h = z & 15;

    const float* Qg = Q + ((long long)(b * NQ + m0)) * DIM + h * DH;
    const float* Kg = K + (long long)b * JTOT * DIM + h * DH;
    const float* Vg = VT + (long long)b * DIM * JTOT + (long long)h * DH * JTOT;
    float* Og = O + ((long long)(b * NQ + m0)) * DIM + h * DH;

    auto load_kv_body = [&](int s, int jt) {
        #pragma unroll
        for (int i = 0; i < 4; i++) {
            int idx = tid + i * 256;
            int cc = idx & 7, r = (idx >> 3) & 63, hf = idx >> 9;
            uint32_t off = (uint32_t)(s * 4096 + (hf * 64 + r) * 32) * 4u + ((cc ^ (r & 7)) << 4);
            cpa16(kb + off, Kg + (long long)(jt * 64 + r) * DIM + hf * 32 + cc * 4);
            cpa16(vb + off, Vg + (long long)r * JTOT + jt * 64 + hf * 32 + cc * 4);
        }
    };

    // group 0: Q (into P buffer) + kv0
    #pragma unroll
    for (int i = 0; i < 8; i++) {
        int idx = tid + i * 256;
        int cc = idx & 7, r = (idx >> 3) & 127, hf = idx >> 10;
        cpa16(pq + (uint32_t)(hf * 128 + r) * 128u + ((cc ^ (r & 7)) << 4),
              Qg + (long long)r * DIM + hf * 32 + cc * 4);
    }
    load_kv_body(0, 0);
    asm volatile("cp.async.commit_group;");
    // group 1: kv1
    load_kv_body(1, 1);
    asm volatile("cp.async.commit_group;");

    float acco[8][4];
    #pragma unroll
    for (int ni = 0; ni < 8; ni++)
        #pragma unroll
        for (int q = 0; q < 4; q++) acco[ni][q] = 0.f;
    float mr0 = -INFINITY, mr1 = -INFINITY, l0 = 0.f, l1 = 0.f;

    const int fr = lane & 15;
    const int fc = lane >> 4;

    // wait for Q + kv0, then extract Q fragments once (own rows only)
    asm volatile("cp.async.wait_group 1;");
    __syncthreads();

    uint32_t qf[8][4];
    #pragma unroll
    for (int kk = 0; kk < 8; kk++) {
        const int hf = kk >> 2;
        const int kc = (kk & 3) * 2 + fc;
        const int r = warp * 16 + fr;
        ldsm4(qf[kk], pq + (uint32_t)(hf * 128 + r) * 128u + ((kc ^ (r & 7)) << 4));
    }

    for (int jt = 0; jt < NJT; jt++) {
        const int s = jt & 1;
        if (jt > 0) {
            asm volatile("cp.async.wait_group 1;");
            __syncthreads();
        }

        // ---- S = Q @ K^T (Q fragments from registers) ----
        float accs[8][4];
        #pragma unroll
        for (int ni = 0; ni < 8; ni++)
            #pragma unroll
            for (int q = 0; q < 4; q++) accs[ni][q] = 0.f;

        #pragma unroll
        for (int kk = 0; kk < 8; kk++) {
            const int hf = kk >> 2;
            const int kc = (kk & 3) * 2 + fc;
            #pragma unroll
            for (int p = 0; p < 4; p++) {
                int r = p * 16 + fr;
                uint32_t bf[4];
                ldsm4(bf, kb + (uint32_t)(s * 4096 + (hf * 64 + r) * 32) * 4u + ((kc ^ (r & 7)) << 4));
                mma_tf32b(accs[2 * p],     qf[kk], bf[0], bf[2]);
                mma_tf32b(accs[2 * p + 1], qf[kk], bf[1], bf[3]);
            }
        }

        // ---- online softmax (exp results written back into accs) ----
        float vm0 = -INFINITY, vm1 = -INFINITY;
        #pragma unroll
        for (int ni = 0; ni < 8; ni++) {
            vm0 = fmaxf(vm0, fmaxf(accs[ni][0], accs[ni][1]));
            vm1 = fmaxf(vm1, fmaxf(accs[ni][2], accs[ni][3]));
        }
        vm0 = fmaxf(vm0, __shfl_xor_sync(0xffffffffu, vm0, 1));
        vm0 = fmaxf(vm0, __shfl_xor_sync(0xffffffffu, vm0, 2));
        vm1 = fmaxf(vm1, __shfl_xor_sync(0xffffffffu, vm1, 1));
        vm1 = fmaxf(vm1, __shfl_xor_sync(0xffffffffu, vm1, 2));
        float mn0 = fmaxf(mr0, vm0), mn1 = fmaxf(mr1, vm1);
        float sc0 = __expf(mr0 - mn0), sc1 = __expf(mr1 - mn1);

        float ps0 = 0.f, ps1 = 0.f;
        #pragma unroll
        for (int ni = 0; ni < 8; ni++) {
            accs[ni][0] = tf32r(__expf(accs[ni][0] - mn0));
            accs[ni][1] = tf32r(__expf(accs[ni][1] - mn0));
            accs[ni][2] = tf32r(__expf(accs[ni][2] - mn1));
            accs[ni][3] = tf32r(__expf(accs[ni][3] - mn1));
            ps0 += accs[ni][0] + accs[ni][1];
            ps1 += accs[ni][2] + accs[ni][3];
        }
        ps0 += __shfl_xor_sync(0xffffffffu, ps0, 1);
        ps0 += __shfl_xor_sync(0xffffffffu, ps0, 2);
        ps1 += __shfl_xor_sync(0xffffffffu, ps1, 1);
        ps1 += __shfl_xor_sync(0xffffffffu, ps1, 2);
        l0 = l0 * sc0 + ps0;
        l1 = l1 * sc1 + ps1;
        mr0 = mn0; mr1 = mn1;
        #pragma unroll
        for (int ni = 0; ni < 8; ni++) {
            acco[ni][0] *= sc0; acco[ni][1] *= sc0;
            acco[ni][2] *= sc1; acco[ni][3] *= sc1;
        }

        // ---- store P (own rows only; Q already consumed into registers) ----
        const int r0 = warp * 16 + g, r1 = r0 + 8;
        #pragma unroll
        for (int ni = 0; ni < 8; ni++) {
            int hf = ni >> 2;
            int cc = (ni & 3) * 2 + (t >> 1);
            uint32_t ofs = (uint32_t)((t & 1) * 8);
            uint32_t a0 = pq + (uint32_t)(hf * 128 + r0) * 128u + ((cc ^ (r0 & 7)) << 4) + ofs;
            uint32_t a1 = pq + (uint32_t)(hf * 128 + r1) * 128u + ((cc ^ (r1 & 7)) << 4) + ofs;
            asm volatile("st.shared.v2.f32 [%0], {%1,%2};" :: "r"(a0), "f"(accs[ni][0]), "f"(accs[ni][1]));
            asm volatile("st.shared.v2.f32 [%0], {%1,%2};" :: "r"(a1), "f"(accs[ni][2]), "f"(accs[ni][3]));
        }
        __syncwarp();

        // ---- O += P @ V ----
        #pragma unroll
        for (int kk = 0; kk < 8; kk++) {
            const int hf = kk >> 2;
            const int kc = (kk & 3) * 2 + fc;
            uint32_t a[4];
            {
                int r = warp * 16 + fr;
                ldsm4(a, pq + (uint32_t)(hf * 128 + r) * 128u + ((kc ^ (r & 7)) << 4));
            }
            #pragma unroll
            for (int p = 0; p < 4; p++) {
                int r = p * 16 + fr;
                uint32_t bf[4];
                ldsm4(bf, vb + (uint32_t)(s * 4096 + (hf * 64 + r) * 32) * 4u + ((kc ^ (r & 7)) << 4));
                mma_tf32b(acco[2 * p],     a, bf[0], bf[2]);
                mma_tf32b(acco[2 * p + 1], a, bf[1], bf[3]);
            }
        }
        __syncthreads();

        if (jt + 2 < NJT) load_kv_body(s, jt + 2);
        asm volatile("cp.async.commit_group;");
    }

    float inv0 = 1.f / l0, inv1 = 1.f / l1;
    const int r0 = warp * 16 + g, r1 = r0 + 8;
    #pragma unroll
    for (int ni = 0; ni < 8; ni++) {
        int col = ni * 8 + 2 * t;
        *(float2*)(Og + (long long)r0 * DIM + col) =
            make_float2(acco[ni][0] * inv0, acco[ni][1] * inv0);
        *(float2*)(Og + (long long)r1 * DIM + col) =
            make_float2(acco[ni][2] * inv1, acco[ni][3] * inv1);
    }
}

// ---------------- batched weight transpose (single launch) ----------------
__global__ void __launch_bounds__(256)
wtrans_all(const float* __restrict__ Wq, const float* __restrict__ Wk,
           const float* __restrict__ Wv, const float* __restrict__ Wo,
           const float* __restrict__ W1, const float* __restrict__ W2,
           float* __restrict__ WqT, float* __restrict__ WkT,
           float* __restrict__ WvT, float* __restrict__ WoT,
           float* __restrict__ W1T, float* __restrict__ W2T)
{
    __shared__ float tbuf[32][33];
    const float* ins[6] = {Wq, Wk, Wv, Wo, W1, W2};
    float* outs[6] = {WqT, WkT, WvT, WoT, W1T, W2T};
    const int Rs[6] = {DIM, DIM, DIM, DIM, DIM, FFH};
    const int Cs[6] = {DIM, DIM, DIM, DIM, 2 * FFH, DIM};

    int tile = blockIdx.x, job = 0;
    #pragma unroll
    for (int j2 = 0; j2 < 6; j2++) {
        int nt = DEPTH * (Rs[j2] / 32) * (Cs[j2] / 32);
        if (tile >= nt) { tile -= nt; job++; }
        else break;
    }
    const int R = Rs[job], C = Cs[job];
    const int tpz = (R / 32) * (C / 32);
    const int zdx = tile / tpz;
    const int rem = tile - zdx * tpz;
    const int ty = rem / (C / 32), tx = rem - ty * (C / 32);
    const float* in = ins[job] + (long long)zdx * R * C;
    float* out = outs[job] + (long long)zdx * R * C;

    int c0 = tx * 32, r0 = ty * 32;
    int x = threadIdx.x & 31, y = threadIdx.x >> 5;
    #pragma unroll
    for (int i = 0; i < 32; i += 8)
        tbuf[y + i][x] = in[(long long)(r0 + y + i) * C + c0 + x];
    __syncthreads();
    #pragma unroll
    for (int i = 0; i < 32; i += 8)
        out[(long long)(c0 + y + i) * R + r0 + x] = tf32r(tbuf[x][y + i]);
}

// ---------------- cos/sin tables ----------------
__global__ void prep_trig(const float* __restrict__ srcf, const float* __restrict__ tgtf,
                          float* __restrict__ cS, float* __restrict__ sS,
                          float* __restrict__ cT, float* __restrict__ sT)
{
    int idx = blockIdx.x * blockDim.x + threadIdx.x;
    if (idx < NQ * DH) {
        float f = srcf[idx];
        cS[idx] = cosf(f); sS[idx] = sinf(f);
    } else if (idx < NQ * DH + MS * DH) {
        int i = idx - NQ * DH;
        float f = tgtf[i];
        cT[i] = cosf(f); sT[i] = sinf(f);
    }
}

// ---------------- launcher ----------------
extern "C" void kernel_launch(void* const* d_in, const int* in_sizes, int n_in,
                              void* d_out, int out_size)
{
    const float* x    = (const float*)d_in[0];
    const float* cond = (const float*)d_in[1];
    const float* Wq   = (const float*)d_in[2];
    const float* Wk   = (const float*)d_in[3];
    const float* Wv   = (const float*)d_in[4];
    const float* Wo   = (const float*)d_in[5];
    const float* bo   = (const float*)d_in[6];
    const float* rpe  = (const float*)d_in[7];
    const float* W1   = (const float*)d_in[8];
    const float* b1   = (const float*)d_in[9];
    const float* W2   = (const float*)d_in[10];
    const float* b2   = (const float*)d_in[11];
    const float* srcf = (const float*)d_in[12];
    const float* tgtf = (const float*)d_in[13];
    const int*   reli = (const int*)d_in[14];
    float* xo = (float*)d_out;

    float *Q, *K, *VT, *O, *Y;
    float *WqT, *WkT, *WvT, *WoT, *W1T, *W2T;
    float *cS, *sS, *cT, *sT;
    cudaGetSymbolAddress((void**)&Q, g_Q);
    cudaGetSymbolAddress((void**)&K, g_K);
    cudaGetSymbolAddress((void**)&VT, g_VT);
    cudaGetSymbolAddress((void**)&O, g_O);
    cudaGetSymbolAddress((void**)&Y, g_Y);
    cudaGetSymbolAddress((void**)&WqT, g_WqT);
    cudaGetSymbolAddress((void**)&WkT, g_WkT);
    cudaGetSymbolAddress((void**)&WvT, g_WvT);
    cudaGetSymbolAddress((void**)&WoT, g_WoT);
    cudaGetSymbolAddress((void**)&W1T, g_W1T);
    cudaGetSymbolAddress((void**)&W2T, g_W2T);
    cudaGetSymbolAddress((void**)&cS, g_cosS);
    cudaGetSymbolAddress((void**)&sS, g_sinS);
    cudaGetSymbolAddress((void**)&cT, g_cosT);
    cudaGetSymbolAddress((void**)&sT, g_sinT);

    const int SM128 = (128 * 32 + 128 * 32) * 3 * 4;     // 96 KB
    const int SMF1  = (128 * 32 + 2 * 64 * 32) * 3 * 4;  // 96 KB
    const int SMFL  = 24576 * 4;                         // 96 KB
    cudaFuncSetAttribute(gemm_tc<0>, cudaFuncAttributeMaxDynamicSharedMemorySize, SM128);
    cudaFuncSetAttribute(gemm_tc<1>, cudaFuncAttributeMaxDynamicSharedMemorySize, SM128);
    cudaFuncSetAttribute(gemm_tc<2>, cudaFuncAttributeMaxDynamicSharedMemorySize, SM128);
    cudaFuncSetAttribute(gemm_tc<3>, cudaFuncAttributeMaxDynamicSharedMemorySize, SM128);
    cudaFuncSetAttribute(gemm_ffn1, cudaFuncAttributeMaxDynamicSharedMemorySize, SMF1);
    cudaFuncSetAttribute(flash_attn, cudaFuncAttributeMaxDynamicSharedMemorySize, SMFL);

    cudaMemcpyAsync(xo, x, (size_t)MROWS * DIM * sizeof(float),
                    cudaMemcpyDeviceToDevice, 0);

    wtrans_all<<<32768, 256>>>(Wq, Wk, Wv, Wo, W1, W2, WqT, WkT, WvT, WoT, W1T, W2T);
    prep_trig<<<((NQ + MS) * DH + 255) / 256, 256>>>(srcf, tgtf, cS, sS, cT, sT);

    for (int l = 0; l < DEPTH; l++) {
        const float* wqt = WqT + (long long)l * DIM * DIM;
        const float* wkt = WkT + (long long)l * DIM * DIM;
        const float* wvt = WvT + (long long)l * DIM * DIM;
        const float* wot = WoT + (long long)l * DIM * DIM;
        const float* bol = bo + l * DIM;
        const float* rpel = rpe + (long long)l * 405 * HEADS;
        const float* w1t = W1T + (long long)l * DIM * 2 * FFH;
        const float* b1l = b1 + (long long)l * (2 * FFH);
        const float* w2t = W2T + (long long)l * DIM * FFH;
        const float* b2l = b2 + l * DIM;

        // Q = rope(x @ Wq) * SCALE
        gemm_tc<1><<<dim3(DIM / 128, MROWS / 128), 256, SM128>>>(
            xo, wqt, Q, nullptr, nullptr,
            DIM, DIM, DIM, DIM, 1.0f, cS, sS, nullptr, nullptr);
        // VT = (cond @ Wv)^T per batch (fused transpose epilogue)
        gemm_tc<3><<<dim3(DIM / 128, CROWS / 128), 256, SM128>>>(
            cond, wvt, VT, nullptr, nullptr,
            DIM, DIM, DIM, DIM, 1.0f, nullptr, nullptr, nullptr, nullptr);
        // K = rope_bias(cond @ Wk)
        gemm_tc<2><<<dim3(DIM / 128, CROWS / 128), 256, SM128>>>(
            cond, wkt, K, nullptr, nullptr,
            DIM, DIM, DIM, DIM, 1.0f, cT, sT, rpel, reli);

        // fused attention -> O
        flash_attn<<<dim3(NQ / 128, BATCH * HEADS), 256, SMFL>>>(Q, K, VT, O);

        // x = x + O @ Wo + bo
        gemm_tc<0><<<dim3(DIM / 128, MROWS / 128), 256, SM128>>>(
            O, wot, xo, xo, bol,
            DIM, DIM, DIM, DIM, 1.0f, nullptr, nullptr, nullptr, nullptr);

        // Y = GEGLU(x @ W1 + b1)
        gemm_ffn1<<<dim3(FFH / 64, MROWS / 128), 256, SMF1>>>(xo, w1t, Y, b1l);

        // x = x + Y @ W2 + b2
        gemm_tc<0><<<dim3(DIM / 128, MROWS / 128), 256, SM128>>>(
            Y, w2t, xo, xo, b2l,
            FFH, FFH, FFH, DIM, 1.0f, nullptr, nullptr, nullptr, nullptr);
    }
}

// round 11
// speedup vs baseline: 1.1439x; 1.0626x over previous
#include <cuda_runtime.h>
#include <math.h>
#include <stdint.h>

// ---------------- problem constants ----------------
#define DEPTH 2
#define DIM   1024
#define HEADS 16
#define DH    64
#define BATCH 8
#define NQ    256
#define JTOT  1088
#define MS    1024
#define MROWS (BATCH*NQ)    // 2048
#define CROWS (BATCH*JTOT)  // 8704
#define FFH   4096
#define SCALE 0.125f
#define NJT   17            // JTOT / 64

// ---------------- scratch ----------------
__device__ float g_Q[MROWS * DIM];
__device__ float g_K[CROWS * DIM];
__device__ float g_VT[(long)BATCH * DIM * JTOT];
__device__ float g_O[MROWS * DIM];
__device__ float g_Y[(long)MROWS * FFH];
__device__ float g_WqT[(long)DEPTH * DIM * DIM];
__device__ float g_WkT[(long)DEPTH * DIM * DIM];
__device__ float g_WvT[(long)DEPTH * DIM * DIM];
__device__ float g_WoT[(long)DEPTH * DIM * DIM];
__device__ float g_W1T[(long)DEPTH * 2 * FFH * DIM];   // interleaved: row 2c=a_c, 2c+1=g_c
__device__ float g_W2T[(long)DEPTH * DIM * FFH];
__device__ float g_cosS[NQ * DH];
__device__ float g_sinS[NQ * DH];
__device__ float g_cosT[MS * DH];
__device__ float g_sinT[MS * DH];

// ---------------- ptx helpers ----------------
__device__ __forceinline__ float tf32r(float f) {
    uint32_t u;
    asm("cvt.rna.tf32.f32 %0, %1;" : "=r"(u) : "f"(f));
    return __uint_as_float(u);
}
__device__ __forceinline__ void ldsm4(uint32_t* r, uint32_t a) {
    asm volatile("ldmatrix.sync.aligned.m8n8.x4.shared.b16 {%0,%1,%2,%3}, [%4];"
                 : "=r"(r[0]), "=r"(r[1]), "=r"(r[2]), "=r"(r[3]) : "r"(a));
}
__device__ __forceinline__ void ldsm2(uint32_t* r, uint32_t a) {
    asm volatile("ldmatrix.sync.aligned.m8n8.x2.shared.b16 {%0,%1}, [%2];"
                 : "=r"(r[0]), "=r"(r[1]) : "r"(a));
}
__device__ __forceinline__ void mma_tf32(float* c, const uint32_t* a, const uint32_t* b) {
    asm volatile(
        "mma.sync.aligned.m16n8k8.row.col.f32.tf32.tf32.f32 "
        "{%0,%1,%2,%3}, {%4,%5,%6,%7}, {%8,%9}, {%0,%1,%2,%3};"
        : "+f"(c[0]), "+f"(c[1]), "+f"(c[2]), "+f"(c[3])
        : "r"(a[0]), "r"(a[1]), "r"(a[2]), "r"(a[3]), "r"(b[0]), "r"(b[1]));
}
__device__ __forceinline__ void mma_tf32b(float* c, const uint32_t* a, uint32_t b0, uint32_t b1) {
    asm volatile(
        "mma.sync.aligned.m16n8k8.row.col.f32.tf32.tf32.f32 "
        "{%0,%1,%2,%3}, {%4,%5,%6,%7}, {%8,%9}, {%0,%1,%2,%3};"
        : "+f"(c[0]), "+f"(c[1]), "+f"(c[2]), "+f"(c[3])
        : "r"(a[0]), "r"(a[1]), "r"(a[2]), "r"(a[3]), "r"(b0), "r"(b1));
}
__device__ __forceinline__ void cpa16(uint32_t d, const float* s) {
    asm volatile("cp.async.cg.shared.global [%0], [%1], 16;" :: "r"(d), "l"(s));
}

// ---- tf32 GEMM; EPI: 0=plain, 1=rope_q, 2=rpe+rope_k, 3=V^T, 4=GEGLU pairs --
template <int EPI>
__global__ void __launch_bounds__(256, 2)
gemm_tc(const float* __restrict__ A, const float* __restrict__ B,
        float* __restrict__ C, const float* __restrict__ Cadd,
        const float* __restrict__ bias,
        int K, int lda, int ldb, int ldc, float alpha,
        const float* __restrict__ ctab, const float* __restrict__ stab,
        const float* __restrict__ rpe_l, const int* __restrict__ rel_idx)
{
    constexpr int BM = 128, BN = 128;
    constexpr int ASZ = BM * 32, STF = ASZ + BN * 32;
    constexpr int WTM = 64, WTN = 32;   // WM=2, WN=4
    constexpr int MI = 4, NI = 4;

    extern __shared__ float smdyn[];
    const uint32_t sb = (uint32_t)__cvta_generic_to_shared(smdyn);

    const int tid = threadIdx.x, warp = tid >> 5, lane = tid & 31;
    const int wm = warp >> 2, wn = warp & 3;
    const int g = lane >> 2, t = lane & 3;
    const int bm0 = blockIdx.y * BM, bn0 = blockIdx.x * BN;

    const int arow = tid >> 3;
    const int cc   = tid & 7;

    const float* Ag = A + (long long)(bm0 + arow) * lda + cc * 4;
    const float* Bg = B + (long long)(bn0 + arow) * ldb + cc * 4;

    const int KT = K >> 5;

    auto load_stage = [&](int s, int kt) {
        if (kt < KT) {
            const int k0 = kt << 5;
            uint32_t ab = sb + (uint32_t)(s * STF) * 4u;
            uint32_t bb = ab + (uint32_t)ASZ * 4u;
            #pragma unroll
            for (int i = 0; i < 4; i++) {
                int r = arow + i * 32;
                uint32_t sw = (uint32_t)((cc ^ (r & 7)) << 4);
                cpa16(ab + r * 128 + sw, Ag + (long long)i * 32 * lda + k0);
                cpa16(bb + r * 128 + sw, Bg + (long long)i * 32 * ldb + k0);
            }
        }
        asm volatile("cp.async.commit_group;");
    };

    float acc[MI][NI][4];
    #pragma unroll
    for (int mi = 0; mi < MI; mi++)
        #pragma unroll
        for (int ni = 0; ni < NI; ni++)
            #pragma unroll
            for (int q = 0; q < 4; q++) acc[mi][ni][q] = 0.f;

    const int a_r  = lane & 15;
    const int a_kc = lane >> 4;
    const int b_r  = lane & 7;
    const int b_kc = (lane >> 3) & 1;

    load_stage(0, 0);
    load_stage(1, 1);

    for (int kt = 0; kt < KT; kt++) {
        asm volatile("cp.async.wait_group 1;");
        __syncthreads();
        load_stage((kt + 2) % 3, kt + 2);

        const int s = kt % 3;
        const uint32_t ab = sb + (uint32_t)(s * STF) * 4u;
        const uint32_t bb = ab + (uint32_t)ASZ * 4u;

        #pragma unroll
        for (int kk = 0; kk < 4; kk++) {
            uint32_t af[MI][4], bf[NI][2];
            #pragma unroll
            for (int mi = 0; mi < MI; mi++) {
                int r = wm * WTM + mi * 16 + a_r;
                int kc = kk * 2 + a_kc;
                ldsm4(af[mi], ab + r * 128 + ((kc ^ (r & 7)) << 4));
            }
            #pragma unroll
            for (int ni = 0; ni < NI; ni++) {
                int r = wn * WTN + ni * 8 + b_r;
                int kc = kk * 2 + b_kc;
                ldsm2(bf[ni], bb + r * 128 + ((kc ^ (r & 7)) << 4));
            }
            #pragma unroll
            for (int mi = 0; mi < MI; mi++)
                #pragma unroll
                for (int ni = 0; ni < NI; ni++)
                    mma_tf32(acc[mi][ni], af[mi], bf[ni]);
        }
    }

    #pragma unroll
    for (int mi = 0; mi < MI; mi++) {
        int row0 = bm0 + wm * WTM + mi * 16 + g;
        int jA = 0, jB = 0, bA = 0, bB = 0;
        if (EPI == 2 || EPI == 3) {
            bA = row0 / JTOT;       jA = row0 - bA * JTOT;
            bB = (row0 + 8) / JTOT; jB = (row0 + 8) - bB * JTOT;
        }
        #pragma unroll
        for (int ni = 0; ni < NI; ni++) {
            int col = bn0 + wn * WTN + ni * 8 + 2 * t;
            float v0 = alpha * acc[mi][ni][0];
            float v1 = alpha * acc[mi][ni][1];
            float v2 = alpha * acc[mi][ni][2];
            float v3 = alpha * acc[mi][ni][3];
            if (bias && EPI != 4) {
                float b0 = bias[col], b1 = bias[col + 1];
                v0 += b0; v1 += b1; v2 += b0; v3 += b1;
            }
            if (Cadd) {
                const float2 c0 = *(const float2*)(Cadd + (long long)row0 * ldc + col);
                const float2 c1 = *(const float2*)(Cadd + (long long)(row0 + 8) * ldc + col);
                v0 += c0.x; v1 += c0.y; v2 += c1.x; v3 += c1.y;
            }
            if (EPI == 1) {
                int d = col & (DH - 1);
                int nA = row0 & (NQ - 1), nB = (row0 + 8) & (NQ - 1);
                float cA0 = ctab[nA * DH + d],     sA0 = stab[nA * DH + d];
                float cA1 = ctab[nA * DH + d + 1], sA1 = stab[nA * DH + d + 1];
                float cB0 = ctab[nB * DH + d],     sB0 = stab[nB * DH + d];
                float cB1 = ctab[nB * DH + d + 1], sB1 = stab[nB * DH + d + 1];
                float o0 = (v0 * cA0 - v1 * sA0) * SCALE;
                float o1 = (v1 * cA1 + v0 * sA1) * SCALE;
                float o2 = (v2 * cB0 - v3 * sB0) * SCALE;
                float o3 = (v3 * cB1 + v2 * sB1) * SCALE;
                v0 = o0; v1 = o1; v2 = o2; v3 = o3;
            }
            if (EPI == 2) {
                int d = col & (DH - 1);
                int h = col >> 6;
                if (jA < MS) {
                    float bb2 = rpe_l[rel_idx[jA >> 8] * HEADS + h];
                    float k0 = v0 + bb2, k1 = v1 + bb2;
                    float c0 = ctab[jA * DH + d],     s0 = stab[jA * DH + d];
                    float c1 = ctab[jA * DH + d + 1], s1 = stab[jA * DH + d + 1];
                    v0 = k0 * c0 - k1 * s0;
                    v1 = k1 * c1 + k0 * s1;
                }
                if (jB < MS) {
                    float bb2 = rpe_l[rel_idx[jB >> 8] * HEADS + h];
                    float k0 = v2 + bb2, k1 = v3 + bb2;
                    float c0 = ctab[jB * DH + d],     s0 = stab[jB * DH + d];
                    float c1 = ctab[jB * DH + d + 1], s1 = stab[jB * DH + d + 1];
                    v2 = k0 * c0 - k1 * s0;
                    v3 = k1 * c1 + k0 * s1;
                }
            }
            if (EPI == 3) {
                float* vtA = C + (long long)bA * DIM * JTOT + (long long)col * JTOT + jA;
                float* vtB = C + (long long)bB * DIM * JTOT + (long long)col * JTOT + jB;
                vtA[0]    = tf32r(v0);
                vtA[JTOT] = tf32r(v1);
                vtB[0]    = tf32r(v2);
                vtB[JTOT] = tf32r(v3);
            } else if (EPI == 4) {
                // interleaved pairs: even col = a, odd col = g for output col oc
                int oc = col >> 1;
                float ba = bias[oc], bg = bias[FFH + oc];
                float a0 = v0 + ba, g0 = v1 + bg;
                float a1 = v2 + ba, g1 = v3 + bg;
                float y0 = a0 * (0.5f * g0 * (1.0f + erff(g0 * 0.70710678118654752f)));
                float y1 = a1 * (0.5f * g1 * (1.0f + erff(g1 * 0.70710678118654752f)));
                C[(long long)row0 * ldc + oc]       = y0;
                C[(long long)(row0 + 8) * ldc + oc] = y1;
            } else {
                *(float2*)(C + (long long)row0 * ldc + col) = make_float2(v0, v1);
                *(float2*)(C + (long long)(row0 + 8) * ldc + col) = make_float2(v2, v3);
            }
        }
    }
}

// ---------------- flash attention: Q in registers, 96KB smem ----------------
__global__ void __launch_bounds__(256, 2)
flash_attn(const float* __restrict__ Q, const float* __restrict__ K,
           const float* __restrict__ VT, float* __restrict__ O)
{
    extern __shared__ float sm[];
    const uint32_t sb = (uint32_t)__cvta_generic_to_shared(sm);
    const uint32_t pq = sb;
    const uint32_t kb = sb + 8192u * 4u;
    const uint32_t vb = sb + 16384u * 4u;

    const int tid = threadIdx.x, warp = tid >> 5, lane = tid & 31;
    const int g = lane >> 2, t = lane & 3;
    const int m0 = blockIdx.x * 128;
    const int z = blockIdx.y;
    const int b = z >> 4, h = z & 15;

    const float* Qg = Q + ((long long)(b * NQ + m0)) * DIM + h * DH;
    const float* Kg = K + (long long)b * JTOT * DIM + h * DH;
    const float* Vg = VT + (long long)b * DIM * JTOT + (long long)h * DH * JTOT;
    float* Og = O + ((long long)(b * NQ + m0)) * DIM + h * DH;

    auto load_kv_body = [&](int s, int jt) {
        #pragma unroll
        for (int i = 0; i < 4; i++) {
            int idx = tid + i * 256;
            int cc = idx & 7, r = (idx >> 3) & 63, hf = idx >> 9;
            uint32_t off = (uint32_t)(s * 4096 + (hf * 64 + r) * 32) * 4u + ((cc ^ (r & 7)) << 4);
            cpa16(kb + off, Kg + (long long)(jt * 64 + r) * DIM + hf * 32 + cc * 4);
            cpa16(vb + off, Vg + (long long)r * JTOT + jt * 64 + hf * 32 + cc * 4);
        }
    };

    #pragma unroll
    for (int i = 0; i < 8; i++) {
        int idx = tid + i * 256;
        int cc = idx & 7, r = (idx >> 3) & 127, hf = idx >> 10;
        cpa16(pq + (uint32_t)(hf * 128 + r) * 128u + ((cc ^ (r & 7)) << 4),
              Qg + (long long)r * DIM + hf * 32 + cc * 4);
    }
    load_kv_body(0, 0);
    asm volatile("cp.async.commit_group;");
    load_kv_body(1, 1);
    asm volatile("cp.async.commit_group;");

    float acco[8][4];
    #pragma unroll
    for (int ni = 0; ni < 8; ni++)
        #pragma unroll
        for (int q = 0; q < 4; q++) acco[ni][q] = 0.f;
    float mr0 = -INFINITY, mr1 = -INFINITY, l0 = 0.f, l1 = 0.f;

    const int fr = lane & 15;
    const int fc = lane >> 4;

    asm volatile("cp.async.wait_group 1;");
    __syncthreads();

    uint32_t qf[8][4];
    #pragma unroll
    for (int kk = 0; kk < 8; kk++) {
        const int hf = kk >> 2;
        const int kc = (kk & 3) * 2 + fc;
        const int r = warp * 16 + fr;
        ldsm4(qf[kk], pq + (uint32_t)(hf * 128 + r) * 128u + ((kc ^ (r & 7)) << 4));
    }

    for (int jt = 0; jt < NJT; jt++) {
        const int s = jt & 1;
        if (jt > 0) {
            asm volatile("cp.async.wait_group 1;");
            __syncthreads();
        }

        float accs[8][4];
        #pragma unroll
        for (int ni = 0; ni < 8; ni++)
            #pragma unroll
            for (int q = 0; q < 4; q++) accs[ni][q] = 0.f;

        #pragma unroll
        for (int kk = 0; kk < 8; kk++) {
            const int hf = kk >> 2;
            const int kc = (kk & 3) * 2 + fc;
            #pragma unroll
            for (int p = 0; p < 4; p++) {
                int r = p * 16 + fr;
                uint32_t bf[4];
                ldsm4(bf, kb + (uint32_t)(s * 4096 + (hf * 64 + r) * 32) * 4u + ((kc ^ (r & 7)) << 4));
                mma_tf32b(accs[2 * p],     qf[kk], bf[0], bf[2]);
                mma_tf32b(accs[2 * p + 1], qf[kk], bf[1], bf[3]);
            }
        }

        float vm0 = -INFINITY, vm1 = -INFINITY;
        #pragma unroll
        for (int ni = 0; ni < 8; ni++) {
            vm0 = fmaxf(vm0, fmaxf(accs[ni][0], accs[ni][1]));
            vm1 = fmaxf(vm1, fmaxf(accs[ni][2], accs[ni][3]));
        }
        vm0 = fmaxf(vm0, __shfl_xor_sync(0xffffffffu, vm0, 1));
        vm0 = fmaxf(vm0, __shfl_xor_sync(0xffffffffu, vm0, 2));
        vm1 = fmaxf(vm1, __shfl_xor_sync(0xffffffffu, vm1, 1));
        vm1 = fmaxf(vm1, __shfl_xor_sync(0xffffffffu, vm1, 2));
        float mn0 = fmaxf(mr0, vm0), mn1 = fmaxf(mr1, vm1);
        float sc0 = __expf(mr0 - mn0), sc1 = __expf(mr1 - mn1);

        float ps0 = 0.f, ps1 = 0.f;
        #pragma unroll
        for (int ni = 0; ni < 8; ni++) {
            accs[ni][0] = tf32r(__expf(accs[ni][0] - mn0));
            accs[ni][1] = tf32r(__expf(accs[ni][1] - mn0));
            accs[ni][2] = tf32r(__expf(accs[ni][2] - mn1));
            accs[ni][3] = tf32r(__expf(accs[ni][3] - mn1));
            ps0 += accs[ni][0] + accs[ni][1];
            ps1 += accs[ni][2] + accs[ni][3];
        }
        ps0 += __shfl_xor_sync(0xffffffffu, ps0, 1);
        ps0 += __shfl_xor_sync(0xffffffffu, ps0, 2);
        ps1 += __shfl_xor_sync(0xffffffffu, ps1, 1);
        ps1 += __shfl_xor_sync(0xffffffffu, ps1, 2);
        l0 = l0 * sc0 + ps0;
        l1 = l1 * sc1 + ps1;
        mr0 = mn0; mr1 = mn1;
        #pragma unroll
        for (int ni = 0; ni < 8; ni++) {
            acco[ni][0] *= sc0; acco[ni][1] *= sc0;
            acco[ni][2] *= sc1; acco[ni][3] *= sc1;
        }

        const int r0 = warp * 16 + g, r1 = r0 + 8;
        #pragma unroll
        for (int ni = 0; ni < 8; ni++) {
            int hf = ni >> 2;
            int cc = (ni & 3) * 2 + (t >> 1);
            uint32_t ofs = (uint32_t)((t & 1) * 8);
            uint32_t a0 = pq + (uint32_t)(hf * 128 + r0) * 128u + ((cc ^ (r0 & 7)) << 4) + ofs;
            uint32_t a1 = pq + (uint32_t)(hf * 128 + r1) * 128u + ((cc ^ (r1 & 7)) << 4) + ofs;
            asm volatile("st.shared.v2.f32 [%0], {%1,%2};" :: "r"(a0), "f"(accs[ni][0]), "f"(accs[ni][1]));
            asm volatile("st.shared.v2.f32 [%0], {%1,%2};" :: "r"(a1), "f"(accs[ni][2]), "f"(accs[ni][3]));
        }
        __syncwarp();

        #pragma unroll
        for (int kk = 0; kk < 8; kk++) {
            const int hf = kk >> 2;
            const int kc = (kk & 3) * 2 + fc;
            uint32_t a[4];
            {
                int r = warp * 16 + fr;
                ldsm4(a, pq + (uint32_t)(hf * 128 + r) * 128u + ((kc ^ (r & 7)) << 4));
            }
            #pragma unroll
            for (int p = 0; p < 4; p++) {
                int r = p * 16 + fr;
                uint32_t bf[4];
                ldsm4(bf, vb + (uint32_t)(s * 4096 + (hf * 64 + r) * 32) * 4u + ((kc ^ (r & 7)) << 4));
                mma_tf32b(acco[2 * p],     a, bf[0], bf[2]);
                mma_tf32b(acco[2 * p + 1], a, bf[1], bf[3]);
            }
        }
        __syncthreads();

        if (jt + 2 < NJT) load_kv_body(s, jt + 2);
        asm volatile("cp.async.commit_group;");
    }

    float inv0 = 1.f / l0, inv1 = 1.f / l1;
    const int r0 = warp * 16 + g, r1 = r0 + 8;
    #pragma unroll
    for (int ni = 0; ni < 8; ni++) {
        int col = ni * 8 + 2 * t;
        *(float2*)(Og + (long long)r0 * DIM + col) =
            make_float2(acco[ni][0] * inv0, acco[ni][1] * inv0);
        *(float2*)(Og + (long long)r1 * DIM + col) =
            make_float2(acco[ni][2] * inv1, acco[ni][3] * inv1);
    }
}

// ---- batched weight transpose: 64x64 tiles, float4 global I/O ----
// job 4 (W1): output rows interleaved (2c for a-half, 2c+1 for g-half)
__global__ void __launch_bounds__(256)
wtrans_all(const float* __restrict__ Wq, const float* __restrict__ Wk,
           const float* __restrict__ Wv, const float* __restrict__ Wo,
           const float* __restrict__ W1, const float* __restrict__ W2,
           float* __restrict__ WqT, float* __restrict__ WkT,
           float* __restrict__ WvT, float* __restrict__ WoT,
           float* __restrict__ W1T, float* __restrict__ W2T)
{
    __shared__ float tb[64][65];
    const float* ins[6] = {Wq, Wk, Wv, Wo, W1, W2};
    float* outs[6] = {WqT, WkT, WvT, WoT, W1T, W2T};
    const int Rs[6] = {DIM, DIM, DIM, DIM, DIM, FFH};
    const int Cs[6] = {DIM, DIM, DIM, DIM, 2 * FFH, DIM};

    int tile = blockIdx.x, job = 0;
    #pragma unroll
    for (int j2 = 0; j2 < 6; j2++) {
        int nt = DEPTH * (Rs[j2] / 64) * (Cs[j2] / 64);
        if (tile >= nt) { tile -= nt; job++; }
        else break;
    }
    const int R = Rs[job], C = Cs[job];
    const int tpz = (R / 64) * (C / 64);
    const int zdx = tile / tpz;
    const int rem = tile - zdx * tpz;
    const int ty4 = rem / (C / 64), tx4 = rem - ty4 * (C / 64);
    const float* in = ins[job] + (long long)zdx * R * C;
    float* out = outs[job] + (long long)zdx * R * C;

    const int c0 = tx4 * 64, r0 = ty4 * 64;
    const int tx = threadIdx.x & 15, ty = threadIdx.x >> 4;   // 16x16

    #pragma unroll
    for (int i = 0; i < 4; i++) {
        int r = ty + i * 16;
        float4 v = *(const float4*)(in + (long long)(r0 + r) * C + c0 + tx * 4);
        tb[r][tx * 4 + 0] = v.x;
        tb[r][tx * 4 + 1] = v.y;
        tb[r][tx * 4 + 2] = v.z;
        tb[r][tx * 4 + 3] = v.w;
    }
    __syncthreads();

    #pragma unroll
    for (int i = 0; i < 4; i++) {
        int c = c0 + ty + i * 16;                 // output row (pre-permute)
        int sc = ty + i * 16;                     // smem column
        long long orow = c;
        if (job == 4) orow = (c < FFH) ? (2LL * c) : (2LL * (c - FFH) + 1);
        float4 w;
        w.x = tf32r(tb[tx * 4 + 0][sc]);
        w.y = tf32r(tb[tx * 4 + 1][sc]);
        w.z = tf32r(tb[tx * 4 + 2][sc]);
        w.w = tf32r(tb[tx * 4 + 3][sc]);
        *(float4*)(out + orow * R + r0 + tx * 4) = w;
    }
}

// ---------------- cos/sin tables ----------------
__global__ void prep_trig(const float* __restrict__ srcf, const float* __restrict__ tgtf,
                          float* __restrict__ cS, float* __restrict__ sS,
                          float* __restrict__ cT, float* __restrict__ sT)
{
    int idx = blockIdx.x * blockDim.x + threadIdx.x;
    if (idx < NQ * DH) {
        float f = srcf[idx];
        cS[idx] = cosf(f); sS[idx] = sinf(f);
    } else if (idx < NQ * DH + MS * DH) {
        int i = idx - NQ * DH;
        float f = tgtf[i];
        cT[i] = cosf(f); sT[i] = sinf(f);
    }
}

// ---------------- launcher ----------------
extern "C" void kernel_launch(void* const* d_in, const int* in_sizes, int n_in,
                              void* d_out, int out_size)
{
    const float* x    = (const float*)d_in[0];
    const float* cond = (const float*)d_in[1];
    const float* Wq   = (const float*)d_in[2];
    const float* Wk   = (const float*)d_in[3];
    const float* Wv   = (const float*)d_in[4];
    const float* Wo   = (const float*)d_in[5];
    const float* bo   = (const float*)d_in[6];
    const float* rpe  = (const float*)d_in[7];
    const float* W1   = (const float*)d_in[8];
    const float* b1   = (const float*)d_in[9];
    const float* W2   = (const float*)d_in[10];
    const float* b2   = (const float*)d_in[11];
    const float* srcf = (const float*)d_in[12];
    const float* tgtf = (const float*)d_in[13];
    const int*   reli = (const int*)d_in[14];
    float* xo = (float*)d_out;

    float *Q, *K, *VT, *O, *Y;
    float *WqT, *WkT, *WvT, *WoT, *W1T, *W2T;
    float *cS, *sS, *cT, *sT;
    cudaGetSymbolAddress((void**)&Q, g_Q);
    cudaGetSymbolAddress((void**)&K, g_K);
    cudaGetSymbolAddress((void**)&VT, g_VT);
    cudaGetSymbolAddress((void**)&O, g_O);
    cudaGetSymbolAddress((void**)&Y, g_Y);
    cudaGetSymbolAddress((void**)&WqT, g_WqT);
    cudaGetSymbolAddress((void**)&WkT, g_WkT);
    cudaGetSymbolAddress((void**)&WvT, g_WvT);
    cudaGetSymbolAddress((void**)&WoT, g_WoT);
    cudaGetSymbolAddress((void**)&W1T, g_W1T);
    cudaGetSymbolAddress((void**)&W2T, g_W2T);
    cudaGetSymbolAddress((void**)&cS, g_cosS);
    cudaGetSymbolAddress((void**)&sS, g_sinS);
    cudaGetSymbolAddress((void**)&cT, g_cosT);
    cudaGetSymbolAddress((void**)&sT, g_sinT);

    const int SM128 = (128 * 32 + 128 * 32) * 3 * 4;     // 96 KB
    const int SMFL  = 24576 * 4;                         // 96 KB
    cudaFuncSetAttribute(gemm_tc<0>, cudaFuncAttributeMaxDynamicSharedMemorySize, SM128);
    cudaFuncSetAttribute(gemm_tc<1>, cudaFuncAttributeMaxDynamicSharedMemorySize, SM128);
    cudaFuncSetAttribute(gemm_tc<2>, cudaFuncAttributeMaxDynamicSharedMemorySize, SM128);
    cudaFuncSetAttribute(gemm_tc<3>, cudaFuncAttributeMaxDynamicSharedMemorySize, SM128);
    cudaFuncSetAttribute(gemm_tc<4>, cudaFuncAttributeMaxDynamicSharedMemorySize, SM128);
    cudaFuncSetAttribute(flash_attn, cudaFuncAttributeMaxDynamicSharedMemorySize, SMFL);

    cudaMemcpyAsync(xo, x, (size_t)MROWS * DIM * sizeof(float),
                    cudaMemcpyDeviceToDevice, 0);

    // total 64x64 tiles: 4 jobs of 2*16*16 + W1 2*16*128 + W2 2*64*16 = 2048 + 4096 + 2048 = 8192
    wtrans_all<<<8192, 256>>>(Wq, Wk, Wv, Wo, W1, W2, WqT, WkT, WvT, WoT, W1T, W2T);
    prep_trig<<<((NQ + MS) * DH + 255) / 256, 256>>>(srcf, tgtf, cS, sS, cT, sT);

    for (int l = 0; l < DEPTH; l++) {
        const float* wqt = WqT + (long long)l * DIM * DIM;
        const float* wkt = WkT + (long long)l * DIM * DIM;
        const float* wvt = WvT + (long long)l * DIM * DIM;
        const float* wot = WoT + (long long)l * DIM * DIM;
        const float* bol = bo + l * DIM;
        const float* rpel = rpe + (long long)l * 405 * HEADS;
        const float* w1t = W1T + (long long)l * DIM * 2 * FFH;
        const float* b1l = b1 + (long long)l * (2 * FFH);
        const float* w2t = W2T + (long long)l * DIM * FFH;
        const float* b2l = b2 + l * DIM;

        // Q = rope(x @ Wq) * SCALE
        gemm_tc<1><<<dim3(DIM / 128, MROWS / 128), 256, SM128>>>(
            xo, wqt, Q, nullptr, nullptr,
            DIM, DIM, DIM, DIM, 1.0f, cS, sS, nullptr, nullptr);
        // VT = (cond @ Wv)^T per batch (fused transpose epilogue)
        gemm_tc<3><<<dim3(DIM / 128, CROWS / 128), 256, SM128>>>(
            cond, wvt, VT, nullptr, nullptr,
            DIM, DIM, DIM, DIM, 1.0f, nullptr, nullptr, nullptr, nullptr);
        // K = rope_bias(cond @ Wk)
        gemm_tc<2><<<dim3(DIM / 128, CROWS / 128), 256, SM128>>>(
            cond, wkt, K, nullptr, nullptr,
            DIM, DIM, DIM, DIM, 1.0f, cT, sT, rpel, reli);

        // fused attention -> O
        flash_attn<<<dim3(NQ / 128, BATCH * HEADS), 256, SMFL>>>(Q, K, VT, O);

        // x = x + O @ Wo + bo
        gemm_tc<0><<<dim3(DIM / 128, MROWS / 128), 256, SM128>>>(
            O, wot, xo, xo, bol,
            DIM, DIM, DIM, DIM, 1.0f, nullptr, nullptr, nullptr, nullptr);

        // Y = GEGLU(x @ W1 + b1)  (interleaved W1T, pair epilogue)
        gemm_tc<4><<<dim3(2 * FFH / 128, MROWS / 128), 256, SM128>>>(
            xo, w1t, Y, nullptr, b1l,
            DIM, DIM, DIM, FFH, 1.0f, nullptr, nullptr, nullptr, nullptr);

        // x = x + Y @ W2 + b2
        gemm_tc<0><<<dim3(DIM / 128, MROWS / 128), 256, SM128>>>(
            Y, w2t, xo, xo, b2l,
            FFH, FFH, FFH, DIM, 1.0f, nullptr, nullptr, nullptr, nullptr);
    }
}

// round 12
// speedup vs baseline: 1.2026x; 1.0513x over previous
#include <cuda_runtime.h>
#include <math.h>
#include <stdint.h>

// ---------------- problem constants ----------------
#define DEPTH 2
#define DIM   1024
#define HEADS 16
#define DH    64
#define BATCH 8
#define NQ    256
#define JTOT  1088
#define MS    1024
#define MROWS (BATCH*NQ)    // 2048
#define CROWS (BATCH*JTOT)  // 8704
#define FFH   4096
#define SCALE 0.125f
#define NJT   17            // JTOT / 64

// ---------------- scratch ----------------
__device__ float g_Q[MROWS * DIM];
__device__ float g_K[(long)DEPTH * CROWS * DIM];          // double-buffered per layer
__device__ float g_VT[(long)DEPTH * BATCH * DIM * JTOT];  // double-buffered per layer
__device__ float g_O[MROWS * DIM];
__device__ float g_Y[(long)MROWS * FFH];
__device__ float g_WqT[(long)DEPTH * DIM * DIM];
__device__ float g_WkT[(long)DEPTH * DIM * DIM];
__device__ float g_WvT[(long)DEPTH * DIM * DIM];
__device__ float g_WoT[(long)DEPTH * DIM * DIM];
__device__ float g_W1T[(long)DEPTH * 2 * FFH * DIM];   // interleaved: row 2c=a_c, 2c+1=g_c
__device__ float g_W2T[(long)DEPTH * DIM * FFH];
__device__ float g_cosS[NQ * DH];
__device__ float g_sinS[NQ * DH];
__device__ float g_cosT[MS * DH];
__device__ float g_sinT[MS * DH];

// ---------------- ptx helpers ----------------
__device__ __forceinline__ float tf32r(float f) {
    uint32_t u;
    asm("cvt.rna.tf32.f32 %0, %1;" : "=r"(u) : "f"(f));
    return __uint_as_float(u);
}
__device__ __forceinline__ void ldsm4(uint32_t* r, uint32_t a) {
    asm volatile("ldmatrix.sync.aligned.m8n8.x4.shared.b16 {%0,%1,%2,%3}, [%4];"
                 : "=r"(r[0]), "=r"(r[1]), "=r"(r[2]), "=r"(r[3]) : "r"(a));
}
__device__ __forceinline__ void ldsm2(uint32_t* r, uint32_t a) {
    asm volatile("ldmatrix.sync.aligned.m8n8.x2.shared.b16 {%0,%1}, [%2];"
                 : "=r"(r[0]), "=r"(r[1]) : "r"(a));
}
__device__ __forceinline__ void mma_tf32(float* c, const uint32_t* a, const uint32_t* b) {
    asm volatile(
        "mma.sync.aligned.m16n8k8.row.col.f32.tf32.tf32.f32 "
        "{%0,%1,%2,%3}, {%4,%5,%6,%7}, {%8,%9}, {%0,%1,%2,%3};"
        : "+f"(c[0]), "+f"(c[1]), "+f"(c[2]), "+f"(c[3])
        : "r"(a[0]), "r"(a[1]), "r"(a[2]), "r"(a[3]), "r"(b[0]), "r"(b[1]));
}
__device__ __forceinline__ void mma_tf32b(float* c, const uint32_t* a, uint32_t b0, uint32_t b1) {
    asm volatile(
        "mma.sync.aligned.m16n8k8.row.col.f32.tf32.tf32.f32 "
        "{%0,%1,%2,%3}, {%4,%5,%6,%7}, {%8,%9}, {%0,%1,%2,%3};"
        : "+f"(c[0]), "+f"(c[1]), "+f"(c[2]), "+f"(c[3])
        : "r"(a[0]), "r"(a[1]), "r"(a[2]), "r"(a[3]), "r"(b0), "r"(b1));
}
__device__ __forceinline__ void cpa16(uint32_t d, const float* s) {
    asm volatile("cp.async.cg.shared.global [%0], [%1], 16;" :: "r"(d), "l"(s));
}

// ---- tf32 GEMM; EPI: 0=plain, 1=rope_q, 2=rpe+rope_k, 3=V^T, 4=GEGLU pairs --
template <int EPI>
__global__ void __launch_bounds__(256, 2)
gemm_tc(const float* __restrict__ A, const float* __restrict__ B,
        float* __restrict__ C, const float* __restrict__ Cadd,
        const float* __restrict__ bias,
        int K, int lda, int ldb, int ldc, float alpha,
        const float* __restrict__ ctab, const float* __restrict__ stab,
        const float* __restrict__ rpe_l, const int* __restrict__ rel_idx)
{
    constexpr int BM = 128, BN = 128;
    constexpr int ASZ = BM * 32, STF = ASZ + BN * 32;
    constexpr int WTM = 64, WTN = 32;   // WM=2, WN=4
    constexpr int MI = 4, NI = 4;

    extern __shared__ float smdyn[];
    const uint32_t sb = (uint32_t)__cvta_generic_to_shared(smdyn);

    const int tid = threadIdx.x, warp = tid >> 5, lane = tid & 31;
    const int wm = warp >> 2, wn = warp & 3;
    const int g = lane >> 2, t = lane & 3;
    const int bm0 = blockIdx.y * BM, bn0 = blockIdx.x * BN;

    const int arow = tid >> 3;
    const int cc   = tid & 7;

    const float* Ag = A + (long long)(bm0 + arow) * lda + cc * 4;
    const float* Bg = B + (long long)(bn0 + arow) * ldb + cc * 4;

    const int KT = K >> 5;

    auto load_stage = [&](int s, int kt) {
        if (kt < KT) {
            const int k0 = kt << 5;
            uint32_t ab = sb + (uint32_t)(s * STF) * 4u;
            uint32_t bb = ab + (uint32_t)ASZ * 4u;
            #pragma unroll
            for (int i = 0; i < 4; i++) {
                int r = arow + i * 32;
                uint32_t sw = (uint32_t)((cc ^ (r & 7)) << 4);
                cpa16(ab + r * 128 + sw, Ag + (long long)i * 32 * lda + k0);
                cpa16(bb + r * 128 + sw, Bg + (long long)i * 32 * ldb + k0);
            }
        }
        asm volatile("cp.async.commit_group;");
    };

    float acc[MI][NI][4];
    #pragma unroll
    for (int mi = 0; mi < MI; mi++)
        #pragma unroll
        for (int ni = 0; ni < NI; ni++)
            #pragma unroll
            for (int q = 0; q < 4; q++) acc[mi][ni][q] = 0.f;

    const int a_r  = lane & 15;
    const int a_kc = lane >> 4;
    const int b_r  = lane & 7;
    const int b_kc = (lane >> 3) & 1;

    load_stage(0, 0);
    load_stage(1, 1);

    for (int kt = 0; kt < KT; kt++) {
        asm volatile("cp.async.wait_group 1;");
        __syncthreads();
        load_stage((kt + 2) % 3, kt + 2);

        const int s = kt % 3;
        const uint32_t ab = sb + (uint32_t)(s * STF) * 4u;
        const uint32_t bb = ab + (uint32_t)ASZ * 4u;

        #pragma unroll
        for (int kk = 0; kk < 4; kk++) {
            uint32_t af[MI][4], bf[NI][2];
            #pragma unroll
            for (int mi = 0; mi < MI; mi++) {
                int r = wm * WTM + mi * 16 + a_r;
                int kc = kk * 2 + a_kc;
                ldsm4(af[mi], ab + r * 128 + ((kc ^ (r & 7)) << 4));
            }
            #pragma unroll
            for (int ni = 0; ni < NI; ni++) {
                int r = wn * WTN + ni * 8 + b_r;
                int kc = kk * 2 + b_kc;
                ldsm2(bf[ni], bb + r * 128 + ((kc ^ (r & 7)) << 4));
            }
            #pragma unroll
            for (int mi = 0; mi < MI; mi++)
                #pragma unroll
                for (int ni = 0; ni < NI; ni++)
                    mma_tf32(acc[mi][ni], af[mi], bf[ni]);
        }
    }

    #pragma unroll
    for (int mi = 0; mi < MI; mi++) {
        int row0 = bm0 + wm * WTM + mi * 16 + g;
        int jA = 0, jB = 0, bA = 0, bB = 0;
        if (EPI == 2 || EPI == 3) {
            bA = row0 / JTOT;       jA = row0 - bA * JTOT;
            bB = (row0 + 8) / JTOT; jB = (row0 + 8) - bB * JTOT;
        }
        #pragma unroll
        for (int ni = 0; ni < NI; ni++) {
            int col = bn0 + wn * WTN + ni * 8 + 2 * t;
            float v0 = alpha * acc[mi][ni][0];
            float v1 = alpha * acc[mi][ni][1];
            float v2 = alpha * acc[mi][ni][2];
            float v3 = alpha * acc[mi][ni][3];
            if (bias && EPI != 4) {
                float b0 = bias[col], b1 = bias[col + 1];
                v0 += b0; v1 += b1; v2 += b0; v3 += b1;
            }
            if (Cadd) {
                const float2 c0 = *(const float2*)(Cadd + (long long)row0 * ldc + col);
                const float2 c1 = *(const float2*)(Cadd + (long long)(row0 + 8) * ldc + col);
                v0 += c0.x; v1 += c0.y; v2 += c1.x; v3 += c1.y;
            }
            if (EPI == 1) {
                int d = col & (DH - 1);
                int nA = row0 & (NQ - 1), nB = (row0 + 8) & (NQ - 1);
                float cA0 = ctab[nA * DH + d],     sA0 = stab[nA * DH + d];
                float cA1 = ctab[nA * DH + d + 1], sA1 = stab[nA * DH + d + 1];
                float cB0 = ctab[nB * DH + d],     sB0 = stab[nB * DH + d];
                float cB1 = ctab[nB * DH + d + 1], sB1 = stab[nB * DH + d + 1];
                float o0 = (v0 * cA0 - v1 * sA0) * SCALE;
                float o1 = (v1 * cA1 + v0 * sA1) * SCALE;
                float o2 = (v2 * cB0 - v3 * sB0) * SCALE;
                float o3 = (v3 * cB1 + v2 * sB1) * SCALE;
                v0 = o0; v1 = o1; v2 = o2; v3 = o3;
            }
            if (EPI == 2) {
                int d = col & (DH - 1);
                int h = col >> 6;
                if (jA < MS) {
                    float bb2 = rpe_l[rel_idx[jA >> 8] * HEADS + h];
                    float k0 = v0 + bb2, k1 = v1 + bb2;
                    float c0 = ctab[jA * DH + d],     s0 = stab[jA * DH + d];
                    float c1 = ctab[jA * DH + d + 1], s1 = stab[jA * DH + d + 1];
                    v0 = k0 * c0 - k1 * s0;
                    v1 = k1 * c1 + k0 * s1;
                }
                if (jB < MS) {
                    float bb2 = rpe_l[rel_idx[jB >> 8] * HEADS + h];
                    float k0 = v2 + bb2, k1 = v3 + bb2;
                    float c0 = ctab[jB * DH + d],     s0 = stab[jB * DH + d];
                    float c1 = ctab[jB * DH + d + 1], s1 = stab[jB * DH + d + 1];
                    v2 = k0 * c0 - k1 * s0;
                    v3 = k1 * c1 + k0 * s1;
                }
            }
            if (EPI == 3) {
                float* vtA = C + (long long)bA * DIM * JTOT + (long long)col * JTOT + jA;
                float* vtB = C + (long long)bB * DIM * JTOT + (long long)col * JTOT + jB;
                vtA[0]    = tf32r(v0);
                vtA[JTOT] = tf32r(v1);
                vtB[0]    = tf32r(v2);
                vtB[JTOT] = tf32r(v3);
            } else if (EPI == 4) {
                int oc = col >> 1;
                float ba = bias[oc], bg = bias[FFH + oc];
                float a0 = v0 + ba, g0 = v1 + bg;
                float a1 = v2 + ba, g1 = v3 + bg;
                float y0 = a0 * (0.5f * g0 * (1.0f + erff(g0 * 0.70710678118654752f)));
                float y1 = a1 * (0.5f * g1 * (1.0f + erff(g1 * 0.70710678118654752f)));
                C[(long long)row0 * ldc + oc]       = y0;
                C[(long long)(row0 + 8) * ldc + oc] = y1;
            } else {
                *(float2*)(C + (long long)row0 * ldc + col) = make_float2(v0, v1);
                *(float2*)(C + (long long)(row0 + 8) * ldc + col) = make_float2(v2, v3);
            }
        }
    }
}

// ---------------- flash attention: Q in registers, 96KB smem ----------------
__global__ void __launch_bounds__(256, 2)
flash_attn(const float* __restrict__ Q, const float* __restrict__ K,
           const float* __restrict__ VT, float* __restrict__ O)
{
    extern __shared__ float sm[];
    const uint32_t sb = (uint32_t)__cvta_generic_to_shared(sm);
    const uint32_t pq = sb;
    const uint32_t kb = sb + 8192u * 4u;
    const uint32_t vb = sb + 16384u * 4u;

    const int tid = threadIdx.x, warp = tid >> 5, lane = tid & 31;
    const int g = lane >> 2, t = lane & 3;
    const int m0 = blockIdx.x * 128;
    const int z = blockIdx.y;
    const int b = z >> 4, h = z & 15;

    const float* Qg = Q + ((long long)(b * NQ + m0)) * DIM + h * DH;
    const float* Kg = K + (long long)b * JTOT * DIM + h * DH;
    const float* Vg = VT + (long long)b * DIM * JTOT + (long long)h * DH * JTOT;
    float* Og = O + ((long long)(b * NQ + m0)) * DIM + h * DH;

    auto load_kv_body = [&](int s, int jt) {
        #pragma unroll
        for (int i = 0; i < 4; i++) {
            int idx = tid + i * 256;
            int cc = idx & 7, r = (idx >> 3) & 63, hf = idx >> 9;
            uint32_t off = (uint32_t)(s * 4096 + (hf * 64 + r) * 32) * 4u + ((cc ^ (r & 7)) << 4);
            cpa16(kb + off, Kg + (long long)(jt * 64 + r) * DIM + hf * 32 + cc * 4);
            cpa16(vb + off, Vg + (long long)r * JTOT + jt * 64 + hf * 32 + cc * 4);
        }
    };

    #pragma unroll
    for (int i = 0; i < 8; i++) {
        int idx = tid + i * 256;
        int cc = idx & 7, r = (idx >> 3) & 127, hf = idx >> 10;
        cpa16(pq + (uint32_t)(hf * 128 + r) * 128u + ((cc ^ (r & 7)) << 4),
              Qg + (long long)r * DIM + hf * 32 + cc * 4);
    }
    load_kv_body(0, 0);
    asm volatile("cp.async.commit_group;");
    load_kv_body(1, 1);
    asm volatile("cp.async.commit_group;");

    float acco[8][4];
    #pragma unroll
    for (int ni = 0; ni < 8; ni++)
        #pragma unroll
        for (int q = 0; q < 4; q++) acco[ni][q] = 0.f;
    float mr0 = -INFINITY, mr1 = -INFINITY, l0 = 0.f, l1 = 0.f;

    const int fr = lane & 15;
    const int fc = lane >> 4;

    asm volatile("cp.async.wait_group 1;");
    __syncthreads();

    uint32_t qf[8][4];
    #pragma unroll
    for (int kk = 0; kk < 8; kk++) {
        const int hf = kk >> 2;
        const int kc = (kk & 3) * 2 + fc;
        const int r = warp * 16 + fr;
        ldsm4(qf[kk], pq + (uint32_t)(hf * 128 + r) * 128u + ((kc ^ (r & 7)) << 4));
    }

    for (int jt = 0; jt < NJT; jt++) {
        const int s = jt & 1;
        if (jt > 0) {
            asm volatile("cp.async.wait_group 1;");
            __syncthreads();
        }

        float accs[8][4];
        #pragma unroll
        for (int ni = 0; ni < 8; ni++)
            #pragma unroll
            for (int q = 0; q < 4; q++) accs[ni][q] = 0.f;

        #pragma unroll
        for (int kk = 0; kk < 8; kk++) {
            const int hf = kk >> 2;
            const int kc = (kk & 3) * 2 + fc;
            #pragma unroll
            for (int p = 0; p < 4; p++) {
                int r = p * 16 + fr;
                uint32_t bf[4];
                ldsm4(bf, kb + (uint32_t)(s * 4096 + (hf * 64 + r) * 32) * 4u + ((kc ^ (r & 7)) << 4));
                mma_tf32b(accs[2 * p],     qf[kk], bf[0], bf[2]);
                mma_tf32b(accs[2 * p + 1], qf[kk], bf[1], bf[3]);
            }
        }

        float vm0 = -INFINITY, vm1 = -INFINITY;
        #pragma unroll
        for (int ni = 0; ni < 8; ni++) {
            vm0 = fmaxf(vm0, fmaxf(accs[ni][0], accs[ni][1]));
            vm1 = fmaxf(vm1, fmaxf(accs[ni][2], accs[ni][3]));
        }
        vm0 = fmaxf(vm0, __shfl_xor_sync(0xffffffffu, vm0, 1));
        vm0 = fmaxf(vm0, __shfl_xor_sync(0xffffffffu, vm0, 2));
        vm1 = fmaxf(vm1, __shfl_xor_sync(0xffffffffu, vm1, 1));
        vm1 = fmaxf(vm1, __shfl_xor_sync(0xffffffffu, vm1, 2));
        float mn0 = fmaxf(mr0, vm0), mn1 = fmaxf(mr1, vm1);
        float sc0 = __expf(mr0 - mn0), sc1 = __expf(mr1 - mn1);

        float ps0 = 0.f, ps1 = 0.f;
        #pragma unroll
        for (int ni = 0; ni < 8; ni++) {
            accs[ni][0] = tf32r(__expf(accs[ni][0] - mn0));
            accs[ni][1] = tf32r(__expf(accs[ni][1] - mn0));
            accs[ni][2] = tf32r(__expf(accs[ni][2] - mn1));
            accs[ni][3] = tf32r(__expf(accs[ni][3] - mn1));
            ps0 += accs[ni][0] + accs[ni][1];
            ps1 += accs[ni][2] + accs[ni][3];
        }
        ps0 += __shfl_xor_sync(0xffffffffu, ps0, 1);
        ps0 += __shfl_xor_sync(0xffffffffu, ps0, 2);
        ps1 += __shfl_xor_sync(0xffffffffu, ps1, 1);
        ps1 += __shfl_xor_sync(0xffffffffu, ps1, 2);
        l0 = l0 * sc0 + ps0;
        l1 = l1 * sc1 + ps1;
        mr0 = mn0; mr1 = mn1;
        #pragma unroll
        for (int ni = 0; ni < 8; ni++) {
            acco[ni][0] *= sc0; acco[ni][1] *= sc0;
            acco[ni][2] *= sc1; acco[ni][3] *= sc1;
        }

        const int r0 = warp * 16 + g, r1 = r0 + 8;
        #pragma unroll
        for (int ni = 0; ni < 8; ni++) {
            int hf = ni >> 2;
            int cc = (ni & 3) * 2 + (t >> 1);
            uint32_t ofs = (uint32_t)((t & 1) * 8);
            uint32_t a0 = pq + (uint32_t)(hf * 128 + r0) * 128u + ((cc ^ (r0 & 7)) << 4) + ofs;
            uint32_t a1 = pq + (uint32_t)(hf * 128 + r1) * 128u + ((cc ^ (r1 & 7)) << 4) + ofs;
            asm volatile("st.shared.v2.f32 [%0], {%1,%2};" :: "r"(a0), "f"(accs[ni][0]), "f"(accs[ni][1]));
            asm volatile("st.shared.v2.f32 [%0], {%1,%2};" :: "r"(a1), "f"(accs[ni][2]), "f"(accs[ni][3]));
        }
        __syncwarp();

        #pragma unroll
        for (int kk = 0; kk < 8; kk++) {
            const int hf = kk >> 2;
            const int kc = (kk & 3) * 2 + fc;
            uint32_t a[4];
            {
                int r = warp * 16 + fr;
                ldsm4(a, pq + (uint32_t)(hf * 128 + r) * 128u + ((kc ^ (r & 7)) << 4));
            }
            #pragma unroll
            for (int p = 0; p < 4; p++) {
                int r = p * 16 + fr;
                uint32_t bf[4];
                ldsm4(bf, vb + (uint32_t)(s * 4096 + (hf * 64 + r) * 32) * 4u + ((kc ^ (r & 7)) << 4));
                mma_tf32b(acco[2 * p],     a, bf[0], bf[2]);
                mma_tf32b(acco[2 * p + 1], a, bf[1], bf[3]);
            }
        }
        __syncthreads();

        if (jt + 2 < NJT) load_kv_body(s, jt + 2);
        asm volatile("cp.async.commit_group;");
    }

    float inv0 = 1.f / l0, inv1 = 1.f / l1;
    const int r0 = warp * 16 + g, r1 = r0 + 8;
    #pragma unroll
    for (int ni = 0; ni < 8; ni++) {
        int col = ni * 8 + 2 * t;
        *(float2*)(Og + (long long)r0 * DIM + col) =
            make_float2(acco[ni][0] * inv0, acco[ni][1] * inv0);
        *(float2*)(Og + (long long)r1 * DIM + col) =
            make_float2(acco[ni][2] * inv1, acco[ni][3] * inv1);
    }
}

// ---- batched weight transpose: 64x64 tiles, float4 global I/O ----
__global__ void __launch_bounds__(256)
wtrans_all(const float* __restrict__ Wq, const float* __restrict__ Wk,
           const float* __restrict__ Wv, const float* __restrict__ Wo,
           const float* __restrict__ W1, const float* __restrict__ W2,
           float* __restrict__ WqT, float* __restrict__ WkT,
           float* __restrict__ WvT, float* __restrict__ WoT,
           float* __restrict__ W1T, float* __restrict__ W2T)
{
    __shared__ float tb[64][65];
    const float* ins[6] = {Wq, Wk, Wv, Wo, W1, W2};
    float* outs[6] = {WqT, WkT, WvT, WoT, W1T, W2T};
    const int Rs[6] = {DIM, DIM, DIM, DIM, DIM, FFH};
    const int Cs[6] = {DIM, DIM, DIM, DIM, 2 * FFH, DIM};

    int tile = blockIdx.x, job = 0;
    #pragma unroll
    for (int j2 = 0; j2 < 6; j2++) {
        int nt = DEPTH * (Rs[j2] / 64) * (Cs[j2] / 64);
        if (tile >= nt) { tile -= nt; job++; }
        else break;
    }
    const int R = Rs[job], C = Cs[job];
    const int tpz = (R / 64) * (C / 64);
    const int zdx = tile / tpz;
    const int rem = tile - zdx * tpz;
    const int ty4 = rem / (C / 64), tx4 = rem - ty4 * (C / 64);
    const float* in = ins[job] + (long long)zdx * R * C;
    float* out = outs[job] + (long long)zdx * R * C;

    const int c0 = tx4 * 64, r0 = ty4 * 64;
    const int tx = threadIdx.x & 15, ty = threadIdx.x >> 4;   // 16x16

    #pragma unroll
    for (int i = 0; i < 4; i++) {
        int r = ty + i * 16;
        float4 v = *(const float4*)(in + (long long)(r0 + r) * C + c0 + tx * 4);
        tb[r][tx * 4 + 0] = v.x;
        tb[r][tx * 4 + 1] = v.y;
        tb[r][tx * 4 + 2] = v.z;
        tb[r][tx * 4 + 3] = v.w;
    }
    __syncthreads();

    #pragma unroll
    for (int i = 0; i < 4; i++) {
        int c = c0 + ty + i * 16;
        int sc = ty + i * 16;
        long long orow = c;
        if (job == 4) orow = (c < FFH) ? (2LL * c) : (2LL * (c - FFH) + 1);
        float4 w;
        w.x = tf32r(tb[tx * 4 + 0][sc]);
        w.y = tf32r(tb[tx * 4 + 1][sc]);
        w.z = tf32r(tb[tx * 4 + 2][sc]);
        w.w = tf32r(tb[tx * 4 + 3][sc]);
        *(float4*)(out + orow * R + r0 + tx * 4) = w;
    }
}

// ---------------- cos/sin tables ----------------
__global__ void prep_trig(const float* __restrict__ srcf, const float* __restrict__ tgtf,
                          float* __restrict__ cS, float* __restrict__ sS,
                          float* __restrict__ cT, float* __restrict__ sT)
{
    int idx = blockIdx.x * blockDim.x + threadIdx.x;
    if (idx < NQ * DH) {
        float f = srcf[idx];
        cS[idx] = cosf(f); sS[idx] = sinf(f);
    } else if (idx < NQ * DH + MS * DH) {
        int i = idx - NQ * DH;
        float f = tgtf[i];
        cT[i] = cosf(f); sT[i] = sinf(f);
    }
}

// ---------------- launcher ----------------
extern "C" void kernel_launch(void* const* d_in, const int* in_sizes, int n_in,
                              void* d_out, int out_size)
{
    const float* x    = (const float*)d_in[0];
    const float* cond = (const float*)d_in[1];
    const float* Wq   = (const float*)d_in[2];
    const float* Wk   = (const float*)d_in[3];
    const float* Wv   = (const float*)d_in[4];
    const float* Wo   = (const float*)d_in[5];
    const float* bo   = (const float*)d_in[6];
    const float* rpe  = (const float*)d_in[7];
    const float* W1   = (const float*)d_in[8];
    const float* b1   = (const float*)d_in[9];
    const float* W2   = (const float*)d_in[10];
    const float* b2   = (const float*)d_in[11];
    const float* srcf = (const float*)d_in[12];
    const float* tgtf = (const float*)d_in[13];
    const int*   reli = (const int*)d_in[14];
    float* xo = (float*)d_out;

    float *Q, *K, *VT, *O, *Y;
    float *WqT, *WkT, *WvT, *WoT, *W1T, *W2T;
    float *cS, *sS, *cT, *sT;
    cudaGetSymbolAddress((void**)&Q, g_Q);
    cudaGetSymbolAddress((void**)&K, g_K);
    cudaGetSymbolAddress((void**)&VT, g_VT);
    cudaGetSymbolAddress((void**)&O, g_O);
    cudaGetSymbolAddress((void**)&Y, g_Y);
    cudaGetSymbolAddress((void**)&WqT, g_WqT);
    cudaGetSymbolAddress((void**)&WkT, g_WkT);
    cudaGetSymbolAddress((void**)&WvT, g_WvT);
    cudaGetSymbolAddress((void**)&WoT, g_WoT);
    cudaGetSymbolAddress((void**)&W1T, g_W1T);
    cudaGetSymbolAddress((void**)&W2T, g_W2T);
    cudaGetSymbolAddress((void**)&cS, g_cosS);
    cudaGetSymbolAddress((void**)&sS, g_sinS);
    cudaGetSymbolAddress((void**)&cT, g_cosT);
    cudaGetSymbolAddress((void**)&sT, g_sinT);

    const int SM128 = (128 * 32 + 128 * 32) * 3 * 4;     // 96 KB
    const int SMFL  = 24576 * 4;                         // 96 KB
    cudaFuncSetAttribute(gemm_tc<0>, cudaFuncAttributeMaxDynamicSharedMemorySize, SM128);
    cudaFuncSetAttribute(gemm_tc<1>, cudaFuncAttributeMaxDynamicSharedMemorySize, SM128);
    cudaFuncSetAttribute(gemm_tc<2>, cudaFuncAttributeMaxDynamicSharedMemorySize, SM128);
    cudaFuncSetAttribute(gemm_tc<3>, cudaFuncAttributeMaxDynamicSharedMemorySize, SM128);
    cudaFuncSetAttribute(gemm_tc<4>, cudaFuncAttributeMaxDynamicSharedMemorySize, SM128);
    cudaFuncSetAttribute(flash_attn, cudaFuncAttributeMaxDynamicSharedMemorySize, SMFL);

    // side stream + events (host-side objects; created per call, not graph nodes)
    cudaStream_t s1;
    cudaStreamCreate(&s1);
    cudaEvent_t eW, eKV0, eKV1;
    cudaEventCreateWithFlags(&eW,   cudaEventDisableTiming);
    cudaEventCreateWithFlags(&eKV0, cudaEventDisableTiming);
    cudaEventCreateWithFlags(&eKV1, cudaEventDisableTiming);
    cudaEvent_t eKV[2] = {eKV0, eKV1};

    cudaMemcpyAsync(xo, x, (size_t)MROWS * DIM * sizeof(float),
                    cudaMemcpyDeviceToDevice, 0);

    wtrans_all<<<8192, 256>>>(Wq, Wk, Wv, Wo, W1, W2, WqT, WkT, WvT, WoT, W1T, W2T);
    prep_trig<<<((NQ + MS) * DH + 255) / 256, 256>>>(srcf, tgtf, cS, sS, cT, sT);

    // fork: side stream computes K/V projections for BOTH layers (depend only on cond+weights)
    cudaEventRecord(eW, 0);
    cudaStreamWaitEvent(s1, eW, 0);
    for (int l = 0; l < DEPTH; l++) {
        const float* wkt = WkT + (long long)l * DIM * DIM;
        const float* wvt = WvT + (long long)l * DIM * DIM;
        const float* rpel = rpe + (long long)l * 405 * HEADS;
        float* Kl  = K  + (long long)l * CROWS * DIM;
        float* VTl = VT + (long long)l * BATCH * DIM * JTOT;

        gemm_tc<3><<<dim3(DIM / 128, CROWS / 128), 256, SM128, s1>>>(
            cond, wvt, VTl, nullptr, nullptr,
            DIM, DIM, DIM, DIM, 1.0f, nullptr, nullptr, nullptr, nullptr);
        gemm_tc<2><<<dim3(DIM / 128, CROWS / 128), 256, SM128, s1>>>(
            cond, wkt, Kl, nullptr, nullptr,
            DIM, DIM, DIM, DIM, 1.0f, cT, sT, rpel, reli);
        cudaEventRecord(eKV[l], s1);
    }

    // main stream: residual chain
    for (int l = 0; l < DEPTH; l++) {
        const float* wqt = WqT + (long long)l * DIM * DIM;
        const float* wot = WoT + (long long)l * DIM * DIM;
        const float* bol = bo + l * DIM;
        const float* w1t = W1T + (long long)l * DIM * 2 * FFH;
        const float* b1l = b1 + (long long)l * (2 * FFH);
        const float* w2t = W2T + (long long)l * DIM * FFH;
        const float* b2l = b2 + l * DIM;
        const float* Kl  = K  + (long long)l * CROWS * DIM;
        const float* VTl = VT + (long long)l * BATCH * DIM * JTOT;

        // Q = rope(x @ Wq) * SCALE
        gemm_tc<1><<<dim3(DIM / 128, MROWS / 128), 256, SM128>>>(
            xo, wqt, Q, nullptr, nullptr,
            DIM, DIM, DIM, DIM, 1.0f, cS, sS, nullptr, nullptr);

        // join: K/V(l) must be complete
        cudaStreamWaitEvent(0, eKV[l], 0);

        // fused attention -> O
        flash_attn<<<dim3(NQ / 128, BATCH * HEADS), 256, SMFL>>>(Q, Kl, VTl, O);

        // x = x + O @ Wo + bo
        gemm_tc<0><<<dim3(DIM / 128, MROWS / 128), 256, SM128>>>(
            O, wot, xo, xo, bol,
            DIM, DIM, DIM, DIM, 1.0f, nullptr, nullptr, nullptr, nullptr);

        // Y = GEGLU(x @ W1 + b1)
        gemm_tc<4><<<dim3(2 * FFH / 128, MROWS / 128), 256, SM128>>>(
            xo, w1t, Y, nullptr, b1l,
            DIM, DIM, DIM, FFH, 1.0f, nullptr, nullptr, nullptr, nullptr);

        // x = x + Y @ W2 + b2
        gemm_tc<0><<<dim3(DIM / 128, MROWS / 128), 256, SM128>>>(
            Y, w2t, xo, xo, b2l,
            FFH, FFH, FFH, DIM, 1.0f, nullptr, nullptr, nullptr, nullptr);
    }
}

// round 15
// speedup vs baseline: 1.2113x; 1.0073x over previous
#include <cuda_runtime.h>
#include <math.h>
#include <stdint.h>

// ---------------- problem constants ----------------
#define DEPTH 2
#define DIM   1024
#define HEADS 16
#define DH    64
#define BATCH 8
#define NQ    256
#define JTOT  1088
#define MS    1024
#define MROWS (BATCH*NQ)    // 2048
#define CROWS (BATCH*JTOT)  // 8704
#define FFH   4096
#define SCALE 0.125f
#define NJT   17            // JTOT / 64

// ---------------- scratch ----------------
__device__ float g_Q[MROWS * DIM];
__device__ float g_K[(long)DEPTH * CROWS * DIM];
__device__ float g_VT[(long)DEPTH * BATCH * DIM * JTOT];
__device__ float g_O[MROWS * DIM];
__device__ float g_Y[(long)MROWS * FFH];
__device__ float g_WqT[(long)DEPTH * DIM * DIM];
__device__ float g_WkT[(long)DEPTH * DIM * DIM];
__device__ float g_WvT[(long)DEPTH * DIM * DIM];
__device__ float g_WoT[(long)DEPTH * DIM * DIM];
__device__ float g_W1T[(long)DEPTH * 2 * FFH * DIM];   // interleaved rows
__device__ float g_W2T[(long)DEPTH * DIM * FFH];
__device__ float g_cosS[NQ * DH];
__device__ float g_sinS[NQ * DH];
__device__ float g_cosT[MS * DH];
__device__ float g_sinT[MS * DH];

// ---------------- ptx helpers ----------------
__device__ __forceinline__ float tf32r(float f) {
    uint32_t u;
    asm("cvt.rna.tf32.f32 %0, %1;" : "=r"(u) : "f"(f));
    return __uint_as_float(u);
}
__device__ __forceinline__ void ldsm4(uint32_t* r, uint32_t a) {
    asm volatile("ldmatrix.sync.aligned.m8n8.x4.shared.b16 {%0,%1,%2,%3}, [%4];"
                 : "=r"(r[0]), "=r"(r[1]), "=r"(r[2]), "=r"(r[3]) : "r"(a));
}
__device__ __forceinline__ void ldsm2(uint32_t* r, uint32_t a) {
    asm volatile("ldmatrix.sync.aligned.m8n8.x2.shared.b16 {%0,%1}, [%2];"
                 : "=r"(r[0]), "=r"(r[1]) : "r"(a));
}
__device__ __forceinline__ void mma_tf32(float* c, const uint32_t* a, const uint32_t* b) {
    asm volatile(
        "mma.sync.aligned.m16n8k8.row.col.f32.tf32.tf32.f32 "
        "{%0,%1,%2,%3}, {%4,%5,%6,%7}, {%8,%9}, {%0,%1,%2,%3};"
        : "+f"(c[0]), "+f"(c[1]), "+f"(c[2]), "+f"(c[3])
        : "r"(a[0]), "r"(a[1]), "r"(a[2]), "r"(a[3]), "r"(b[0]), "r"(b[1]));
}
__device__ __forceinline__ void mma_tf32b(float* c, const uint32_t* a, uint32_t b0, uint32_t b1) {
    asm volatile(
        "mma.sync.aligned.m16n8k8.row.col.f32.tf32.tf32.f32 "
        "{%0,%1,%2,%3}, {%4,%5,%6,%7}, {%8,%9}, {%0,%1,%2,%3};"
        : "+f"(c[0]), "+f"(c[1]), "+f"(c[2]), "+f"(c[3])
        : "r"(a[0]), "r"(a[1]), "r"(a[2]), "r"(a[3]), "r"(b0), "r"(b1));
}
__device__ __forceinline__ void cpa16(uint32_t d, const float* s) {
    asm volatile("cp.async.cg.shared.global [%0], [%1], 16;" :: "r"(d), "l"(s));
}

// ---- tf32 GEMM; EPI: 0=plain, 1=rope_q, 2=rpe+rope_k, 3=V^T, 4=GEGLU pairs --
template <int EPI>
__global__ void __launch_bounds__(256, 2)
gemm_tc(const float* __restrict__ A, const float* __restrict__ B,
        float* __restrict__ C, const float* __restrict__ Cadd,
        const float* __restrict__ bias,
        int K, int lda, int ldb, int ldc, float alpha,
        const float* __restrict__ ctab, const float* __restrict__ stab,
        const float* __restrict__ rpe_l, const int* __restrict__ rel_idx)
{
    constexpr int BM = 128, BN = 128;
    constexpr int ASZ = BM * 32, STF = ASZ + BN * 32;
    constexpr int WTM = 64, WTN = 32;
    constexpr int MI = 4, NI = 4;

    extern __shared__ float smdyn[];
    const uint32_t sb = (uint32_t)__cvta_generic_to_shared(smdyn);

    const int tid = threadIdx.x, warp = tid >> 5, lane = tid & 31;
    const int wm = warp >> 2, wn = warp & 3;
    const int g = lane >> 2, t = lane & 3;
    const int bm0 = blockIdx.y * BM, bn0 = blockIdx.x * BN;

    const int arow = tid >> 3;
    const int cc   = tid & 7;

    const float* Ag = A + (long long)(bm0 + arow) * lda + cc * 4;
    const float* Bg = B + (long long)(bn0 + arow) * ldb + cc * 4;

    const int KT = K >> 5;

    auto load_stage = [&](int s, int kt) {
        if (kt < KT) {
            const int k0 = kt << 5;
            uint32_t ab = sb + (uint32_t)(s * STF) * 4u;
            uint32_t bb = ab + (uint32_t)ASZ * 4u;
            #pragma unroll
            for (int i = 0; i < 4; i++) {
                int r = arow + i * 32;
                uint32_t sw = (uint32_t)((cc ^ (r & 7)) << 4);
                cpa16(ab + r * 128 + sw, Ag + (long long)i * 32 * lda + k0);
                cpa16(bb + r * 128 + sw, Bg + (long long)i * 32 * ldb + k0);
            }
        }
        asm volatile("cp.async.commit_group;");
    };

    float acc[MI][NI][4];
    #pragma unroll
    for (int mi = 0; mi < MI; mi++)
        #pragma unroll
        for (int ni = 0; ni < NI; ni++)
            #pragma unroll
            for (int q = 0; q < 4; q++) acc[mi][ni][q] = 0.f;

    const int a_r  = lane & 15;
    const int a_kc = lane >> 4;
    const int b_r  = lane & 7;
    const int b_kc = (lane >> 3) & 1;

    load_stage(0, 0);
    load_stage(1, 1);

    for (int kt = 0; kt < KT; kt++) {
        asm volatile("cp.async.wait_group 1;");
        __syncthreads();
        load_stage((kt + 2) % 3, kt + 2);

        const int s = kt % 3;
        const uint32_t ab = sb + (uint32_t)(s * STF) * 4u;
        const uint32_t bb = ab + (uint32_t)ASZ * 4u;

        #pragma unroll
        for (int kk = 0; kk < 4; kk++) {
            uint32_t af[MI][4], bf[NI][2];
            #pragma unroll
            for (int mi = 0; mi < MI; mi++) {
                int r = wm * WTM + mi * 16 + a_r;
                int kc = kk * 2 + a_kc;
                ldsm4(af[mi], ab + r * 128 + ((kc ^ (r & 7)) << 4));
            }
            #pragma unroll
            for (int ni = 0; ni < NI; ni++) {
                int r = wn * WTN + ni * 8 + b_r;
                int kc = kk * 2 + b_kc;
                ldsm2(bf[ni], bb + r * 128 + ((kc ^ (r & 7)) << 4));
            }
            #pragma unroll
            for (int mi = 0; mi < MI; mi++)
                #pragma unroll
                for (int ni = 0; ni < NI; ni++)
                    mma_tf32(acc[mi][ni], af[mi], bf[ni]);
        }
    }

    #pragma unroll
    for (int mi = 0; mi < MI; mi++) {
        int row0 = bm0 + wm * WTM + mi * 16 + g;
        int jA = 0, jB = 0, bA = 0, bB = 0;
        if (EPI == 2 || EPI == 3) {
            bA = row0 / JTOT;       jA = row0 - bA * JTOT;
            bB = (row0 + 8) / JTOT; jB = (row0 + 8) - bB * JTOT;
        }
        #pragma unroll
        for (int ni = 0; ni < NI; ni++) {
            int col = bn0 + wn * WTN + ni * 8 + 2 * t;
            float v0 = alpha * acc[mi][ni][0];
            float v1 = alpha * acc[mi][ni][1];
            float v2 = alpha * acc[mi][ni][2];
            float v3 = alpha * acc[mi][ni][3];
            if (bias && EPI != 4) {
                float b0 = bias[col], b1 = bias[col + 1];
                v0 += b0; v1 += b1; v2 += b0; v3 += b1;
            }
            if (Cadd) {
                const float2 c0 = *(const float2*)(Cadd + (long long)row0 * ldc + col);
                const float2 c1 = *(const float2*)(Cadd + (long long)(row0 + 8) * ldc + col);
                v0 += c0.x; v1 += c0.y; v2 += c1.x; v3 += c1.y;
            }
            if (EPI == 1) {
                int d = col & (DH - 1);
                int nA = row0 & (NQ - 1), nB = (row0 + 8) & (NQ - 1);
                float cA0 = ctab[nA * DH + d],     sA0 = stab[nA * DH + d];
                float cA1 = ctab[nA * DH + d + 1], sA1 = stab[nA * DH + d + 1];
                float cB0 = ctab[nB * DH + d],     sB0 = stab[nB * DH + d];
                float cB1 = ctab[nB * DH + d + 1], sB1 = stab[nB * DH + d + 1];
                float o0 = (v0 * cA0 - v1 * sA0) * SCALE;
                float o1 = (v1 * cA1 + v0 * sA1) * SCALE;
                float o2 = (v2 * cB0 - v3 * sB0) * SCALE;
                float o3 = (v3 * cB1 + v2 * sB1) * SCALE;
                v0 = o0; v1 = o1; v2 = o2; v3 = o3;
            }
            if (EPI == 2) {
                int d = col & (DH - 1);
                int h = col >> 6;
                if (jA < MS) {
                    float bb2 = rpe_l[rel_idx[jA >> 8] * HEADS + h];
                    float k0 = v0 + bb2, k1 = v1 + bb2;
                    float c0 = ctab[jA * DH + d],     s0 = stab[jA * DH + d];
                    float c1 = ctab[jA * DH + d + 1], s1 = stab[jA * DH + d + 1];
                    v0 = k0 * c0 - k1 * s0;
                    v1 = k1 * c1 + k0 * s1;
                }
                if (jB < MS) {
                    float bb2 = rpe_l[rel_idx[jB >> 8] * HEADS + h];
                    float k0 = v2 + bb2, k1 = v3 + bb2;
                    float c0 = ctab[jB * DH + d],     s0 = stab[jB * DH + d];
                    float c1 = ctab[jB * DH + d + 1], s1 = stab[jB * DH + d + 1];
                    v2 = k0 * c0 - k1 * s0;
                    v3 = k1 * c1 + k0 * s1;
                }
            }
            if (EPI == 3) {
                float* vtA = C + (long long)bA * DIM * JTOT + (long long)col * JTOT + jA;
                float* vtB = C + (long long)bB * DIM * JTOT + (long long)col * JTOT + jB;
                vtA[0]    = tf32r(v0);
                vtA[JTOT] = tf32r(v1);
                vtB[0]    = tf32r(v2);
                vtB[JTOT] = tf32r(v3);
            } else if (EPI == 4) {
                int oc = col >> 1;
                float ba = bias[oc], bg = bias[FFH + oc];
                float a0 = v0 + ba, g0 = v1 + bg;
                float a1 = v2 + ba, g1 = v3 + bg;
                float y0 = a0 * (0.5f * g0 * (1.0f + erff(g0 * 0.70710678118654752f)));
                float y1 = a1 * (0.5f * g1 * (1.0f + erff(g1 * 0.70710678118654752f)));
                C[(long long)row0 * ldc + oc]       = y0;
                C[(long long)(row0 + 8) * ldc + oc] = y1;
            } else {
                *(float2*)(C + (long long)row0 * ldc + col) = make_float2(v0, v1);
                *(float2*)(C + (long long)(row0 + 8) * ldc + col) = make_float2(v2, v3);
            }
        }
    }
}

// ---------------- flash attention ----------------
__global__ void __launch_bounds__(256, 2)
flash_attn(const float* __restrict__ Q, const float* __restrict__ K,
           const float* __restrict__ VT, float* __restrict__ O)
{
    extern __shared__ float sm[];
    const uint32_t sb = (uint32_t)__cvta_generic_to_shared(sm);
    const uint32_t pq = sb;
    const uint32_t kb = sb + 8192u * 4u;
    const uint32_t vb = sb + 16384u * 4u;

    const int tid = threadIdx.x, warp = tid >> 5, lane = tid & 31;
    const int g = lane >> 2, t = lane & 3;
    const int m0 = blockIdx.x * 128;
    const int z = blockIdx.y;
    const int b = z >> 4, h = z & 15;

    const float* Qg = Q + ((long long)(b * NQ + m0)) * DIM + h * DH;
    const float* Kg = K + (long long)b * JTOT * DIM + h * DH;
    const float* Vg = VT + (long long)b * DIM * JTOT + (long long)h * DH * JTOT;
    float* Og = O + ((long long)(b * NQ + m0)) * DIM + h * DH;

    auto load_kv_body = [&](int s, int jt) {
        #pragma unroll
        for (int i = 0; i < 4; i++) {
            int idx = tid + i * 256;
            int cc = idx & 7, r = (idx >> 3) & 63, hf = idx >> 9;
            uint32_t off = (uint32_t)(s * 4096 + (hf * 64 + r) * 32) * 4u + ((cc ^ (r & 7)) << 4);
            cpa16(kb + off, Kg + (long long)(jt * 64 + r) * DIM + hf * 32 + cc * 4);
            cpa16(vb + off, Vg + (long long)r * JTOT + jt * 64 + hf * 32 + cc * 4);
        }
    };

    #pragma unroll
    for (int i = 0; i < 8; i++) {
        int idx = tid + i * 256;
        int cc = idx & 7, r = (idx >> 3) & 127, hf = idx >> 10;
        cpa16(pq + (uint32_t)(hf * 128 + r) * 128u + ((cc ^ (r & 7)) << 4),
              Qg + (long long)r * DIM + hf * 32 + cc * 4);
    }
    load_kv_body(0, 0);
    asm volatile("cp.async.commit_group;");
    load_kv_body(1, 1);
    asm volatile("cp.async.commit_group;");

    float acco[8][4];
    #pragma unroll
    for (int ni = 0; ni < 8; ni++)
        #pragma unroll
        for (int q = 0; q < 4; q++) acco[ni][q] = 0.f;
    float mr0 = -INFINITY, mr1 = -INFINITY, l0 = 0.f, l1 = 0.f;

    const int fr = lane & 15;
    const int fc = lane >> 4;

    asm volatile("cp.async.wait_group 1;");
    __syncthreads();

    uint32_t qf[8][4];
    #pragma unroll
    for (int kk = 0; kk < 8; kk++) {
        const int hf = kk >> 2;
        const int kc = (kk & 3) * 2 + fc;
        const int r = warp * 16 + fr;
        ldsm4(qf[kk], pq + (uint32_t)(hf * 128 + r) * 128u + ((kc ^ (r & 7)) << 4));
    }

    for (int jt = 0; jt < NJT; jt++) {
        const int s = jt & 1;
        if (jt > 0) {
            asm volatile("cp.async.wait_group 1;");
            __syncthreads();
        }

        float accs[8][4];
        #pragma unroll
        for (int ni = 0; ni < 8; ni++)
            #pragma unroll
            for (int q = 0; q < 4; q++) accs[ni][q] = 0.f;

        #pragma unroll
        for (int kk = 0; kk < 8; kk++) {
            const int hf = kk >> 2;
            const int kc = (kk & 3) * 2 + fc;
            #pragma unroll
            for (int p = 0; p < 4; p++) {
                int r = p * 16 + fr;
                uint32_t bf[4];
                ldsm4(bf, kb + (uint32_t)(s * 4096 + (hf * 64 + r) * 32) * 4u + ((kc ^ (r & 7)) << 4));
                mma_tf32b(accs[2 * p],     qf[kk], bf[0], bf[2]);
                mma_tf32b(accs[2 * p + 1], qf[kk], bf[1], bf[3]);
            }
        }

        float vm0 = -INFINITY, vm1 = -INFINITY;
        #pragma unroll
        for (int ni = 0; ni < 8; ni++) {
            vm0 = fmaxf(vm0, fmaxf(accs[ni][0], accs[ni][1]));
            vm1 = fmaxf(vm1, fmaxf(accs[ni][2], accs[ni][3]));
        }
        vm0 = fmaxf(vm0, __shfl_xor_sync(0xffffffffu, vm0, 1));
        vm0 = fmaxf(vm0, __shfl_xor_sync(0xffffffffu, vm0, 2));
        vm1 = fmaxf(vm1, __shfl_xor_sync(0xffffffffu, vm1, 1));
        vm1 = fmaxf(vm1, __shfl_xor_sync(0xffffffffu, vm1, 2));
        float mn0 = fmaxf(mr0, vm0), mn1 = fmaxf(mr1, vm1);
        float sc0 = __expf(mr0 - mn0), sc1 = __expf(mr1 - mn1);

        float ps0 = 0.f, ps1 = 0.f;
        #pragma unroll
        for (int ni = 0; ni < 8; ni++) {
            accs[ni][0] = tf32r(__expf(accs[ni][0] - mn0));
            accs[ni][1] = tf32r(__expf(accs[ni][1] - mn0));
            accs[ni][2] = tf32r(__expf(accs[ni][2] - mn1));
            accs[ni][3] = tf32r(__expf(accs[ni][3] - mn1));
            ps0 += accs[ni][0] + accs[ni][1];
            ps1 += accs[ni][2] + accs[ni][3];
        }
        ps0 += __shfl_xor_sync(0xffffffffu, ps0, 1);
        ps0 += __shfl_xor_sync(0xffffffffu, ps0, 2);
        ps1 += __shfl_xor_sync(0xffffffffu, ps1, 1);
        ps1 += __shfl_xor_sync(0xffffffffu, ps1, 2);
        l0 = l0 * sc0 + ps0;
        l1 = l1 * sc1 + ps1;
        mr0 = mn0; mr1 = mn1;
        #pragma unroll
        for (int ni = 0; ni < 8; ni++) {
            acco[ni][0] *= sc0; acco[ni][1] *= sc0;
            acco[ni][2] *= sc1; acco[ni][3] *= sc1;
        }

        const int r0 = warp * 16 + g, r1 = r0 + 8;
        #pragma unroll
        for (int ni = 0; ni < 8; ni++) {
            int hf = ni >> 2;
            int cc = (ni & 3) * 2 + (t >> 1);
            uint32_t ofs = (uint32_t)((t & 1) * 8);
            uint32_t a0 = pq + (uint32_t)(hf * 128 + r0) * 128u + ((cc ^ (r0 & 7)) << 4) + ofs;
            uint32_t a1 = pq + (uint32_t)(hf * 128 + r1) * 128u + ((cc ^ (r1 & 7)) << 4) + ofs;
            asm volatile("st.shared.v2.f32 [%0], {%1,%2};" :: "r"(a0), "f"(accs[ni][0]), "f"(accs[ni][1]));
            asm volatile("st.shared.v2.f32 [%0], {%1,%2};" :: "r"(a1), "f"(accs[ni][2]), "f"(accs[ni][3]));
        }
        __syncwarp();

        #pragma unroll
        for (int kk = 0; kk < 8; kk++) {
            const int hf = kk >> 2;
            const int kc = (kk & 3) * 2 + fc;
            uint32_t a[4];
            {
                int r = warp * 16 + fr;
                ldsm4(a, pq + (uint32_t)(hf * 128 + r) * 128u + ((kc ^ (r & 7)) << 4));
            }
            #pragma unroll
            for (int p = 0; p < 4; p++) {
                int r = p * 16 + fr;
                uint32_t bf[4];
                ldsm4(bf, vb + (uint32_t)(s * 4096 + (hf * 64 + r) * 32) * 4u + ((kc ^ (r & 7)) << 4));
                mma_tf32b(acco[2 * p],     a, bf[0], bf[2]);
                mma_tf32b(acco[2 * p + 1], a, bf[1], bf[3]);
            }
        }
        __syncthreads();

        if (jt + 2 < NJT) load_kv_body(s, jt + 2);
        asm volatile("cp.async.commit_group;");
    }

    float inv0 = 1.f / l0, inv1 = 1.f / l1;
    const int r0 = warp * 16 + g, r1 = r0 + 8;
    #pragma unroll
    for (int ni = 0; ni < 8; ni++) {
        int col = ni * 8 + 2 * t;
        *(float2*)(Og + (long long)r0 * DIM + col) =
            make_float2(acco[ni][0] * inv0, acco[ni][1] * inv0);
        *(float2*)(Og + (long long)r1 * DIM + col) =
            make_float2(acco[ni][2] * inv1, acco[ni][3] * inv1);
    }
}

// ---- batched weight transpose: 64x64 tiles, float4 I/O, tile_base param ----
// job order (tiles): Wq[0,512) Wk[512,1024) Wv[1024,1536) Wo[1536,2048)
//                    W1[2048,6144) W2[6144,8192)
__global__ void __launch_bounds__(256)
wtrans_all(const float* __restrict__ Wq, const float* __restrict__ Wk,
           const float* __restrict__ Wv, const float* __restrict__ Wo,
           const float* __restrict__ W1, const float* __restrict__ W2,
           float* __restrict__ WqT, float* __restrict__ WkT,
           float* __restrict__ WvT, float* __restrict__ WoT,
           float* __restrict__ W1T, float* __restrict__ W2T,
           int tile_base)
{
    __shared__ float tb[64][65];
    const float* ins[6] = {Wq, Wk, Wv, Wo, W1, W2};
    float* outs[6] = {WqT, WkT, WvT, WoT, W1T, W2T};
    const int Rs[6] = {DIM, DIM, DIM, DIM, DIM, FFH};
    const int Cs[6] = {DIM, DIM, DIM, DIM, 2 * FFH, DIM};

    int tile = blockIdx.x + tile_base, job = 0;
    #pragma unroll
    for (int j2 = 0; j2 < 6; j2++) {
        int nt = DEPTH * (Rs[j2] / 64) * (Cs[j2] / 64);
        if (tile >= nt) { tile -= nt; job++; }
        else break;
    }
    const int R = Rs[job], C = Cs[job];
    const int tpz = (R / 64) * (C / 64);
    const int zdx = tile / tpz;
    const int rem = tile - zdx * tpz;
    const int ty4 = rem / (C / 64), tx4 = rem - ty4 * (C / 64);
    const float* in = ins[job] + (long long)zdx * R * C;
    float* out = outs[job] + (long long)zdx * R * C;

    const int c0 = tx4 * 64, r0 = ty4 * 64;
    const int tx = threadIdx.x & 15, ty = threadIdx.x >> 4;

    #pragma unroll
    for (int i = 0; i < 4; i++) {
        int r = ty + i * 16;
        float4 v = *(const float4*)(in + (long long)(r0 + r) * C + c0 + tx * 4);
        tb[r][tx * 4 + 0] = v.x;
        tb[r][tx * 4 + 1] = v.y;
        tb[r][tx * 4 + 2] = v.z;
        tb[r][tx * 4 + 3] = v.w;
    }
    __syncthreads();

    #pragma unroll
    for (int i = 0; i < 4; i++) {
        int c = c0 + ty + i * 16;
        int sc = ty + i * 16;
        long long orow = c;
        if (job == 4) orow = (c < FFH) ? (2LL * c) : (2LL * (c - FFH) + 1);
        float4 w;
        w.x = tf32r(tb[tx * 4 + 0][sc]);
        w.y = tf32r(tb[tx * 4 + 1][sc]);
        w.z = tf32r(tb[tx * 4 + 2][sc]);
        w.w = tf32r(tb[tx * 4 + 3][sc]);
        *(float4*)(out + orow * R + r0 + tx * 4) = w;
    }
}

// ---------------- cos/sin tables ----------------
__global__ void prep_trig(const float* __restrict__ srcf, const float* __restrict__ tgtf,
                          float* __restrict__ cS, float* __restrict__ sS,
                          float* __restrict__ cT, float* __restrict__ sT)
{
    int idx = blockIdx.x * blockDim.x + threadIdx.x;
    if (idx < NQ * DH) {
        float f = srcf[idx];
        cS[idx] = cosf(f); sS[idx] = sinf(f);
    } else if (idx < NQ * DH + MS * DH) {
        int i = idx - NQ * DH;
        float f = tgtf[i];
        cT[i] = cosf(f); sT[i] = sinf(f);
    }
}

// ---------------- launcher ----------------
extern "C" void kernel_launch(void* const* d_in, const int* in_sizes, int n_in,
                              void* d_out, int out_size)
{
    const float* x    = (const float*)d_in[0];
    const float* cond = (const float*)d_in[1];
    const float* Wq   = (const float*)d_in[2];
    const float* Wk   = (const float*)d_in[3];
    const float* Wv   = (const float*)d_in[4];
    const float* Wo   = (const float*)d_in[5];
    const float* bo   = (const float*)d_in[6];
    const float* rpe  = (const float*)d_in[7];
    const float* W1   = (const float*)d_in[8];
    const float* b1   = (const float*)d_in[9];
    const float* W2   = (const float*)d_in[10];
    const float* b2   = (const float*)d_in[11];
    const float* srcf = (const float*)d_in[12];
    const float* tgtf = (const float*)d_in[13];
    const int*   reli = (const int*)d_in[14];
    float* xo = (float*)d_out;

    float *Q, *K, *VT, *O, *Y;
    float *WqT, *WkT, *WvT, *WoT, *W1T, *W2T;
    float *cS, *sS, *cT, *sT;
    cudaGetSymbolAddress((void**)&Q, g_Q);
    cudaGetSymbolAddress((void**)&K, g_K);
    cudaGetSymbolAddress((void**)&VT, g_VT);
    cudaGetSymbolAddress((void**)&O, g_O);
    cudaGetSymbolAddress((void**)&Y, g_Y);
    cudaGetSymbolAddress((void**)&WqT, g_WqT);
    cudaGetSymbolAddress((void**)&WkT, g_WkT);
    cudaGetSymbolAddress((void**)&WvT, g_WvT);
    cudaGetSymbolAddress((void**)&WoT, g_WoT);
    cudaGetSymbolAddress((void**)&W1T, g_W1T);
    cudaGetSymbolAddress((void**)&W2T, g_W2T);
    cudaGetSymbolAddress((void**)&cS, g_cosS);
    cudaGetSymbolAddress((void**)&sS, g_sinS);
    cudaGetSymbolAddress((void**)&cT, g_cosT);
    cudaGetSymbolAddress((void**)&sT, g_sinT);

    const int SM128 = (128 * 32 + 128 * 32) * 3 * 4;     // 96 KB
    const int SMFL  = 24576 * 4;                         // 96 KB

    // --- one-time resource setup (first call = uncaptured correctness run,
    //     so all driver allocations land BEFORE the harness baseline) ---
    static bool s_init = false;
    static cudaStream_t s1, s2;
    static cudaEvent_t eStart, ePrep, eWkv, eV0, eV1, eK0, eK1;
    if (!s_init) {
        cudaFuncSetAttribute(gemm_tc<0>, cudaFuncAttributeMaxDynamicSharedMemorySize, SM128);
        cudaFuncSetAttribute(gemm_tc<1>, cudaFuncAttributeMaxDynamicSharedMemorySize, SM128);
        cudaFuncSetAttribute(gemm_tc<2>, cudaFuncAttributeMaxDynamicSharedMemorySize, SM128);
        cudaFuncSetAttribute(gemm_tc<3>, cudaFuncAttributeMaxDynamicSharedMemorySize, SM128);
        cudaFuncSetAttribute(gemm_tc<4>, cudaFuncAttributeMaxDynamicSharedMemorySize, SM128);
        cudaFuncSetAttribute(flash_attn, cudaFuncAttributeMaxDynamicSharedMemorySize, SMFL);
        cudaStreamCreate(&s1);
        cudaStreamCreate(&s2);
        cudaEventCreateWithFlags(&eStart, cudaEventDisableTiming);
        cudaEventCreateWithFlags(&ePrep,  cudaEventDisableTiming);
        cudaEventCreateWithFlags(&eWkv,   cudaEventDisableTiming);
        cudaEventCreateWithFlags(&eV0, cudaEventDisableTiming);
        cudaEventCreateWithFlags(&eV1, cudaEventDisableTiming);
        cudaEventCreateWithFlags(&eK0, cudaEventDisableTiming);
        cudaEventCreateWithFlags(&eK1, cudaEventDisableTiming);
        s_init = true;
    }
    cudaEvent_t eV[2] = {eV0, eV1}, eK[2] = {eK0, eK1};

    // ---- legal fork: eStart recorded on capturing stream 0 first ----
    cudaMemcpyAsync(xo, x, (size_t)MROWS * DIM * sizeof(float),
                    cudaMemcpyDeviceToDevice, 0);
    cudaEventRecord(eStart, 0);

    // ---- s1: Wk/Wv transpose + V projections ----
    cudaStreamWaitEvent(s1, eStart, 0);
    wtrans_all<<<1024, 256, 0, s1>>>(Wq, Wk, Wv, Wo, W1, W2,
                                     WqT, WkT, WvT, WoT, W1T, W2T, 512);
    cudaEventRecord(eWkv, s1);

    // ---- main stream: trig + remaining transposes ----
    prep_trig<<<((NQ + MS) * DH + 255) / 256, 256>>>(srcf, tgtf, cS, sS, cT, sT);
    cudaEventRecord(ePrep, 0);
    wtrans_all<<<512, 256>>>(Wq, Wk, Wv, Wo, W1, W2,
                             WqT, WkT, WvT, WoT, W1T, W2T, 0);       // Wq
    wtrans_all<<<6656, 256>>>(Wq, Wk, Wv, Wo, W1, W2,
                              WqT, WkT, WvT, WoT, W1T, W2T, 1536);   // Wo,W1,W2

    // ---- s1: V projections (need WvT only) ----
    for (int l = 0; l < DEPTH; l++) {
        const float* wvt = WvT + (long long)l * DIM * DIM;
        float* VTl = VT + (long long)l * BATCH * DIM * JTOT;
        gemm_tc<3><<<dim3(DIM / 128, CROWS / 128), 256, SM128, s1>>>(
            cond, wvt, VTl, nullptr, nullptr,
            DIM, DIM, DIM, DIM, 1.0f, nullptr, nullptr, nullptr, nullptr);
        cudaEventRecord(eV[l], s1);
    }
    // ---- s2: K projections (need WkT + trig) ----
    cudaStreamWaitEvent(s2, eWkv, 0);
    cudaStreamWaitEvent(s2, ePrep, 0);
    for (int l = 0; l < DEPTH; l++) {
        const float* wkt = WkT + (long long)l * DIM * DIM;
        const float* rpel = rpe + (long long)l * 405 * HEADS;
        float* Kl = K + (long long)l * CROWS * DIM;
        gemm_tc<2><<<dim3(DIM / 128, CROWS / 128), 256, SM128, s2>>>(
            cond, wkt, Kl, nullptr, nullptr,
            DIM, DIM, DIM, DIM, 1.0f, cT, sT, rpel, reli);
        cudaEventRecord(eK[l], s2);
    }

    // ---- main stream: residual chain ----
    for (int l = 0; l < DEPTH; l++) {
        const float* wqt = WqT + (long long)l * DIM * DIM;
        const float* wot = WoT + (long long)l * DIM * DIM;
        const float* bol = bo + l * DIM;
        const float* w1t = W1T + (long long)l * DIM * 2 * FFH;
        const float* b1l = b1 + (long long)l * (2 * FFH);
        const float* w2t = W2T + (long long)l * DIM * FFH;
        const float* b2l = b2 + l * DIM;
        const float* Kl  = K  + (long long)l * CROWS * DIM;
        const float* VTl = VT + (long long)l * BATCH * DIM * JTOT;

        gemm_tc<1><<<dim3(DIM / 128, MROWS / 128), 256, SM128>>>(
            xo, wqt, Q, nullptr, nullptr,
            DIM, DIM, DIM, DIM, 1.0f, cS, sS, nullptr, nullptr);

        cudaStreamWaitEvent(0, eV[l], 0);
        cudaStreamWaitEvent(0, eK[l], 0);

        flash_attn<<<dim3(NQ / 128, BATCH * HEADS), 256, SMFL>>>(Q, Kl, VTl, O);

        gemm_tc<0><<<dim3(DIM / 128, MROWS / 128), 256, SM128>>>(
            O, wot, xo, xo, bol,
            DIM, DIM, DIM, DIM, 1.0f, nullptr, nullptr, nullptr, nullptr);

        gemm_tc<4><<<dim3(2 * FFH / 128, MROWS / 128), 256, SM128>>>(
            xo, w1t, Y, nullptr, b1l,
            DIM, DIM, DIM, FFH, 1.0f, nullptr, nullptr, nullptr, nullptr);

        gemm_tc<0><<<dim3(DIM / 128, MROWS / 128), 256, SM128>>>(
            Y, w2t, xo, xo, b2l,
            FFH, FFH, FFH, DIM, 1.0f, nullptr, nullptr, nullptr, nullptr);
    }
}

// round 16
// speedup vs baseline: 1.2140x; 1.0022x over previous
#include <cuda_runtime.h>
#include <math.h>
#include <stdint.h>

// ---------------- problem constants ----------------
#define DEPTH 2
#define DIM   1024
#define HEADS 16
#define DH    64
#define BATCH 8
#define NQ    256
#define JTOT  1088
#define MS    1024
#define MROWS (BATCH*NQ)    // 2048
#define CROWS (BATCH*JTOT)  // 8704
#define FFH   4096
#define SCALE 0.125f
#define NJT   17            // JTOT / 64

// ---------------- scratch ----------------
__device__ float g_Q[MROWS * DIM];
__device__ float g_K[(long)DEPTH * CROWS * DIM];
__device__ float g_VT[(long)DEPTH * BATCH * DIM * JTOT];
__device__ float g_O[MROWS * DIM];
__device__ float g_Y[(long)MROWS * FFH];
__device__ float g_P2[MROWS * DIM];
__device__ float g_WqT[(long)DEPTH * DIM * DIM];
__device__ float g_WkT[(long)DEPTH * DIM * DIM];
__device__ float g_WvT[(long)DEPTH * DIM * DIM];
__device__ float g_WoT[(long)DEPTH * DIM * DIM];
__device__ float g_W1T[(long)DEPTH * 2 * FFH * DIM];   // interleaved rows
__device__ float g_W2T[(long)DEPTH * DIM * FFH];
__device__ float g_cosS[NQ * DH];
__device__ float g_sinS[NQ * DH];
__device__ float g_cosT[MS * DH];
__device__ float g_sinT[MS * DH];

// ---------------- ptx helpers ----------------
__device__ __forceinline__ float tf32r(float f) {
    uint32_t u;
    asm("cvt.rna.tf32.f32 %0, %1;" : "=r"(u) : "f"(f));
    return __uint_as_float(u);
}
__device__ __forceinline__ void ldsm4(uint32_t* r, uint32_t a) {
    asm volatile("ldmatrix.sync.aligned.m8n8.x4.shared.b16 {%0,%1,%2,%3}, [%4];"
                 : "=r"(r[0]), "=r"(r[1]), "=r"(r[2]), "=r"(r[3]) : "r"(a));
}
__device__ __forceinline__ void ldsm2(uint32_t* r, uint32_t a) {
    asm volatile("ldmatrix.sync.aligned.m8n8.x2.shared.b16 {%0,%1}, [%2];"
                 : "=r"(r[0]), "=r"(r[1]) : "r"(a));
}
__device__ __forceinline__ void mma_tf32(float* c, const uint32_t* a, const uint32_t* b) {
    asm volatile(
        "mma.sync.aligned.m16n8k8.row.col.f32.tf32.tf32.f32 "
        "{%0,%1,%2,%3}, {%4,%5,%6,%7}, {%8,%9}, {%0,%1,%2,%3};"
        : "+f"(c[0]), "+f"(c[1]), "+f"(c[2]), "+f"(c[3])
        : "r"(a[0]), "r"(a[1]), "r"(a[2]), "r"(a[3]), "r"(b[0]), "r"(b[1]));
}
__device__ __forceinline__ void mma_tf32b(float* c, const uint32_t* a, uint32_t b0, uint32_t b1) {
    asm volatile(
        "mma.sync.aligned.m16n8k8.row.col.f32.tf32.tf32.f32 "
        "{%0,%1,%2,%3}, {%4,%5,%6,%7}, {%8,%9}, {%0,%1,%2,%3};"
        : "+f"(c[0]), "+f"(c[1]), "+f"(c[2]), "+f"(c[3])
        : "r"(a[0]), "r"(a[1]), "r"(a[2]), "r"(a[3]), "r"(b0), "r"(b1));
}
__device__ __forceinline__ void cpa16(uint32_t d, const float* s) {
    asm volatile("cp.async.cg.shared.global [%0], [%1], 16;" :: "r"(d), "l"(s));
}

// ---- tf32 GEMM; EPI: 0=plain, 1=rope_q, 2=rpe+rope_k, 3=V^T, 4=GEGLU pairs --
template <int EPI>
__global__ void __launch_bounds__(256, 2)
gemm_tc(const float* __restrict__ A, const float* __restrict__ B,
        float* __restrict__ C, const float* __restrict__ Cadd,
        const float* __restrict__ bias,
        int K, int lda, int ldb, int ldc, float alpha,
        const float* __restrict__ ctab, const float* __restrict__ stab,
        const float* __restrict__ rpe_l, const int* __restrict__ rel_idx)
{
    constexpr int BM = 128, BN = 128;
    constexpr int ASZ = BM * 32, STF = ASZ + BN * 32;
    constexpr int WTM = 64, WTN = 32;
    constexpr int MI = 4, NI = 4;

    extern __shared__ float smdyn[];
    const uint32_t sb = (uint32_t)__cvta_generic_to_shared(smdyn);

    const int tid = threadIdx.x, warp = tid >> 5, lane = tid & 31;
    const int wm = warp >> 2, wn = warp & 3;
    const int g = lane >> 2, t = lane & 3;
    const int bm0 = blockIdx.y * BM, bn0 = blockIdx.x * BN;

    const int arow = tid >> 3;
    const int cc   = tid & 7;

    const float* Ag = A + (long long)(bm0 + arow) * lda + cc * 4;
    const float* Bg = B + (long long)(bn0 + arow) * ldb + cc * 4;

    const int KT = K >> 5;

    auto load_stage = [&](int s, int kt) {
        if (kt < KT) {
            const int k0 = kt << 5;
            uint32_t ab = sb + (uint32_t)(s * STF) * 4u;
            uint32_t bb = ab + (uint32_t)ASZ * 4u;
            #pragma unroll
            for (int i = 0; i < 4; i++) {
                int r = arow + i * 32;
                uint32_t sw = (uint32_t)((cc ^ (r & 7)) << 4);
                cpa16(ab + r * 128 + sw, Ag + (long long)i * 32 * lda + k0);
                cpa16(bb + r * 128 + sw, Bg + (long long)i * 32 * ldb + k0);
            }
        }
        asm volatile("cp.async.commit_group;");
    };

    float acc[MI][NI][4];
    #pragma unroll
    for (int mi = 0; mi < MI; mi++)
        #pragma unroll
        for (int ni = 0; ni < NI; ni++)
            #pragma unroll
            for (int q = 0; q < 4; q++) acc[mi][ni][q] = 0.f;

    const int a_r  = lane & 15;
    const int a_kc = lane >> 4;
    const int b_r  = lane & 7;
    const int b_kc = (lane >> 3) & 1;

    load_stage(0, 0);
    load_stage(1, 1);

    for (int kt = 0; kt < KT; kt++) {
        asm volatile("cp.async.wait_group 1;");
        __syncthreads();
        load_stage((kt + 2) % 3, kt + 2);

        const int s = kt % 3;
        const uint32_t ab = sb + (uint32_t)(s * STF) * 4u;
        const uint32_t bb = ab + (uint32_t)ASZ * 4u;

        #pragma unroll
        for (int kk = 0; kk < 4; kk++) {
            uint32_t af[MI][4], bf[NI][2];
            #pragma unroll
            for (int mi = 0; mi < MI; mi++) {
                int r = wm * WTM + mi * 16 + a_r;
                int kc = kk * 2 + a_kc;
                ldsm4(af[mi], ab + r * 128 + ((kc ^ (r & 7)) << 4));
            }
            #pragma unroll
            for (int ni = 0; ni < NI; ni++) {
                int r = wn * WTN + ni * 8 + b_r;
                int kc = kk * 2 + b_kc;
                ldsm2(bf[ni], bb + r * 128 + ((kc ^ (r & 7)) << 4));
            }
            #pragma unroll
            for (int mi = 0; mi < MI; mi++)
                #pragma unroll
                for (int ni = 0; ni < NI; ni++)
                    mma_tf32(acc[mi][ni], af[mi], bf[ni]);
        }
    }

    #pragma unroll
    for (int mi = 0; mi < MI; mi++) {
        int row0 = bm0 + wm * WTM + mi * 16 + g;
        int jA = 0, jB = 0, bA = 0, bB = 0;
        if (EPI == 2 || EPI == 3) {
            bA = row0 / JTOT;       jA = row0 - bA * JTOT;
            bB = (row0 + 8) / JTOT; jB = (row0 + 8) - bB * JTOT;
        }
        #pragma unroll
        for (int ni = 0; ni < NI; ni++) {
            int col = bn0 + wn * WTN + ni * 8 + 2 * t;
            float v0 = alpha * acc[mi][ni][0];
            float v1 = alpha * acc[mi][ni][1];
            float v2 = alpha * acc[mi][ni][2];
            float v3 = alpha * acc[mi][ni][3];
            if (bias && EPI != 4) {
                float b0 = bias[col], b1 = bias[col + 1];
                v0 += b0; v1 += b1; v2 += b0; v3 += b1;
            }
            if (Cadd) {
                const float2 c0 = *(const float2*)(Cadd + (long long)row0 * ldc + col);
                const float2 c1 = *(const float2*)(Cadd + (long long)(row0 + 8) * ldc + col);
                v0 += c0.x; v1 += c0.y; v2 += c1.x; v3 += c1.y;
            }
            if (EPI == 1) {
                int d = col & (DH - 1);
                int nA = row0 & (NQ - 1), nB = (row0 + 8) & (NQ - 1);
                float cA0 = ctab[nA * DH + d],     sA0 = stab[nA * DH + d];
                float cA1 = ctab[nA * DH + d + 1], sA1 = stab[nA * DH + d + 1];
                float cB0 = ctab[nB * DH + d],     sB0 = stab[nB * DH + d];
                float cB1 = ctab[nB * DH + d + 1], sB1 = stab[nB * DH + d + 1];
                float o0 = (v0 * cA0 - v1 * sA0) * SCALE;
                float o1 = (v1 * cA1 + v0 * sA1) * SCALE;
                float o2 = (v2 * cB0 - v3 * sB0) * SCALE;
                float o3 = (v3 * cB1 + v2 * sB1) * SCALE;
                v0 = o0; v1 = o1; v2 = o2; v3 = o3;
            }
            if (EPI == 2) {
                int d = col & (DH - 1);
                int h = col >> 6;
                if (jA < MS) {
                    float bb2 = rpe_l[rel_idx[jA >> 8] * HEADS + h];
                    float k0 = v0 + bb2, k1 = v1 + bb2;
                    float c0 = ctab[jA * DH + d],     s0 = stab[jA * DH + d];
                    float c1 = ctab[jA * DH + d + 1], s1 = stab[jA * DH + d + 1];
                    v0 = k0 * c0 - k1 * s0;
                    v1 = k1 * c1 + k0 * s1;
                }
                if (jB < MS) {
                    float bb2 = rpe_l[rel_idx[jB >> 8] * HEADS + h];
                    float k0 = v2 + bb2, k1 = v3 + bb2;
                    float c0 = ctab[jB * DH + d],     s0 = stab[jB * DH + d];
                    float c1 = ctab[jB * DH + d + 1], s1 = stab[jB * DH + d + 1];
                    v2 = k0 * c0 - k1 * s0;
                    v3 = k1 * c1 + k0 * s1;
                }
            }
            if (EPI == 3) {
                float* vtA = C + (long long)bA * DIM * JTOT + (long long)col * JTOT + jA;
                float* vtB = C + (long long)bB * DIM * JTOT + (long long)col * JTOT + jB;
                vtA[0]    = tf32r(v0);
                vtA[JTOT] = tf32r(v1);
                vtB[0]    = tf32r(v2);
                vtB[JTOT] = tf32r(v3);
            } else if (EPI == 4) {
                int oc = col >> 1;
                float ba = bias[oc], bg = bias[FFH + oc];
                float a0 = v0 + ba, g0 = v1 + bg;
                float a1 = v2 + ba, g1 = v3 + bg;
                float y0 = a0 * (0.5f * g0 * (1.0f + erff(g0 * 0.70710678118654752f)));
                float y1 = a1 * (0.5f * g1 * (1.0f + erff(g1 * 0.70710678118654752f)));
                C[(long long)row0 * ldc + oc]       = y0;
                C[(long long)(row0 + 8) * ldc + oc] = y1;
            } else {
                *(float2*)(C + (long long)row0 * ldc + col) = make_float2(v0, v1);
                *(float2*)(C + (long long)(row0 + 8) * ldc + col) = make_float2(v2, v3);
            }
        }
    }
}

// ---------------- flash attention ----------------
__global__ void __launch_bounds__(256, 2)
flash_attn(const float* __restrict__ Q, const float* __restrict__ K,
           const float* __restrict__ VT, float* __restrict__ O)
{
    extern __shared__ float sm[];
    const uint32_t sb = (uint32_t)__cvta_generic_to_shared(sm);
    const uint32_t pq = sb;
    const uint32_t kb = sb + 8192u * 4u;
    const uint32_t vb = sb + 16384u * 4u;

    const int tid = threadIdx.x, warp = tid >> 5, lane = tid & 31;
    const int g = lane >> 2, t = lane & 3;
    const int m0 = blockIdx.x * 128;
    const int z = blockIdx.y;
    const int b = z >> 4, h = z & 15;

    const float* Qg = Q + ((long long)(b * NQ + m0)) * DIM + h * DH;
    const float* Kg = K + (long long)b * JTOT * DIM + h * DH;
    const float* Vg = VT + (long long)b * DIM * JTOT + (long long)h * DH * JTOT;
    float* Og = O + ((long long)(b * NQ + m0)) * DIM + h * DH;

    auto load_kv_body = [&](int s, int jt) {
        #pragma unroll
        for (int i = 0; i < 4; i++) {
            int idx = tid + i * 256;
            int cc = idx & 7, r = (idx >> 3) & 63, hf = idx >> 9;
            uint32_t off = (uint32_t)(s * 4096 + (hf * 64 + r) * 32) * 4u + ((cc ^ (r & 7)) << 4);
            cpa16(kb + off, Kg + (long long)(jt * 64 + r) * DIM + hf * 32 + cc * 4);
            cpa16(vb + off, Vg + (long long)r * JTOT + jt * 64 + hf * 32 + cc * 4);
        }
    };

    #pragma unroll
    for (int i = 0; i < 8; i++) {
        int idx = tid + i * 256;
        int cc = idx & 7, r = (idx >> 3) & 127, hf = idx >> 10;
        cpa16(pq + (uint32_t)(hf * 128 + r) * 128u + ((cc ^ (r & 7)) << 4),
              Qg + (long long)r * DIM + hf * 32 + cc * 4);
    }
    load_kv_body(0, 0);
    asm volatile("cp.async.commit_group;");
    load_kv_body(1, 1);
    asm volatile("cp.async.commit_group;");

    float acco[8][4];
    #pragma unroll
    for (int ni = 0; ni < 8; ni++)
        #pragma unroll
        for (int q = 0; q < 4; q++) acco[ni][q] = 0.f;
    float mr0 = -INFINITY, mr1 = -INFINITY, l0 = 0.f, l1 = 0.f;

    const int fr = lane & 15;
    const int fc = lane >> 4;

    asm volatile("cp.async.wait_group 1;");
    __syncthreads();

    uint32_t qf[8][4];
    #pragma unroll
    for (int kk = 0; kk < 8; kk++) {
        const int hf = kk >> 2;
        const int kc = (kk & 3) * 2 + fc;
        const int r = warp * 16 + fr;
        ldsm4(qf[kk], pq + (uint32_t)(hf * 128 + r) * 128u + ((kc ^ (r & 7)) << 4));
    }

    for (int jt = 0; jt < NJT; jt++) {
        const int s = jt & 1;
        if (jt > 0) {
            asm volatile("cp.async.wait_group 1;");
            __syncthreads();
        }

        float accs[8][4];
        #pragma unroll
        for (int ni = 0; ni < 8; ni++)
            #pragma unroll
            for (int q = 0; q < 4; q++) accs[ni][q] = 0.f;

        #pragma unroll
        for (int kk = 0; kk < 8; kk++) {
            const int hf = kk >> 2;
            const int kc = (kk & 3) * 2 + fc;
            #pragma unroll
            for (int p = 0; p < 4; p++) {
                int r = p * 16 + fr;
                uint32_t bf[4];
                ldsm4(bf, kb + (uint32_t)(s * 4096 + (hf * 64 + r) * 32) * 4u + ((kc ^ (r & 7)) << 4));
                mma_tf32b(accs[2 * p],     qf[kk], bf[0], bf[2]);
                mma_tf32b(accs[2 * p + 1], qf[kk], bf[1], bf[3]);
            }
        }

        float vm0 = -INFINITY, vm1 = -INFINITY;
        #pragma unroll
        for (int ni = 0; ni < 8; ni++) {
            vm0 = fmaxf(vm0, fmaxf(accs[ni][0], accs[ni][1]));
            vm1 = fmaxf(vm1, fmaxf(accs[ni][2], accs[ni][3]));
        }
        vm0 = fmaxf(vm0, __shfl_xor_sync(0xffffffffu, vm0, 1));
        vm0 = fmaxf(vm0, __shfl_xor_sync(0xffffffffu, vm0, 2));
        vm1 = fmaxf(vm1, __shfl_xor_sync(0xffffffffu, vm1, 1));
        vm1 = fmaxf(vm1, __shfl_xor_sync(0xffffffffu, vm1, 2));
        float mn0 = fmaxf(mr0, vm0), mn1 = fmaxf(mr1, vm1);
        float sc0 = __expf(mr0 - mn0), sc1 = __expf(mr1 - mn1);

        float ps0 = 0.f, ps1 = 0.f;
        #pragma unroll
        for (int ni = 0; ni < 8; ni++) {
            accs[ni][0] = tf32r(__expf(accs[ni][0] - mn0));
            accs[ni][1] = tf32r(__expf(accs[ni][1] - mn0));
            accs[ni][2] = tf32r(__expf(accs[ni][2] - mn1));
            accs[ni][3] = tf32r(__expf(accs[ni][3] - mn1));
            ps0 += accs[ni][0] + accs[ni][1];
            ps1 += accs[ni][2] + accs[ni][3];
        }
        ps0 += __shfl_xor_sync(0xffffffffu, ps0, 1);
        ps0 += __shfl_xor_sync(0xffffffffu, ps0, 2);
        ps1 += __shfl_xor_sync(0xffffffffu, ps1, 1);
        ps1 += __shfl_xor_sync(0xffffffffu, ps1, 2);
        l0 = l0 * sc0 + ps0;
        l1 = l1 * sc1 + ps1;
        mr0 = mn0; mr1 = mn1;
        #pragma unroll
        for (int ni = 0; ni < 8; ni++) {
            acco[ni][0] *= sc0; acco[ni][1] *= sc0;
            acco[ni][2] *= sc1; acco[ni][3] *= sc1;
        }

        const int r0 = warp * 16 + g, r1 = r0 + 8;
        #pragma unroll
        for (int ni = 0; ni < 8; ni++) {
            int hf = ni >> 2;
            int cc = (ni & 3) * 2 + (t >> 1);
            uint32_t ofs = (uint32_t)((t & 1) * 8);
            uint32_t a0 = pq + (uint32_t)(hf * 128 + r0) * 128u + ((cc ^ (r0 & 7)) << 4) + ofs;
            uint32_t a1 = pq + (uint32_t)(hf * 128 + r1) * 128u + ((cc ^ (r1 & 7)) << 4) + ofs;
            asm volatile("st.shared.v2.f32 [%0], {%1,%2};" :: "r"(a0), "f"(accs[ni][0]), "f"(accs[ni][1]));
            asm volatile("st.shared.v2.f32 [%0], {%1,%2};" :: "r"(a1), "f"(accs[ni][2]), "f"(accs[ni][3]));
        }
        __syncwarp();

        #pragma unroll
        for (int kk = 0; kk < 8; kk++) {
            const int hf = kk >> 2;
            const int kc = (kk & 3) * 2 + fc;
            uint32_t a[4];
            {
                int r = warp * 16 + fr;
                ldsm4(a, pq + (uint32_t)(hf * 128 + r) * 128u + ((kc ^ (r & 7)) << 4));
            }
            #pragma unroll
            for (int p = 0; p < 4; p++) {
                int r = p * 16 + fr;
                uint32_t bf[4];
                ldsm4(bf, vb + (uint32_t)(s * 4096 + (hf * 64 + r) * 32) * 4u + ((kc ^ (r & 7)) << 4));
                mma_tf32b(acco[2 * p],     a, bf[0], bf[2]);
                mma_tf32b(acco[2 * p + 1], a, bf[1], bf[3]);
            }
        }
        __syncthreads();

        if (jt + 2 < NJT) load_kv_body(s, jt + 2);
        asm volatile("cp.async.commit_group;");
    }

    float inv0 = 1.f / l0, inv1 = 1.f / l1;
    const int r0 = warp * 16 + g, r1 = r0 + 8;
    #pragma unroll
    for (int ni = 0; ni < 8; ni++) {
        int col = ni * 8 + 2 * t;
        *(float2*)(Og + (long long)r0 * DIM + col) =
            make_float2(acco[ni][0] * inv0, acco[ni][1] * inv0);
        *(float2*)(Og + (long long)r1 * DIM + col) =
            make_float2(acco[ni][2] * inv1, acco[ni][3] * inv1);
    }
}

// ---- batched weight transpose: 64x64 tiles, float4 I/O, tile_base param ----
__global__ void __launch_bounds__(256)
wtrans_all(const float* __restrict__ Wq, const float* __restrict__ Wk,
           const float* __restrict__ Wv, const float* __restrict__ Wo,
           const float* __restrict__ W1, const float* __restrict__ W2,
           float* __restrict__ WqT, float* __restrict__ WkT,
           float* __restrict__ WvT, float* __restrict__ WoT,
           float* __restrict__ W1T, float* __restrict__ W2T,
           int tile_base)
{
    __shared__ float tb[64][65];
    const float* ins[6] = {Wq, Wk, Wv, Wo, W1, W2};
    float* outs[6] = {WqT, WkT, WvT, WoT, W1T, W2T};
    const int Rs[6] = {DIM, DIM, DIM, DIM, DIM, FFH};
    const int Cs[6] = {DIM, DIM, DIM, DIM, 2 * FFH, DIM};

    int tile = blockIdx.x + tile_base, job = 0;
    #pragma unroll
    for (int j2 = 0; j2 < 6; j2++) {
        int nt = DEPTH * (Rs[j2] / 64) * (Cs[j2] / 64);
        if (tile >= nt) { tile -= nt; job++; }
        else break;
    }
    const int R = Rs[job], C = Cs[job];
    const int tpz = (R / 64) * (C / 64);
    const int zdx = tile / tpz;
    const int rem = tile - zdx * tpz;
    const int ty4 = rem / (C / 64), tx4 = rem - ty4 * (C / 64);
    const float* in = ins[job] + (long long)zdx * R * C;
    float* out = outs[job] + (long long)zdx * R * C;

    const int c0 = tx4 * 64, r0 = ty4 * 64;
    const int tx = threadIdx.x & 15, ty = threadIdx.x >> 4;

    #pragma unroll
    for (int i = 0; i < 4; i++) {
        int r = ty + i * 16;
        float4 v = *(const float4*)(in + (long long)(r0 + r) * C + c0 + tx * 4);
        tb[r][tx * 4 + 0] = v.x;
        tb[r][tx * 4 + 1] = v.y;
        tb[r][tx * 4 + 2] = v.z;
        tb[r][tx * 4 + 3] = v.w;
    }
    __syncthreads();

    #pragma unroll
    for (int i = 0; i < 4; i++) {
        int c = c0 + ty + i * 16;
        int sc = ty + i * 16;
        long long orow = c;
        if (job == 4) orow = (c < FFH) ? (2LL * c) : (2LL * (c - FFH) + 1);
        float4 w;
        w.x = tf32r(tb[tx * 4 + 0][sc]);
        w.y = tf32r(tb[tx * 4 + 1][sc]);
        w.z = tf32r(tb[tx * 4 + 2][sc]);
        w.w = tf32r(tb[tx * 4 + 3][sc]);
        *(float4*)(out + orow * R + r0 + tx * 4) = w;
    }
}

// ---------------- cos/sin tables ----------------
__global__ void prep_trig(const float* __restrict__ srcf, const float* __restrict__ tgtf,
                          float* __restrict__ cS, float* __restrict__ sS,
                          float* __restrict__ cT, float* __restrict__ sT)
{
    int idx = blockIdx.x * blockDim.x + threadIdx.x;
    if (idx < NQ * DH) {
        float f = srcf[idx];
        cS[idx] = cosf(f); sS[idx] = sinf(f);
    } else if (idx < NQ * DH + MS * DH) {
        int i = idx - NQ * DH;
        float f = tgtf[i];
        cT[i] = cosf(f); sT[i] = sinf(f);
    }
}

// ---------------- xo += P2 ----------------
__global__ void __launch_bounds__(256)
add_vec(float* __restrict__ xo, const float* __restrict__ p2)
{
    int idx = blockIdx.x * blockDim.x + threadIdx.x;
    float4 a = *(float4*)(xo + idx * 4);
    float4 b = *(const float4*)(p2 + idx * 4);
    a.x += b.x; a.y += b.y; a.z += b.z; a.w += b.w;
    *(float4*)(xo + idx * 4) = a;
}

// ---------------- launcher ----------------
extern "C" void kernel_launch(void* const* d_in, const int* in_sizes, int n_in,
                              void* d_out, int out_size)
{
    const float* x    = (const float*)d_in[0];
    const float* cond = (const float*)d_in[1];
    const float* Wq   = (const float*)d_in[2];
    const float* Wk   = (const float*)d_in[3];
    const float* Wv   = (const float*)d_in[4];
    const float* Wo   = (const float*)d_in[5];
    const float* bo   = (const float*)d_in[6];
    const float* rpe  = (const float*)d_in[7];
    const float* W1   = (const float*)d_in[8];
    const float* b1   = (const float*)d_in[9];
    const float* W2   = (const float*)d_in[10];
    const float* b2   = (const float*)d_in[11];
    const float* srcf = (const float*)d_in[12];
    const float* tgtf = (const float*)d_in[13];
    const int*   reli = (const int*)d_in[14];
    float* xo = (float*)d_out;

    float *Q, *K, *VT, *O, *Y, *P2;
    float *WqT, *WkT, *WvT, *WoT, *W1T, *W2T;
    float *cS, *sS, *cT, *sT;
    cudaGetSymbolAddress((void**)&Q, g_Q);
    cudaGetSymbolAddress((void**)&K, g_K);
    cudaGetSymbolAddress((void**)&VT, g_VT);
    cudaGetSymbolAddress((void**)&O, g_O);
    cudaGetSymbolAddress((void**)&Y, g_Y);
    cudaGetSymbolAddress((void**)&P2, g_P2);
    cudaGetSymbolAddress((void**)&WqT, g_WqT);
    cudaGetSymbolAddress((void**)&WkT, g_WkT);
    cudaGetSymbolAddress((void**)&WvT, g_WvT);
    cudaGetSymbolAddress((void**)&WoT, g_WoT);
    cudaGetSymbolAddress((void**)&W1T, g_W1T);
    cudaGetSymbolAddress((void**)&W2T, g_W2T);
    cudaGetSymbolAddress((void**)&cS, g_cosS);
    cudaGetSymbolAddress((void**)&sS, g_sinS);
    cudaGetSymbolAddress((void**)&cT, g_cosT);
    cudaGetSymbolAddress((void**)&sT, g_sinT);

    const int SM128 = (128 * 32 + 128 * 32) * 3 * 4;     // 96 KB
    const int SMFL  = 24576 * 4;                         // 96 KB

    static bool s_init = false;
    static cudaStream_t s1, s2;
    static cudaEvent_t eStart, ePrep, eWkv, eV0, eV1, eK0, eK1, eY0, eY1, eP0, eP1;
    if (!s_init) {
        cudaFuncSetAttribute(gemm_tc<0>, cudaFuncAttributeMaxDynamicSharedMemorySize, SM128);
        cudaFuncSetAttribute(gemm_tc<1>, cudaFuncAttributeMaxDynamicSharedMemorySize, SM128);
        cudaFuncSetAttribute(gemm_tc<2>, cudaFuncAttributeMaxDynamicSharedMemorySize, SM128);
        cudaFuncSetAttribute(gemm_tc<3>, cudaFuncAttributeMaxDynamicSharedMemorySize, SM128);
        cudaFuncSetAttribute(gemm_tc<4>, cudaFuncAttributeMaxDynamicSharedMemorySize, SM128);
        cudaFuncSetAttribute(flash_attn, cudaFuncAttributeMaxDynamicSharedMemorySize, SMFL);
        cudaStreamCreate(&s1);
        cudaStreamCreate(&s2);
        cudaEventCreateWithFlags(&eStart, cudaEventDisableTiming);
        cudaEventCreateWithFlags(&ePrep,  cudaEventDisableTiming);
        cudaEventCreateWithFlags(&eWkv,   cudaEventDisableTiming);
        cudaEventCreateWithFlags(&eV0, cudaEventDisableTiming);
        cudaEventCreateWithFlags(&eV1, cudaEventDisableTiming);
        cudaEventCreateWithFlags(&eK0, cudaEventDisableTiming);
        cudaEventCreateWithFlags(&eK1, cudaEventDisableTiming);
        cudaEventCreateWithFlags(&eY0, cudaEventDisableTiming);
        cudaEventCreateWithFlags(&eY1, cudaEventDisableTiming);
        cudaEventCreateWithFlags(&eP0, cudaEventDisableTiming);
        cudaEventCreateWithFlags(&eP1, cudaEventDisableTiming);
        s_init = true;
    }
    cudaEvent_t eV[2] = {eV0, eV1}, eK[2] = {eK0, eK1};
    cudaEvent_t eY[2] = {eY0, eY1}, eP[2] = {eP0, eP1};

    // ---- legal fork: eStart recorded on capturing stream 0 first ----
    cudaMemcpyAsync(xo, x, (size_t)MROWS * DIM * sizeof(float),
                    cudaMemcpyDeviceToDevice, 0);
    cudaEventRecord(eStart, 0);

    // ---- s1: Wk/Wv transpose + V projections ----
    cudaStreamWaitEvent(s1, eStart, 0);
    wtrans_all<<<1024, 256, 0, s1>>>(Wq, Wk, Wv, Wo, W1, W2,
                                     WqT, WkT, WvT, WoT, W1T, W2T, 512);
    cudaEventRecord(eWkv, s1);

    // ---- main stream: trig + remaining transposes ----
    prep_trig<<<((NQ + MS) * DH + 255) / 256, 256>>>(srcf, tgtf, cS, sS, cT, sT);
    cudaEventRecord(ePrep, 0);
    wtrans_all<<<512, 256>>>(Wq, Wk, Wv, Wo, W1, W2,
                             WqT, WkT, WvT, WoT, W1T, W2T, 0);       // Wq
    wtrans_all<<<6656, 256>>>(Wq, Wk, Wv, Wo, W1, W2,
                              WqT, WkT, WvT, WoT, W1T, W2T, 1536);   // Wo,W1,W2

    // ---- s1: V projections ----
    for (int l = 0; l < DEPTH; l++) {
        const float* wvt = WvT + (long long)l * DIM * DIM;
        float* VTl = VT + (long long)l * BATCH * DIM * JTOT;
        gemm_tc<3><<<dim3(DIM / 128, CROWS / 128), 256, SM128, s1>>>(
            cond, wvt, VTl, nullptr, nullptr,
            DIM, DIM, DIM, DIM, 1.0f, nullptr, nullptr, nullptr, nullptr);
        cudaEventRecord(eV[l], s1);
    }
    // ---- s2: K projections ----
    cudaStreamWaitEvent(s2, eWkv, 0);
    cudaStreamWaitEvent(s2, ePrep, 0);
    for (int l = 0; l < DEPTH; l++) {
        const float* wkt = WkT + (long long)l * DIM * DIM;
        const float* rpel = rpe + (long long)l * 405 * HEADS;
        float* Kl = K + (long long)l * CROWS * DIM;
        gemm_tc<2><<<dim3(DIM / 128, CROWS / 128), 256, SM128, s2>>>(
            cond, wkt, Kl, nullptr, nullptr,
            DIM, DIM, DIM, DIM, 1.0f, cT, sT, rpel, reli);
        cudaEventRecord(eK[l], s2);
    }

    // ---- main stream: residual chain with split-K FFN2 ----
    for (int l = 0; l < DEPTH; l++) {
        const float* wqt = WqT + (long long)l * DIM * DIM;
        const float* wot = WoT + (long long)l * DIM * DIM;
        const float* bol = bo + l * DIM;
        const float* w1t = W1T + (long long)l * DIM * 2 * FFH;
        const float* b1l = b1 + (long long)l * (2 * FFH);
        const float* w2t = W2T + (long long)l * DIM * FFH;
        const float* b2l = b2 + l * DIM;
        const float* Kl  = K  + (long long)l * CROWS * DIM;
        const float* VTl = VT + (long long)l * BATCH * DIM * JTOT;

        gemm_tc<1><<<dim3(DIM / 128, MROWS / 128), 256, SM128>>>(
            xo, wqt, Q, nullptr, nullptr,
            DIM, DIM, DIM, DIM, 1.0f, cS, sS, nullptr, nullptr);

        cudaStreamWaitEvent(0, eV[l], 0);
        cudaStreamWaitEvent(0, eK[l], 0);

        flash_attn<<<dim3(NQ / 128, BATCH * HEADS), 256, SMFL>>>(Q, Kl, VTl, O);

        gemm_tc<0><<<dim3(DIM / 128, MROWS / 128), 256, SM128>>>(
            O, wot, xo, xo, bol,
            DIM, DIM, DIM, DIM, 1.0f, nullptr, nullptr, nullptr, nullptr);

        // Y = GEGLU(x @ W1 + b1)
        gemm_tc<4><<<dim3(2 * FFH / 128, MROWS / 128), 256, SM128>>>(
            xo, w1t, Y, nullptr, b1l,
            DIM, DIM, DIM, FFH, 1.0f, nullptr, nullptr, nullptr, nullptr);
        cudaEventRecord(eY[l], 0);

        // FFN2b on s1: P2 = Y[:,2048:] @ W2T rows, k in [2048,4096)
        cudaStreamWaitEvent(s1, eY[l], 0);
        gemm_tc<0><<<dim3(DIM / 128, MROWS / 128), 256, SM128, s1>>>(
            Y + 2048, w2t + 2048, P2, nullptr, nullptr,
            FFH / 2, FFH, FFH, DIM, 1.0f, nullptr, nullptr, nullptr, nullptr);
        cudaEventRecord(eP[l], s1);

        // FFN2a on main: xo = xo + Y[:, :2048] @ W2T + b2
        gemm_tc<0><<<dim3(DIM / 128, MROWS / 128), 256, SM128>>>(
            Y, w2t, xo, xo, b2l,
            FFH / 2, FFH, FFH, DIM, 1.0f, nullptr, nullptr, nullptr, nullptr);

        // xo += P2
        cudaStreamWaitEvent(0, eP[l], 0);
        add_vec<<<(MROWS * DIM / 4) / 256, 256>>>(xo, P2);
    }
}

// round 17
// speedup vs baseline: 1.2161x; 1.0017x over previous
#include <cuda_runtime.h>
#include <math.h>
#include <stdint.h>

// ---------------- problem constants ----------------
#define DEPTH 2
#define DIM   1024
#define HEADS 16
#define DH    64
#define BATCH 8
#define NQ    256
#define JTOT  1088
#define MS    1024
#define MROWS (BATCH*NQ)    // 2048
#define CROWS (BATCH*JTOT)  // 8704
#define FFH   4096
#define SCALE 0.125f
#define NJT   17            // JTOT / 64

// ---------------- scratch ----------------
__device__ float g_Q[MROWS * DIM];
__device__ float g_K[(long)DEPTH * CROWS * DIM];
__device__ float g_VT[(long)DEPTH * BATCH * DIM * JTOT];
__device__ float g_O[MROWS * DIM];
__device__ float g_Y[(long)MROWS * FFH];
__device__ float g_P2[MROWS * DIM];
__device__ float g_WqT[(long)DEPTH * DIM * DIM];
__device__ float g_WkT[(long)DEPTH * DIM * DIM];
__device__ float g_WvT[(long)DEPTH * DIM * DIM];
__device__ float g_WoT[(long)DEPTH * DIM * DIM];
__device__ float g_W1T[(long)DEPTH * 2 * FFH * DIM];   // interleaved rows
__device__ float g_W2T[(long)DEPTH * DIM * FFH];
__device__ float g_cosS[NQ * DH];
__device__ float g_sinS[NQ * DH];
__device__ float g_cosT[MS * DH];
__device__ float g_sinT[MS * DH];

// ---------------- ptx helpers ----------------
__device__ __forceinline__ float tf32r(float f) {
    uint32_t u;
    asm("cvt.rna.tf32.f32 %0, %1;" : "=r"(u) : "f"(f));
    return __uint_as_float(u);
}
__device__ __forceinline__ void ldsm4(uint32_t* r, uint32_t a) {
    asm volatile("ldmatrix.sync.aligned.m8n8.x4.shared.b16 {%0,%1,%2,%3}, [%4];"
                 : "=r"(r[0]), "=r"(r[1]), "=r"(r[2]), "=r"(r[3]) : "r"(a));
}
__device__ __forceinline__ void ldsm2(uint32_t* r, uint32_t a) {
    asm volatile("ldmatrix.sync.aligned.m8n8.x2.shared.b16 {%0,%1}, [%2];"
                 : "=r"(r[0]), "=r"(r[1]) : "r"(a));
}
__device__ __forceinline__ void mma_tf32(float* c, const uint32_t* a, const uint32_t* b) {
    asm volatile(
        "mma.sync.aligned.m16n8k8.row.col.f32.tf32.tf32.f32 "
        "{%0,%1,%2,%3}, {%4,%5,%6,%7}, {%8,%9}, {%0,%1,%2,%3};"
        : "+f"(c[0]), "+f"(c[1]), "+f"(c[2]), "+f"(c[3])
        : "r"(a[0]), "r"(a[1]), "r"(a[2]), "r"(a[3]), "r"(b[0]), "r"(b[1]));
}
__device__ __forceinline__ void mma_tf32b(float* c, const uint32_t* a, uint32_t b0, uint32_t b1) {
    asm volatile(
        "mma.sync.aligned.m16n8k8.row.col.f32.tf32.tf32.f32 "
        "{%0,%1,%2,%3}, {%4,%5,%6,%7}, {%8,%9}, {%0,%1,%2,%3};"
        : "+f"(c[0]), "+f"(c[1]), "+f"(c[2]), "+f"(c[3])
        : "r"(a[0]), "r"(a[1]), "r"(a[2]), "r"(a[3]), "r"(b0), "r"(b1));
}
__device__ __forceinline__ void cpa16(uint32_t d, const float* s) {
    asm volatile("cp.async.cg.shared.global [%0], [%1], 16;" :: "r"(d), "l"(s));
}

// ---- tf32 GEMM; EPI: 0=plain, 1=rope_q, 2=rpe+rope_k, 3=V^T, 4=GEGLU pairs --
template <int EPI>
__global__ void __launch_bounds__(256, 2)
gemm_tc(const float* __restrict__ A, const float* __restrict__ B,
        float* __restrict__ C, const float* __restrict__ Cadd,
        const float* __restrict__ bias,
        int K, int lda, int ldb, int ldc, float alpha,
        const float* __restrict__ ctab, const float* __restrict__ stab,
        const float* __restrict__ rpe_l, const int* __restrict__ rel_idx)
{
    constexpr int BM = 128, BN = 128;
    constexpr int ASZ = BM * 32, STF = ASZ + BN * 32;
    constexpr int WTM = 64, WTN = 32;
    constexpr int MI = 4, NI = 4;

    extern __shared__ float smdyn[];
    const uint32_t sb = (uint32_t)__cvta_generic_to_shared(smdyn);

    const int tid = threadIdx.x, warp = tid >> 5, lane = tid & 31;
    const int wm = warp >> 2, wn = warp & 3;
    const int g = lane >> 2, t = lane & 3;
    const int bm0 = blockIdx.y * BM, bn0 = blockIdx.x * BN;

    const int arow = tid >> 3;
    const int cc   = tid & 7;

    const float* Ag = A + (long long)(bm0 + arow) * lda + cc * 4;
    const float* Bg = B + (long long)(bn0 + arow) * ldb + cc * 4;

    const int KT = K >> 5;

    auto load_stage = [&](int s, int kt) {
        if (kt < KT) {
            const int k0 = kt << 5;
            uint32_t ab = sb + (uint32_t)(s * STF) * 4u;
            uint32_t bb = ab + (uint32_t)ASZ * 4u;
            #pragma unroll
            for (int i = 0; i < 4; i++) {
                int r = arow + i * 32;
                uint32_t sw = (uint32_t)((cc ^ (r & 7)) << 4);
                cpa16(ab + r * 128 + sw, Ag + (long long)i * 32 * lda + k0);
                cpa16(bb + r * 128 + sw, Bg + (long long)i * 32 * ldb + k0);
            }
        }
        asm volatile("cp.async.commit_group;");
    };

    float acc[MI][NI][4];
    #pragma unroll
    for (int mi = 0; mi < MI; mi++)
        #pragma unroll
        for (int ni = 0; ni < NI; ni++)
            #pragma unroll
            for (int q = 0; q < 4; q++) acc[mi][ni][q] = 0.f;

    const int a_r  = lane & 15;
    const int a_kc = lane >> 4;
    const int b_r  = lane & 7;
    const int b_kc = (lane >> 3) & 1;

    load_stage(0, 0);
    load_stage(1, 1);

    for (int kt = 0; kt < KT; kt++) {
        asm volatile("cp.async.wait_group 1;");
        __syncthreads();
        load_stage((kt + 2) % 3, kt + 2);

        const int s = kt % 3;
        const uint32_t ab = sb + (uint32_t)(s * STF) * 4u;
        const uint32_t bb = ab + (uint32_t)ASZ * 4u;

        #pragma unroll
        for (int kk = 0; kk < 4; kk++) {
            uint32_t af[MI][4], bf[NI][2];
            #pragma unroll
            for (int mi = 0; mi < MI; mi++) {
                int r = wm * WTM + mi * 16 + a_r;
                int kc = kk * 2 + a_kc;
                ldsm4(af[mi], ab + r * 128 + ((kc ^ (r & 7)) << 4));
            }
            #pragma unroll
            for (int ni = 0; ni < NI; ni++) {
                int r = wn * WTN + ni * 8 + b_r;
                int kc = kk * 2 + b_kc;
                ldsm2(bf[ni], bb + r * 128 + ((kc ^ (r & 7)) << 4));
            }
            #pragma unroll
            for (int mi = 0; mi < MI; mi++)
                #pragma unroll
                for (int ni = 0; ni < NI; ni++)
                    mma_tf32(acc[mi][ni], af[mi], bf[ni]);
        }
    }

    #pragma unroll
    for (int mi = 0; mi < MI; mi++) {
        int row0 = bm0 + wm * WTM + mi * 16 + g;
        int jA = 0, jB = 0, bA = 0, bB = 0;
        if (EPI == 2 || EPI == 3) {
            bA = row0 / JTOT;       jA = row0 - bA * JTOT;
            bB = (row0 + 8) / JTOT; jB = (row0 + 8) - bB * JTOT;
        }
        #pragma unroll
        for (int ni = 0; ni < NI; ni++) {
            int col = bn0 + wn * WTN + ni * 8 + 2 * t;
            float v0 = alpha * acc[mi][ni][0];
            float v1 = alpha * acc[mi][ni][1];
            float v2 = alpha * acc[mi][ni][2];
            float v3 = alpha * acc[mi][ni][3];
            if (bias && EPI != 4) {
                float b0 = bias[col], b1 = bias[col + 1];
                v0 += b0; v1 += b1; v2 += b0; v3 += b1;
            }
            if (Cadd) {
                const float2 c0 = *(const float2*)(Cadd + (long long)row0 * ldc + col);
                const float2 c1 = *(const float2*)(Cadd + (long long)(row0 + 8) * ldc + col);
                v0 += c0.x; v1 += c0.y; v2 += c1.x; v3 += c1.y;
            }
            if (EPI == 1) {
                int d = col & (DH - 1);
                int nA = row0 & (NQ - 1), nB = (row0 + 8) & (NQ - 1);
                float cA0 = ctab[nA * DH + d],     sA0 = stab[nA * DH + d];
                float cA1 = ctab[nA * DH + d + 1], sA1 = stab[nA * DH + d + 1];
                float cB0 = ctab[nB * DH + d],     sB0 = stab[nB * DH + d];
                float cB1 = ctab[nB * DH + d + 1], sB1 = stab[nB * DH + d + 1];
                float o0 = (v0 * cA0 - v1 * sA0) * SCALE;
                float o1 = (v1 * cA1 + v0 * sA1) * SCALE;
                float o2 = (v2 * cB0 - v3 * sB0) * SCALE;
                float o3 = (v3 * cB1 + v2 * sB1) * SCALE;
                v0 = o0; v1 = o1; v2 = o2; v3 = o3;
            }
            if (EPI == 2) {
                int d = col & (DH - 1);
                int h = col >> 6;
                if (jA < MS) {
                    float bb2 = rpe_l[rel_idx[jA >> 8] * HEADS + h];
                    float k0 = v0 + bb2, k1 = v1 + bb2;
                    float c0 = ctab[jA * DH + d],     s0 = stab[jA * DH + d];
                    float c1 = ctab[jA * DH + d + 1], s1 = stab[jA * DH + d + 1];
                    v0 = k0 * c0 - k1 * s0;
                    v1 = k1 * c1 + k0 * s1;
                }
                if (jB < MS) {
                    float bb2 = rpe_l[rel_idx[jB >> 8] * HEADS + h];
                    float k0 = v2 + bb2, k1 = v3 + bb2;
                    float c0 = ctab[jB * DH + d],     s0 = stab[jB * DH + d];
                    float c1 = ctab[jB * DH + d + 1], s1 = stab[jB * DH + d + 1];
                    v2 = k0 * c0 - k1 * s0;
                    v3 = k1 * c1 + k0 * s1;
                }
            }
            if (EPI == 3) {
                float* vtA = C + (long long)bA * DIM * JTOT + (long long)col * JTOT + jA;
                float* vtB = C + (long long)bB * DIM * JTOT + (long long)col * JTOT + jB;
                vtA[0]    = tf32r(v0);
                vtA[JTOT] = tf32r(v1);
                vtB[0]    = tf32r(v2);
                vtB[JTOT] = tf32r(v3);
            } else if (EPI == 4) {
                int oc = col >> 1;
                float ba = bias[oc], bg = bias[FFH + oc];
                float a0 = v0 + ba, g0 = v1 + bg;
                float a1 = v2 + ba, g1 = v3 + bg;
                float y0 = a0 * (0.5f * g0 * (1.0f + erff(g0 * 0.70710678118654752f)));
                float y1 = a1 * (0.5f * g1 * (1.0f + erff(g1 * 0.70710678118654752f)));
                C[(long long)row0 * ldc + oc]       = y0;
                C[(long long)(row0 + 8) * ldc + oc] = y1;
            } else {
                *(float2*)(C + (long long)row0 * ldc + col) = make_float2(v0, v1);
                *(float2*)(C + (long long)(row0 + 8) * ldc + col) = make_float2(v2, v3);
            }
        }
    }
}

// ---------------- flash attention ----------------
__global__ void __launch_bounds__(256, 2)
flash_attn(const float* __restrict__ Q, const float* __restrict__ K,
           const float* __restrict__ VT, float* __restrict__ O)
{
    extern __shared__ float sm[];
    const uint32_t sb = (uint32_t)__cvta_generic_to_shared(sm);
    const uint32_t pq = sb;
    const uint32_t kb = sb + 8192u * 4u;
    const uint32_t vb = sb + 16384u * 4u;

    const int tid = threadIdx.x, warp = tid >> 5, lane = tid & 31;
    const int g = lane >> 2, t = lane & 3;
    const int m0 = blockIdx.x * 128;
    const int z = blockIdx.y;
    const int b = z >> 4, h = z & 15;

    const float* Qg = Q + ((long long)(b * NQ + m0)) * DIM + h * DH;
    const float* Kg = K + (long long)b * JTOT * DIM + h * DH;
    const float* Vg = VT + (long long)b * DIM * JTOT + (long long)h * DH * JTOT;
    float* Og = O + ((long long)(b * NQ + m0)) * DIM + h * DH;

    auto load_kv_body = [&](int s, int jt) {
        #pragma unroll
        for (int i = 0; i < 4; i++) {
            int idx = tid + i * 256;
            int cc = idx & 7, r = (idx >> 3) & 63, hf = idx >> 9;
            uint32_t off = (uint32_t)(s * 4096 + (hf * 64 + r) * 32) * 4u + ((cc ^ (r & 7)) << 4);
            cpa16(kb + off, Kg + (long long)(jt * 64 + r) * DIM + hf * 32 + cc * 4);
            cpa16(vb + off, Vg + (long long)r * JTOT + jt * 64 + hf * 32 + cc * 4);
        }
    };

    #pragma unroll
    for (int i = 0; i < 8; i++) {
        int idx = tid + i * 256;
        int cc = idx & 7, r = (idx >> 3) & 127, hf = idx >> 10;
        cpa16(pq + (uint32_t)(hf * 128 + r) * 128u + ((cc ^ (r & 7)) << 4),
              Qg + (long long)r * DIM + hf * 32 + cc * 4);
    }
    load_kv_body(0, 0);
    asm volatile("cp.async.commit_group;");
    load_kv_body(1, 1);
    asm volatile("cp.async.commit_group;");

    float acco[8][4];
    #pragma unroll
    for (int ni = 0; ni < 8; ni++)
        #pragma unroll
        for (int q = 0; q < 4; q++) acco[ni][q] = 0.f;
    float mr0 = -INFINITY, mr1 = -INFINITY, l0 = 0.f, l1 = 0.f;

    const int fr = lane & 15;
    const int fc = lane >> 4;

    asm volatile("cp.async.wait_group 1;");
    __syncthreads();

    uint32_t qf[8][4];
    #pragma unroll
    for (int kk = 0; kk < 8; kk++) {
        const int hf = kk >> 2;
        const int kc = (kk & 3) * 2 + fc;
        const int r = warp * 16 + fr;
        ldsm4(qf[kk], pq + (uint32_t)(hf * 128 + r) * 128u + ((kc ^ (r & 7)) << 4));
    }

    for (int jt = 0; jt < NJT; jt++) {
        const int s = jt & 1;
        if (jt > 0) {
            asm volatile("cp.async.wait_group 1;");
            __syncthreads();
        }

        float accs[8][4];
        #pragma unroll
        for (int ni = 0; ni < 8; ni++)
            #pragma unroll
            for (int q = 0; q < 4; q++) accs[ni][q] = 0.f;

        #pragma unroll
        for (int kk = 0; kk < 8; kk++) {
            const int hf = kk >> 2;
            const int kc = (kk & 3) * 2 + fc;
            #pragma unroll
            for (int p = 0; p < 4; p++) {
                int r = p * 16 + fr;
                uint32_t bf[4];
                ldsm4(bf, kb + (uint32_t)(s * 4096 + (hf * 64 + r) * 32) * 4u + ((kc ^ (r & 7)) << 4));
                mma_tf32b(accs[2 * p],     qf[kk], bf[0], bf[2]);
                mma_tf32b(accs[2 * p + 1], qf[kk], bf[1], bf[3]);
            }
        }

        float vm0 = -INFINITY, vm1 = -INFINITY;
        #pragma unroll
        for (int ni = 0; ni < 8; ni++) {
            vm0 = fmaxf(vm0, fmaxf(accs[ni][0], accs[ni][1]));
            vm1 = fmaxf(vm1, fmaxf(accs[ni][2], accs[ni][3]));
        }
        vm0 = fmaxf(vm0, __shfl_xor_sync(0xffffffffu, vm0, 1));
        vm0 = fmaxf(vm0, __shfl_xor_sync(0xffffffffu, vm0, 2));
        vm1 = fmaxf(vm1, __shfl_xor_sync(0xffffffffu, vm1, 1));
        vm1 = fmaxf(vm1, __shfl_xor_sync(0xffffffffu, vm1, 2));
        float mn0 = fmaxf(mr0, vm0), mn1 = fmaxf(mr1, vm1);
        float sc0 = __expf(mr0 - mn0), sc1 = __expf(mr1 - mn1);

        float ps0 = 0.f, ps1 = 0.f;
        #pragma unroll
        for (int ni = 0; ni < 8; ni++) {
            accs[ni][0] = tf32r(__expf(accs[ni][0] - mn0));
            accs[ni][1] = tf32r(__expf(accs[ni][1] - mn0));
            accs[ni][2] = tf32r(__expf(accs[ni][2] - mn1));
            accs[ni][3] = tf32r(__expf(accs[ni][3] - mn1));
            ps0 += accs[ni][0] + accs[ni][1];
            ps1 += accs[ni][2] + accs[ni][3];
        }
        ps0 += __shfl_xor_sync(0xffffffffu, ps0, 1);
        ps0 += __shfl_xor_sync(0xffffffffu, ps0, 2);
        ps1 += __shfl_xor_sync(0xffffffffu, ps1, 1);
        ps1 += __shfl_xor_sync(0xffffffffu, ps1, 2);
        l0 = l0 * sc0 + ps0;
        l1 = l1 * sc1 + ps1;
        mr0 = mn0; mr1 = mn1;
        #pragma unroll
        for (int ni = 0; ni < 8; ni++) {
            acco[ni][0] *= sc0; acco[ni][1] *= sc0;
            acco[ni][2] *= sc1; acco[ni][3] *= sc1;
        }

        const int r0 = warp * 16 + g, r1 = r0 + 8;
        #pragma unroll
        for (int ni = 0; ni < 8; ni++) {
            int hf = ni >> 2;
            int cc = (ni & 3) * 2 + (t >> 1);
            uint32_t ofs = (uint32_t)((t & 1) * 8);
            uint32_t a0 = pq + (uint32_t)(hf * 128 + r0) * 128u + ((cc ^ (r0 & 7)) << 4) + ofs;
            uint32_t a1 = pq + (uint32_t)(hf * 128 + r1) * 128u + ((cc ^ (r1 & 7)) << 4) + ofs;
            asm volatile("st.shared.v2.f32 [%0], {%1,%2};" :: "r"(a0), "f"(accs[ni][0]), "f"(accs[ni][1]));
            asm volatile("st.shared.v2.f32 [%0], {%1,%2};" :: "r"(a1), "f"(accs[ni][2]), "f"(accs[ni][3]));
        }
        __syncwarp();

        #pragma unroll
        for (int kk = 0; kk < 8; kk++) {
            const int hf = kk >> 2;
            const int kc = (kk & 3) * 2 + fc;
            uint32_t a[4];
            {
                int r = warp * 16 + fr;
                ldsm4(a, pq + (uint32_t)(hf * 128 + r) * 128u + ((kc ^ (r & 7)) << 4));
            }
            #pragma unroll
            for (int p = 0; p < 4; p++) {
                int r = p * 16 + fr;
                uint32_t bf[4];
                ldsm4(bf, vb + (uint32_t)(s * 4096 + (hf * 64 + r) * 32) * 4u + ((kc ^ (r & 7)) << 4));
                mma_tf32b(acco[2 * p],     a, bf[0], bf[2]);
                mma_tf32b(acco[2 * p + 1], a, bf[1], bf[3]);
            }
        }
        __syncthreads();

        if (jt + 2 < NJT) load_kv_body(s, jt + 2);
        asm volatile("cp.async.commit_group;");
    }

    float inv0 = 1.f / l0, inv1 = 1.f / l1;
    const int r0 = warp * 16 + g, r1 = r0 + 8;
    #pragma unroll
    for (int ni = 0; ni < 8; ni++) {
        int col = ni * 8 + 2 * t;
        *(float2*)(Og + (long long)r0 * DIM + col) =
            make_float2(acco[ni][0] * inv0, acco[ni][1] * inv0);
        *(float2*)(Og + (long long)r1 * DIM + col) =
            make_float2(acco[ni][2] * inv1, acco[ni][3] * inv1);
    }
}

// ---- batched weight transpose: 64x64 tiles, float4 I/O, tile_base param ----
__global__ void __launch_bounds__(256)
wtrans_all(const float* __restrict__ Wq, const float* __restrict__ Wk,
           const float* __restrict__ Wv, const float* __restrict__ Wo,
           const float* __restrict__ W1, const float* __restrict__ W2,
           float* __restrict__ WqT, float* __restrict__ WkT,
           float* __restrict__ WvT, float* __restrict__ WoT,
           float* __restrict__ W1T, float* __restrict__ W2T,
           int tile_base)
{
    __shared__ float tb[64][65];
    const float* ins[6] = {Wq, Wk, Wv, Wo, W1, W2};
    float* outs[6] = {WqT, WkT, WvT, WoT, W1T, W2T};
    const int Rs[6] = {DIM, DIM, DIM, DIM, DIM, FFH};
    const int Cs[6] = {DIM, DIM, DIM, DIM, 2 * FFH, DIM};

    int tile = blockIdx.x + tile_base, job = 0;
    #pragma unroll
    for (int j2 = 0; j2 < 6; j2++) {
        int nt = DEPTH * (Rs[j2] / 64) * (Cs[j2] / 64);
        if (tile >= nt) { tile -= nt; job++; }
        else break;
    }
    const int R = Rs[job], C = Cs[job];
    const int tpz = (R / 64) * (C / 64);
    const int zdx = tile / tpz;
    const int rem = tile - zdx * tpz;
    const int ty4 = rem / (C / 64), tx4 = rem - ty4 * (C / 64);
    const float* in = ins[job] + (long long)zdx * R * C;
    float* out = outs[job] + (long long)zdx * R * C;

    const int c0 = tx4 * 64, r0 = ty4 * 64;
    const int tx = threadIdx.x & 15, ty = threadIdx.x >> 4;

    #pragma unroll
    for (int i = 0; i < 4; i++) {
        int r = ty + i * 16;
        float4 v = *(const float4*)(in + (long long)(r0 + r) * C + c0 + tx * 4);
        tb[r][tx * 4 + 0] = v.x;
        tb[r][tx * 4 + 1] = v.y;
        tb[r][tx * 4 + 2] = v.z;
        tb[r][tx * 4 + 3] = v.w;
    }
    __syncthreads();

    #pragma unroll
    for (int i = 0; i < 4; i++) {
        int c = c0 + ty + i * 16;
        int sc = ty + i * 16;
        long long orow = c;
        if (job == 4) orow = (c < FFH) ? (2LL * c) : (2LL * (c - FFH) + 1);
        float4 w;
        w.x = tf32r(tb[tx * 4 + 0][sc]);
        w.y = tf32r(tb[tx * 4 + 1][sc]);
        w.z = tf32r(tb[tx * 4 + 2][sc]);
        w.w = tf32r(tb[tx * 4 + 3][sc]);
        *(float4*)(out + orow * R + r0 + tx * 4) = w;
    }
}

// ---------------- cos/sin tables ----------------
__global__ void prep_trig(const float* __restrict__ srcf, const float* __restrict__ tgtf,
                          float* __restrict__ cS, float* __restrict__ sS,
                          float* __restrict__ cT, float* __restrict__ sT)
{
    int idx = blockIdx.x * blockDim.x + threadIdx.x;
    if (idx < NQ * DH) {
        float f = srcf[idx];
        cS[idx] = cosf(f); sS[idx] = sinf(f);
    } else if (idx < NQ * DH + MS * DH) {
        int i = idx - NQ * DH;
        float f = tgtf[i];
        cT[i] = cosf(f); sT[i] = sinf(f);
    }
}

// ---------------- xo += P2 ----------------
__global__ void __launch_bounds__(256)
add_vec(float* __restrict__ xo, const float* __restrict__ p2)
{
    int idx = blockIdx.x * blockDim.x + threadIdx.x;
    float4 a = *(float4*)(xo + idx * 4);
    float4 b = *(const float4*)(p2 + idx * 4);
    a.x += b.x; a.y += b.y; a.z += b.z; a.w += b.w;
    *(float4*)(xo + idx * 4) = a;
}

// ---------------- launcher ----------------
extern "C" void kernel_launch(void* const* d_in, const int* in_sizes, int n_in,
                              void* d_out, int out_size)
{
    const float* x    = (const float*)d_in[0];
    const float* cond = (const float*)d_in[1];
    const float* Wq   = (const float*)d_in[2];
    const float* Wk   = (const float*)d_in[3];
    const float* Wv   = (const float*)d_in[4];
    const float* Wo   = (const float*)d_in[5];
    const float* bo   = (const float*)d_in[6];
    const float* rpe  = (const float*)d_in[7];
    const float* W1   = (const float*)d_in[8];
    const float* b1   = (const float*)d_in[9];
    const float* W2   = (const float*)d_in[10];
    const float* b2   = (const float*)d_in[11];
    const float* srcf = (const float*)d_in[12];
    const float* tgtf = (const float*)d_in[13];
    const int*   reli = (const int*)d_in[14];
    float* xo = (float*)d_out;

    float *Q, *K, *VT, *O, *Y, *P2;
    float *WqT, *WkT, *WvT, *WoT, *W1T, *W2T;
    float *cS, *sS, *cT, *sT;
    cudaGetSymbolAddress((void**)&Q, g_Q);
    cudaGetSymbolAddress((void**)&K, g_K);
    cudaGetSymbolAddress((void**)&VT, g_VT);
    cudaGetSymbolAddress((void**)&O, g_O);
    cudaGetSymbolAddress((void**)&Y, g_Y);
    cudaGetSymbolAddress((void**)&P2, g_P2);
    cudaGetSymbolAddress((void**)&WqT, g_WqT);
    cudaGetSymbolAddress((void**)&WkT, g_WkT);
    cudaGetSymbolAddress((void**)&WvT, g_WvT);
    cudaGetSymbolAddress((void**)&WoT, g_WoT);
    cudaGetSymbolAddress((void**)&W1T, g_W1T);
    cudaGetSymbolAddress((void**)&W2T, g_W2T);
    cudaGetSymbolAddress((void**)&cS, g_cosS);
    cudaGetSymbolAddress((void**)&sS, g_sinS);
    cudaGetSymbolAddress((void**)&cT, g_cosT);
    cudaGetSymbolAddress((void**)&sT, g_sinT);

    const int SM128 = (128 * 32 + 128 * 32) * 3 * 4;     // 96 KB
    const int SMFL  = 24576 * 4;                         // 96 KB

    static bool s_init = false;
    static cudaStream_t s1, s2;
    static cudaEvent_t eStart, ePrep, eWkv, eV0, eV1, eK0, eK1, eY0, eY1, eP0, eP1;
    if (!s_init) {
        cudaFuncSetAttribute(gemm_tc<0>, cudaFuncAttributeMaxDynamicSharedMemorySize, SM128);
        cudaFuncSetAttribute(gemm_tc<1>, cudaFuncAttributeMaxDynamicSharedMemorySize, SM128);
        cudaFuncSetAttribute(gemm_tc<2>, cudaFuncAttributeMaxDynamicSharedMemorySize, SM128);
        cudaFuncSetAttribute(gemm_tc<3>, cudaFuncAttributeMaxDynamicSharedMemorySize, SM128);
        cudaFuncSetAttribute(gemm_tc<4>, cudaFuncAttributeMaxDynamicSharedMemorySize, SM128);
        cudaFuncSetAttribute(flash_attn, cudaFuncAttributeMaxDynamicSharedMemorySize, SMFL);
        cudaStreamCreate(&s1);
        cudaStreamCreate(&s2);
        cudaEventCreateWithFlags(&eStart, cudaEventDisableTiming);
        cudaEventCreateWithFlags(&ePrep,  cudaEventDisableTiming);
        cudaEventCreateWithFlags(&eWkv,   cudaEventDisableTiming);
        cudaEventCreateWithFlags(&eV0, cudaEventDisableTiming);
        cudaEventCreateWithFlags(&eV1, cudaEventDisableTiming);
        cudaEventCreateWithFlags(&eK0, cudaEventDisableTiming);
        cudaEventCreateWithFlags(&eK1, cudaEventDisableTiming);
        cudaEventCreateWithFlags(&eY0, cudaEventDisableTiming);
        cudaEventCreateWithFlags(&eY1, cudaEventDisableTiming);
        cudaEventCreateWithFlags(&eP0, cudaEventDisableTiming);
        cudaEventCreateWithFlags(&eP1, cudaEventDisableTiming);
        s_init = true;
    }
    cudaEvent_t eV[2] = {eV0, eV1}, eK[2] = {eK0, eK1};
    cudaEvent_t eY[2] = {eY0, eY1}, eP[2] = {eP0, eP1};

    // ---- legal fork ----
    cudaMemcpyAsync(xo, x, (size_t)MROWS * DIM * sizeof(float),
                    cudaMemcpyDeviceToDevice, 0);
    cudaEventRecord(eStart, 0);

    // ---- s1: Wk/Wv transpose ----
    cudaStreamWaitEvent(s1, eStart, 0);
    wtrans_all<<<1024, 256, 0, s1>>>(Wq, Wk, Wv, Wo, W1, W2,
                                     WqT, WkT, WvT, WoT, W1T, W2T, 512);
    cudaEventRecord(eWkv, s1);

    // ---- main: trig + Wq transpose + Q(l0) hoisted before the big transpose ----
    prep_trig<<<((NQ + MS) * DH + 255) / 256, 256>>>(srcf, tgtf, cS, sS, cT, sT);
    cudaEventRecord(ePrep, 0);
    wtrans_all<<<512, 256>>>(Wq, Wk, Wv, Wo, W1, W2,
                             WqT, WkT, WvT, WoT, W1T, W2T, 0);       // Wq
    gemm_tc<1><<<dim3(DIM / 128, MROWS / 128), 256, SM128>>>(
        xo, WqT, Q, nullptr, nullptr,
        DIM, DIM, DIM, DIM, 1.0f, cS, sS, nullptr, nullptr);         // Q(l0)
    wtrans_all<<<6656, 256>>>(Wq, Wk, Wv, Wo, W1, W2,
                              WqT, WkT, WvT, WoT, W1T, W2T, 1536);   // Wo,W1,W2

    // ---- s2: K projections (need WkT + trig) ----
    cudaStreamWaitEvent(s2, eWkv, 0);
    cudaStreamWaitEvent(s2, ePrep, 0);
    for (int l = 0; l < DEPTH; l++) {
        const float* wkt = WkT + (long long)l * DIM * DIM;
        const float* rpel = rpe + (long long)l * 405 * HEADS;
        float* Kl = K + (long long)l * CROWS * DIM;
        gemm_tc<2><<<dim3(DIM / 128, CROWS / 128), 256, SM128, s2>>>(
            cond, wkt, Kl, nullptr, nullptr,
            DIM, DIM, DIM, DIM, 1.0f, cT, sT, rpel, reli);
        cudaEventRecord(eK[l], s2);
    }

    // ---- s1: V0; then V1 gated behind K0 (keeps V1 off the critical window) ----
    {
        gemm_tc<3><<<dim3(DIM / 128, CROWS / 128), 256, SM128, s1>>>(
            cond, WvT, VT, nullptr, nullptr,
            DIM, DIM, DIM, DIM, 1.0f, nullptr, nullptr, nullptr, nullptr);
        cudaEventRecord(eV0, s1);
        cudaStreamWaitEvent(s1, eK0, 0);
        gemm_tc<3><<<dim3(DIM / 128, CROWS / 128), 256, SM128, s1>>>(
            cond, WvT + (long long)DIM * DIM,
            VT + (long long)BATCH * DIM * JTOT, nullptr, nullptr,
            DIM, DIM, DIM, DIM, 1.0f, nullptr, nullptr, nullptr, nullptr);
        cudaEventRecord(eV1, s1);
    }

    // ---- main stream: residual chain ----
    for (int l = 0; l < DEPTH; l++) {
        const float* wqt = WqT + (long long)l * DIM * DIM;
        const float* wot = WoT + (long long)l * DIM * DIM;
        const float* bol = bo + l * DIM;
        const float* w1t = W1T + (long long)l * DIM * 2 * FFH;
        const float* b1l = b1 + (long long)l * (2 * FFH);
        const float* w2t = W2T + (long long)l * DIM * FFH;
        const float* b2l = b2 + l * DIM;
        const float* Kl  = K  + (long long)l * CROWS * DIM;
        const float* VTl = VT + (long long)l * BATCH * DIM * JTOT;

        if (l > 0) {
            gemm_tc<1><<<dim3(DIM / 128, MROWS / 128), 256, SM128>>>(
                xo, wqt, Q, nullptr, nullptr,
                DIM, DIM, DIM, DIM, 1.0f, cS, sS, nullptr, nullptr);
        }

        cudaStreamWaitEvent(0, eV[l], 0);
        cudaStreamWaitEvent(0, eK[l], 0);

        flash_attn<<<dim3(NQ / 128, BATCH * HEADS), 256, SMFL>>>(Q, Kl, VTl, O);

        gemm_tc<0><<<dim3(DIM / 128, MROWS / 128), 256, SM128>>>(
            O, wot, xo, xo, bol,
            DIM, DIM, DIM, DIM, 1.0f, nullptr, nullptr, nullptr, nullptr);

        // Y = GEGLU(x @ W1 + b1)
        gemm_tc<4><<<dim3(2 * FFH / 128, MROWS / 128), 256, SM128>>>(
            xo, w1t, Y, nullptr, b1l,
            DIM, DIM, DIM, FFH, 1.0f, nullptr, nullptr, nullptr, nullptr);
        cudaEventRecord(eY[l], 0);

        // FFN2b on s1: P2 = Y[:,2048:] @ W2T rows, k in [2048,4096)
        cudaStreamWaitEvent(s1, eY[l], 0);
        gemm_tc<0><<<dim3(DIM / 128, MROWS / 128), 256, SM128, s1>>>(
            Y + 2048, w2t + 2048, P2, nullptr, nullptr,
            FFH / 2, FFH, FFH, DIM, 1.0f, nullptr, nullptr, nullptr, nullptr);
        cudaEventRecord(eP[l], s1);

        // FFN2a on main: xo = xo + Y[:, :2048] @ W2T + b2
        gemm_tc<0><<<dim3(DIM / 128, MROWS / 128), 256, SM128>>>(
            Y, w2t, xo, xo, b2l,
            FFH / 2, FFH, FFH, DIM, 1.0f, nullptr, nullptr, nullptr, nullptr);

        // xo += P2
        cudaStreamWaitEvent(0, eP[l], 0);
        add_vec<<<(MROWS * DIM / 4) / 256, 256>>>(xo, P2);
    }
}